// round 2
// baseline (speedup 1.0000x reference)
#include <cuda_runtime.h>
#include <math.h>
#include <stdint.h>
#include <mma.h>

using namespace nvcuda;

#define BATCH   4
#define LQ      1024
#define TSEQ    2048            // 2*L
#define DMODEL  256
#define DTIME   16
#define DDIM    272
#define NLAYER  4
#define DINNER  544
#define DSTATE  16
#define DCONV   4
#define DTRANK  17
#define NDBL    (DTRANK + 2*DSTATE)   // 49
#define MROWS   (BATCH*TSEQ)          // 8192
#define NCHUNK  32
#define CHUNK   (TSEQ/NCHUNK)         // 64
#define CONVT   16

// ---------------- scratch (static device globals; no allocation) ----------------
__device__ float g_h   [MROWS*DDIM];
__device__ float g_res [MROWS*DDIM];
__device__ float g_hn  [MROWS*DDIM];
__device__ float g_xz  [MROWS*2*DINNER];
__device__ float g_xconv[MROWS*DINNER];
__device__ float g_dbl [MROWS*NDBL];
__device__ float g_delta[MROWS*DINNER];
__device__ float g_yg  [MROWS*DINNER];
__device__ float g_hend[BATCH*NCHUNK*DINNER*DSTATE];
__device__ float g_P   [BATCH*NCHUNK*DINNER*DSTATE];
__device__ float g_Hin [BATCH*NCHUNK*DINNER*DSTATE];

__device__ __forceinline__ float ex2(float x) {
    float y; asm("ex2.approx.ftz.f32 %0, %1;" : "=f"(y) : "f"(x)); return y;
}

// ---------------- embedding + temporal pe + sequence concat ----------------
__global__ void __launch_bounds__(DDIM) embed_kernel(
    const int* __restrict__ type_seq, const float* __restrict__ time_seq,
    const float* __restrict__ temp_seq, const float* __restrict__ emb)
{
    int row = blockIdx.x;            // 0..8191 : b*TSEQ + t
    int d = threadIdx.x;             // 0..271
    int b = row / TSEQ, t = row % TSEQ;
    float v;
    if (t < LQ) {
        if (d < DMODEL) {
            v = tanhf(emb[(size_t)type_seq[b*LQ + t]*DMODEL + d]);
        } else {
            int j = d - DMODEL;
            int i = j >> 1;
            float div = expf(-0.57564627324851142f * (float)(2*i));
            float arg = time_seq[b*LQ + t] * div;
            v = (j & 1) ? cosf(arg) : sinf(arg);
        }
    } else {
        v = (d < DMODEL) ? 0.f
                         : temp_seq[(size_t)(b*LQ + (t - LQ))*DTIME + (d - DMODEL)];
    }
    g_h[(size_t)row*DDIM + d] = v;
}

// ---------------- residual add + layernorm ----------------
__global__ void __launch_bounds__(128) addnorm_kernel(
    const float* __restrict__ gamma, const float* __restrict__ beta, int addflag)
{
    int row = blockIdx.x;
    int tid = threadIdx.x;
    float v[3];
    float s = 0.f, s2 = 0.f;
#pragma unroll
    for (int j = 0; j < 3; j++) {
        int d = tid + j*128;
        float x = 0.f;
        if (d < DDIM) {
            x = g_h[(size_t)row*DDIM + d];
            if (addflag) x += g_res[(size_t)row*DDIM + d];
        }
        v[j] = x; s += x; s2 += x*x;
    }
#pragma unroll
    for (int o = 16; o > 0; o >>= 1) {
        s  += __shfl_down_sync(0xffffffffu, s,  o);
        s2 += __shfl_down_sync(0xffffffffu, s2, o);
    }
    __shared__ float ss[4], ss2[4];
    if ((tid & 31) == 0) { ss[tid >> 5] = s; ss2[tid >> 5] = s2; }
    __syncthreads();
    if (tid == 0) {
        float a  = ss[0]+ss[1]+ss[2]+ss[3];
        float a2 = ss2[0]+ss2[1]+ss2[2]+ss2[3];
        float mean = a * (1.f/DDIM);
        float var  = a2 * (1.f/DDIM) - mean*mean;
        ss[0] = mean;
        ss2[0] = rsqrtf(var + 1e-5f);
    }
    __syncthreads();
    float mean = ss[0], rstd = ss2[0];
#pragma unroll
    for (int j = 0; j < 3; j++) {
        int d = tid + j*128;
        if (d < DDIM) {
            g_res[(size_t)row*DDIM + d] = v[j];
            g_hn[(size_t)row*DDIM + d] = (v[j]-mean)*rstd*gamma[d] + beta[d];
        }
    }
}

// ---------------- final add + layernorm -> output (first LQ timesteps) ----------------
__global__ void __launch_bounds__(128) final_kernel(
    const float* __restrict__ gamma, const float* __restrict__ beta,
    float* __restrict__ out)
{
    int rowo = blockIdx.x;           // 0..4095 : b*LQ + t
    int tid = threadIdx.x;
    int b = rowo / LQ, t = rowo % LQ;
    int m = b*TSEQ + t;
    float v[3];
    float s = 0.f, s2 = 0.f;
#pragma unroll
    for (int j = 0; j < 3; j++) {
        int d = tid + j*128;
        float x = 0.f;
        if (d < DDIM) x = g_h[(size_t)m*DDIM + d] + g_res[(size_t)m*DDIM + d];
        v[j] = x; s += x; s2 += x*x;
    }
#pragma unroll
    for (int o = 16; o > 0; o >>= 1) {
        s  += __shfl_down_sync(0xffffffffu, s,  o);
        s2 += __shfl_down_sync(0xffffffffu, s2, o);
    }
    __shared__ float ss[4], ss2[4];
    if ((tid & 31) == 0) { ss[tid >> 5] = s; ss2[tid >> 5] = s2; }
    __syncthreads();
    if (tid == 0) {
        float a  = ss[0]+ss[1]+ss[2]+ss[3];
        float a2 = ss2[0]+ss2[1]+ss2[2]+ss2[3];
        float mean = a * (1.f/DDIM);
        float var  = a2 * (1.f/DDIM) - mean*mean;
        ss[0] = mean;
        ss2[0] = rsqrtf(var + 1e-5f);
    }
    __syncthreads();
    float mean = ss[0], rstd = ss2[0];
#pragma unroll
    for (int j = 0; j < 3; j++) {
        int d = tid + j*128;
        if (d < DDIM)
            out[(size_t)rowo*DDIM + d] = (v[j]-mean)*rstd*gamma[d] + beta[d];
    }
}

// ---------------- tensor-core TN GEMM (3xTF32 split): C[M,N] = A[M,K] @ W[N,K]^T
// BM=128, BN=64, BK=16, 256 threads (8 warps: 4x2), warp tile 32x32 (2x2 wmma 16x16x8).
// Requires: M % 128 == 0, K % 16 == 0, N % 16 == 0 (grid may overcover N; W
// loads zero-filled and stores skipped for OOB 16-col fragments).
#define GBK 16
#define GPAD 4
__global__ void __launch_bounds__(256) gemm_tf32(
    const float* __restrict__ A, const float* __restrict__ W,
    float* __restrict__ C, int M, int N, int K)
{
    __shared__ float As[128][GBK+GPAD];
    __shared__ float Ws[64][GBK+GPAD];
    int tid = threadIdx.x;
    int warp = tid >> 5;
    int wm = warp >> 1;      // 0..3
    int wn = warp & 1;       // 0..1
    int mb = blockIdx.y * 128;
    int nb = blockIdx.x * 64;

    int lr = tid >> 2;       // 0..63
    int lk = (tid & 3) * 4;  // 0,4,8,12

    wmma::fragment<wmma::accumulator,16,16,8,float> acc[2][2];
#pragma unroll
    for (int i = 0; i < 2; i++)
#pragma unroll
        for (int j = 0; j < 2; j++) wmma::fill_fragment(acc[i][j], 0.f);

    const float* Arow0 = A + (size_t)(mb + lr) * K + lk;
    const float* Arow1 = Arow0 + (size_t)64 * K;
    bool wvalid = (nb + lr) < N;
    const float* Wrow = W + (size_t)(nb + lr) * K + lk;

    for (int k0 = 0; k0 < K; k0 += GBK) {
        float4 a0 = *(const float4*)(Arow0 + k0);
        float4 a1 = *(const float4*)(Arow1 + k0);
        float4 w0 = wvalid ? *(const float4*)(Wrow + k0)
                           : make_float4(0.f,0.f,0.f,0.f);
        __syncthreads();
        *(float4*)&As[lr][lk]    = a0;
        *(float4*)&As[lr+64][lk] = a1;
        *(float4*)&Ws[lr][lk]    = w0;
        __syncthreads();
#pragma unroll
        for (int ks = 0; ks < GBK; ks += 8) {
            wmma::fragment<wmma::matrix_a,16,16,8,wmma::precision::tf32,wmma::row_major> ahi[2], alo[2];
            wmma::fragment<wmma::matrix_b,16,16,8,wmma::precision::tf32,wmma::col_major> bhi[2], blo[2];
#pragma unroll
            for (int i = 0; i < 2; i++) {
                wmma::load_matrix_sync(ahi[i], &As[wm*32 + i*16][ks], GBK+GPAD);
#pragma unroll
                for (int e = 0; e < ahi[i].num_elements; e++) {
                    float v = ahi[i].x[e];
                    float h = wmma::__float_to_tf32(v);
                    ahi[i].x[e] = h;
                    alo[i].x[e] = wmma::__float_to_tf32(v - h);
                }
            }
#pragma unroll
            for (int j = 0; j < 2; j++) {
                wmma::load_matrix_sync(bhi[j], &Ws[wn*32 + j*16][ks], GBK+GPAD);
#pragma unroll
                for (int e = 0; e < bhi[j].num_elements; e++) {
                    float v = bhi[j].x[e];
                    float h = wmma::__float_to_tf32(v);
                    bhi[j].x[e] = h;
                    blo[j].x[e] = wmma::__float_to_tf32(v - h);
                }
            }
#pragma unroll
            for (int i = 0; i < 2; i++)
#pragma unroll
                for (int j = 0; j < 2; j++) {
                    wmma::mma_sync(acc[i][j], alo[i], bhi[j], acc[i][j]);
                    wmma::mma_sync(acc[i][j], ahi[i], blo[j], acc[i][j]);
                    wmma::mma_sync(acc[i][j], ahi[i], bhi[j], acc[i][j]);
                }
        }
    }
#pragma unroll
    for (int i = 0; i < 2; i++)
#pragma unroll
        for (int j = 0; j < 2; j++) {
            int n0 = nb + wn*32 + j*16;
            if (n0 < N)
                wmma::store_matrix_sync(C + (size_t)(mb + wm*32 + i*16)*N + n0,
                                        acc[i][j], N, wmma::mem_row_major);
        }
}

// ---------------- generic FFMA TN GEMM (kept for N=49 x_proj) ----------------
__global__ void __launch_bounds__(256) gemm_tn(
    const float* __restrict__ A, const float* __restrict__ W,
    float* __restrict__ C, int M, int N, int K)
{
    __shared__ float As[16][132];
    __shared__ float Ws[16][68];
    int tid = threadIdx.x;
    int mb = blockIdx.y * 128;
    int nb = blockIdx.x * 64;
    int lr = tid >> 2;
    int lk = (tid & 3) << 2;
    int ty = tid >> 4;
    int tx = tid & 15;

    float acc[8][4];
#pragma unroll
    for (int i = 0; i < 8; i++)
#pragma unroll
        for (int j = 0; j < 4; j++) acc[i][j] = 0.f;

    const float* Arow0 = A + (size_t)(mb + lr) * K + lk;
    const float* Arow1 = Arow0 + (size_t)64 * K;
    bool wvalid = (nb + lr) < N;
    const float* Wrow = W + (size_t)(nb + lr) * K + lk;

    int ktiles = K >> 4;
    for (int kt = 0; kt < ktiles; kt++) {
        float4 a0 = *(const float4*)(Arow0 + kt*16);
        float4 a1 = *(const float4*)(Arow1 + kt*16);
        float4 w0 = wvalid ? *(const float4*)(Wrow + kt*16)
                           : make_float4(0.f, 0.f, 0.f, 0.f);
        __syncthreads();
        As[lk+0][lr] = a0.x; As[lk+1][lr] = a0.y; As[lk+2][lr] = a0.z; As[lk+3][lr] = a0.w;
        As[lk+0][lr+64] = a1.x; As[lk+1][lr+64] = a1.y; As[lk+2][lr+64] = a1.z; As[lk+3][lr+64] = a1.w;
        Ws[lk+0][lr] = w0.x; Ws[lk+1][lr] = w0.y; Ws[lk+2][lr] = w0.z; Ws[lk+3][lr] = w0.w;
        __syncthreads();
#pragma unroll
        for (int kk = 0; kk < 16; kk++) {
            float ra[8], rw[4];
            *(float4*)&ra[0] = *(const float4*)&As[kk][ty*8];
            *(float4*)&ra[4] = *(const float4*)&As[kk][ty*8 + 4];
            *(float4*)&rw[0] = *(const float4*)&Ws[kk][tx*4];
#pragma unroll
            for (int i = 0; i < 8; i++)
#pragma unroll
                for (int j = 0; j < 4; j++)
                    acc[i][j] = fmaf(ra[i], rw[j], acc[i][j]);
        }
    }
#pragma unroll
    for (int i = 0; i < 8; i++) {
        int m = mb + ty*8 + i;
#pragma unroll
        for (int j = 0; j < 4; j++) {
            int n = nb + tx*4 + j;
            if (n < N) C[(size_t)m*N + n] = acc[i][j];
        }
    }
}

// ---------------- depthwise causal conv1d + bias + silu (sliding window) ----------------
__global__ void __launch_bounds__(DINNER) conv_kernel(
    const float* __restrict__ conv_w, const float* __restrict__ conv_b, int layer)
{
    int d = threadIdx.x;
    int t0 = blockIdx.x * CONVT;     // within TSEQ
    int b = blockIdx.y;
    const float* wp = conv_w + (size_t)(layer*DINNER + d)*DCONV;
    float w0 = wp[0], w1 = wp[1], w2 = wp[2], w3 = wp[3];
    float bias = conv_b[layer*DINNER + d];
    size_t base = (size_t)(b*TSEQ)*(2*DINNER) + d;
    // window: x[t0-3], x[t0-2], x[t0-1]
    float x0 = (t0-3 >= 0) ? g_xz[base + (size_t)(t0-3)*(2*DINNER)] : 0.f;
    float x1 = (t0-2 >= 0) ? g_xz[base + (size_t)(t0-2)*(2*DINNER)] : 0.f;
    float x2 = (t0-1 >= 0) ? g_xz[base + (size_t)(t0-1)*(2*DINNER)] : 0.f;
#pragma unroll
    for (int i = 0; i < CONVT; i++) {
        int t = t0 + i;
        float x3 = g_xz[base + (size_t)t*(2*DINNER)];
        float s = bias;
        s = fmaf(w0, x0, s);
        s = fmaf(w1, x1, s);
        s = fmaf(w2, x2, s);
        s = fmaf(w3, x3, s);
        float sl = s / (1.f + __expf(-s));
        g_xconv[(size_t)(b*TSEQ + t)*DINNER + d] = sl;
        x0 = x1; x1 = x2; x2 = x3;
    }
}

// ---------------- delta = softplus(dt @ dt_w^T + dt_b), K=17 ----------------
__global__ void __launch_bounds__(DINNER) delta_kernel(
    const float* __restrict__ dt_w, const float* __restrict__ dt_b, int layer)
{
    __shared__ float sdbl[16][DTRANK];
    int m0 = blockIdx.x * 16;
    int tid = threadIdx.x;
    if (tid < 16*DTRANK) {
        int mm = tid / DTRANK, r = tid % DTRANK;
        sdbl[mm][r] = g_dbl[(size_t)(m0+mm)*NDBL + r];
    }
    __syncthreads();
    int d = tid;
    float wreg[DTRANK];
#pragma unroll
    for (int r = 0; r < DTRANK; r++)
        wreg[r] = dt_w[(size_t)(layer*DINNER + d)*DTRANK + r];
    float bias = dt_b[layer*DINNER + d];
    for (int mm = 0; mm < 16; mm++) {
        float s = bias;
#pragma unroll
        for (int r = 0; r < DTRANK; r++) s = fmaf(sdbl[mm][r], wreg[r], s);
        float sp = fmaxf(s, 0.f) + log1pf(__expf(-fabsf(s)));
        g_delta[(size_t)(m0+mm)*DINNER + d] = sp;
    }
}

// ---------------- chunked selective scan ----------------
__global__ void __launch_bounds__(DINNER) scan1_kernel(
    const float* __restrict__ A_log, int layer)
{
    int c = blockIdx.x, b = blockIdx.y;
    int d = threadIdx.x;
    const float LOG2E = 1.4426950408889634f;
    float A2[DSTATE];
#pragma unroll
    for (int n = 0; n < DSTATE; n++)
        A2[n] = -__expf(A_log[(size_t)(layer*DINNER + d)*DSTATE + n]) * LOG2E;
    float base = A2[0];
    bool fast = true;
#pragma unroll
    for (int n = 1; n < DSTATE; n++)
        fast = fast && (fabsf(A2[n] - (float)(n+1)*base)
                        <= 1e-4f*fabsf((float)(n+1)*base) + 1e-6f);

    float h[DSTATE];
#pragma unroll
    for (int n = 0; n < DSTATE; n++) h[n] = 0.f;
    float sumd = 0.f;
    __shared__ float sB[2][DSTATE];

    int m0 = b*TSEQ + c*CHUNK;
    for (int i = 0; i < CHUNK; i++) {
        int m = m0 + i;
        if (d < DSTATE) sB[i & 1][d] = g_dbl[(size_t)m*NDBL + DTRANK + d];
        float delta = g_delta[(size_t)m*DINNER + d];
        float u     = g_xconv[(size_t)m*DINNER + d];
        __syncthreads();
        float du = delta * u;
        if (fast) {
            float e1 = ex2(delta * base);
            float p = e1;
#pragma unroll
            for (int n = 0; n < DSTATE; n++) {
                h[n] = fmaf(p, h[n], du * sB[i & 1][n]);
                p *= e1;
            }
        } else {
#pragma unroll
            for (int n = 0; n < DSTATE; n++) {
                float a = ex2(delta * A2[n]);
                h[n] = fmaf(a, h[n], du * sB[i & 1][n]);
            }
        }
        sumd += delta;
    }
    size_t o = ((size_t)(b*NCHUNK + c)*DINNER + d)*DSTATE;
#pragma unroll
    for (int n = 0; n < DSTATE; n++) {
        g_hend[o + n] = h[n];
        g_P[o + n] = ex2(A2[n] * sumd);
    }
}

__global__ void scan2_kernel()
{
    int idx = blockIdx.x*blockDim.x + threadIdx.x;
    if (idx >= BATCH*DINNER) return;
    int b = idx / DINNER, d = idx % DINNER;
    float H[DSTATE];
#pragma unroll
    for (int n = 0; n < DSTATE; n++) H[n] = 0.f;
    for (int c = 0; c < NCHUNK; c++) {
        size_t o = ((size_t)(b*NCHUNK + c)*DINNER + d)*DSTATE;
#pragma unroll
        for (int n = 0; n < DSTATE; n++) g_Hin[o + n] = H[n];
#pragma unroll
        for (int n = 0; n < DSTATE; n++) H[n] = fmaf(g_P[o + n], H[n], g_hend[o + n]);
    }
}

__global__ void __launch_bounds__(DINNER) scan3_kernel(
    const float* __restrict__ A_log, const float* __restrict__ D_param, int layer)
{
    int c = blockIdx.x, b = blockIdx.y;
    int d = threadIdx.x;
    const float LOG2E = 1.4426950408889634f;
    float A2[DSTATE];
#pragma unroll
    for (int n = 0; n < DSTATE; n++)
        A2[n] = -__expf(A_log[(size_t)(layer*DINNER + d)*DSTATE + n]) * LOG2E;
    float base = A2[0];
    bool fast = true;
#pragma unroll
    for (int n = 1; n < DSTATE; n++)
        fast = fast && (fabsf(A2[n] - (float)(n+1)*base)
                        <= 1e-4f*fabsf((float)(n+1)*base) + 1e-6f);

    float h[DSTATE];
    size_t oin = ((size_t)(b*NCHUNK + c)*DINNER + d)*DSTATE;
#pragma unroll
    for (int n = 0; n < DSTATE; n++) h[n] = g_Hin[oin + n];
    float Dp = D_param[layer*DINNER + d];

    __shared__ float sBC[2][2*DSTATE];
    int m0 = b*TSEQ + c*CHUNK;
    for (int i = 0; i < CHUNK; i++) {
        int m = m0 + i;
        if (d < 2*DSTATE) sBC[i & 1][d] = g_dbl[(size_t)m*NDBL + DTRANK + d];
        float delta = g_delta[(size_t)m*DINNER + d];
        float u     = g_xconv[(size_t)m*DINNER + d];
        float z     = g_xz[(size_t)m*(2*DINNER) + DINNER + d];
        __syncthreads();
        float du = delta * u;
        float y = 0.f;
        if (fast) {
            float e1 = ex2(delta * base);
            float p = e1;
#pragma unroll
            for (int n = 0; n < DSTATE; n++) {
                h[n] = fmaf(p, h[n], du * sBC[i & 1][n]);
                y = fmaf(h[n], sBC[i & 1][DSTATE + n], y);
                p *= e1;
            }
        } else {
#pragma unroll
            for (int n = 0; n < DSTATE; n++) {
                float a = ex2(delta * A2[n]);
                h[n] = fmaf(a, h[n], du * sBC[i & 1][n]);
                y = fmaf(h[n], sBC[i & 1][DSTATE + n], y);
            }
        }
        float silz = z / (1.f + __expf(-z));
        g_yg[(size_t)m*DINNER + d] = fmaf(u, Dp, y) * silz;
    }
}

// ---------------- host launcher ----------------
extern "C" void kernel_launch(void* const* d_in, const int* in_sizes, int n_in,
                              void* d_out, int out_size)
{
    (void)in_sizes; (void)n_in; (void)out_size;
    const int*   type_seq = (const int*)  d_in[0];
    const float* time_seq = (const float*)d_in[1];
    const float* temp_seq = (const float*)d_in[2];
    const float* emb      = (const float*)d_in[3];
    const float* norm_w   = (const float*)d_in[4];
    const float* norm_b   = (const float*)d_in[5];
    const float* in_w     = (const float*)d_in[6];
    const float* conv_w   = (const float*)d_in[7];
    const float* conv_b   = (const float*)d_in[8];
    const float* xproj_w  = (const float*)d_in[9];
    const float* dt_w     = (const float*)d_in[10];
    const float* dt_b     = (const float*)d_in[11];
    const float* A_log    = (const float*)d_in[12];
    const float* D_param  = (const float*)d_in[13];
    const float* out_w    = (const float*)d_in[14];
    const float* normf_w  = (const float*)d_in[15];
    const float* normf_b  = (const float*)d_in[16];
    float* out = (float*)d_out;

    float *p_hn, *p_xz, *p_xconv, *p_dbl, *p_yg, *p_h;
    cudaGetSymbolAddress((void**)&p_hn,    g_hn);
    cudaGetSymbolAddress((void**)&p_xz,    g_xz);
    cudaGetSymbolAddress((void**)&p_xconv, g_xconv);
    cudaGetSymbolAddress((void**)&p_dbl,   g_dbl);
    cudaGetSymbolAddress((void**)&p_yg,    g_yg);
    cudaGetSymbolAddress((void**)&p_h,     g_h);

    embed_kernel<<<MROWS, DDIM>>>(type_seq, time_seq, temp_seq, emb);

    for (int l = 0; l < NLAYER; l++) {
        addnorm_kernel<<<MROWS, 128>>>(norm_w + l*DDIM, norm_b + l*DDIM, l > 0);

        // xz = hn @ in_w^T : (8192,272)x(1088,272)^T  [tensor cores, 3xTF32]
        gemm_tf32<<<dim3((2*DINNER + 63)/64, MROWS/128), 256>>>(
            p_hn, in_w + (size_t)l*2*DINNER*DDIM, p_xz, MROWS, 2*DINNER, DDIM);

        conv_kernel<<<dim3(TSEQ/CONVT, BATCH), DINNER>>>(conv_w, conv_b, l);

        // dbl = xconv @ xproj_w^T : (8192,544)x(49,544)^T  [FFMA, tiny N]
        gemm_tn<<<dim3((NDBL + 63)/64, MROWS/128), 256>>>(
            p_xconv, xproj_w + (size_t)l*NDBL*DINNER, p_dbl, MROWS, NDBL, DINNER);

        delta_kernel<<<MROWS/16, DINNER>>>(dt_w, dt_b, l);

        scan1_kernel<<<dim3(NCHUNK, BATCH), DINNER>>>(A_log, l);
        scan2_kernel<<<(BATCH*DINNER + 255)/256, 256>>>();
        scan3_kernel<<<dim3(NCHUNK, BATCH), DINNER>>>(A_log, D_param, l);

        // h = yg @ out_w^T : (8192,544)x(272,544)^T  [tensor cores, 3xTF32]
        gemm_tf32<<<dim3((DDIM + 63)/64, MROWS/128), 256>>>(
            p_yg, out_w + (size_t)l*DDIM*DINNER, p_h, MROWS, DDIM, DINNER);
    }

    final_kernel<<<BATCH*LQ, 128>>>(normf_w, normf_b, out);
}

// round 3
// speedup vs baseline: 1.2847x; 1.2847x over previous
#include <cuda_runtime.h>
#include <cuda_bf16.h>
#include <math.h>
#include <stdint.h>
#include <mma.h>

using namespace nvcuda;

#define BATCH   4
#define LQ      1024
#define TSEQ    2048            // 2*L
#define DMODEL  256
#define DTIME   16
#define DDIM    272
#define KPAD1   288             // DDIM padded to 32
#define NLAYER  4
#define DINNER  544
#define DSTATE  16
#define DCONV   4
#define DTRANK  17
#define NDBL    (DTRANK + 2*DSTATE)   // 49
#define MROWS   (BATCH*TSEQ)          // 8192
#define NCHUNK  32
#define CHUNK   (TSEQ/NCHUNK)         // 64
#define CONVT   16

typedef __nv_bfloat16 bf16;

// ---------------- scratch (static device globals; no allocation) ----------------
__device__ float g_h   [MROWS*DDIM];
__device__ float g_res [MROWS*DDIM];
__device__ float g_xz  [MROWS*2*DINNER];
__device__ float g_xconv[MROWS*DINNER];
__device__ float g_dbl [MROWS*NDBL];
__device__ float g_delta[MROWS*DINNER];
__device__ float g_hend[BATCH*NCHUNK*DINNER*DSTATE];
__device__ float g_P   [BATCH*NCHUNK*DINNER*DSTATE];
__device__ float g_Hin [BATCH*NCHUNK*DINNER*DSTATE];
// bf16 split activation buffers
__device__ bf16 g_hn_hi[MROWS*KPAD1];
__device__ bf16 g_hn_lo[MROWS*KPAD1];
__device__ bf16 g_yg_hi[MROWS*DINNER];
__device__ bf16 g_yg_lo[MROWS*DINNER];
// bf16 split weight buffers (reused per layer)
__device__ bf16 g_w1_hi[2*DINNER*KPAD1];
__device__ bf16 g_w1_lo[2*DINNER*KPAD1];
__device__ bf16 g_w2_hi[DDIM*DINNER];
__device__ bf16 g_w2_lo[DDIM*DINNER];

__device__ __forceinline__ float ex2(float x) {
    float y; asm("ex2.approx.ftz.f32 %0, %1;" : "=f"(y) : "f"(x)); return y;
}
__device__ __forceinline__ void split_bf16(float v, bf16& hi, bf16& lo) {
    hi = __float2bfloat16_rn(v);
    lo = __float2bfloat16_rn(v - __bfloat162float(hi));
}

// ---------------- embedding + temporal pe + sequence concat ----------------
__global__ void __launch_bounds__(DDIM) embed_kernel(
    const int* __restrict__ type_seq, const float* __restrict__ time_seq,
    const float* __restrict__ temp_seq, const float* __restrict__ emb)
{
    int row = blockIdx.x;
    int d = threadIdx.x;
    int b = row / TSEQ, t = row % TSEQ;
    float v;
    if (t < LQ) {
        if (d < DMODEL) {
            v = tanhf(emb[(size_t)type_seq[b*LQ + t]*DMODEL + d]);
        } else {
            int j = d - DMODEL;
            int i = j >> 1;
            float div = expf(-0.57564627324851142f * (float)(2*i));
            float arg = time_seq[b*LQ + t] * div;
            v = (j & 1) ? cosf(arg) : sinf(arg);
        }
    } else {
        v = (d < DMODEL) ? 0.f
                         : temp_seq[(size_t)(b*LQ + (t - LQ))*DTIME + (d - DMODEL)];
    }
    g_h[(size_t)row*DDIM + d] = v;
}

// ---------------- weight split converter: W[N][K] fp32 -> hi/lo [N][Kpad] bf16 ----------------
__global__ void __launch_bounds__(256) convert_w(
    const float* __restrict__ W, bf16* __restrict__ hi, bf16* __restrict__ lo,
    int N, int K, int Kpad)
{
    int idx = blockIdx.x*256 + threadIdx.x;
    if (idx >= N*Kpad) return;
    int r = idx / Kpad, c = idx - r*Kpad;
    float v = (c < K) ? W[(size_t)r*K + c] : 0.f;
    split_bf16(v, hi[idx], lo[idx]);
}

// ---------------- residual add + layernorm -> bf16 split hn ----------------
__global__ void __launch_bounds__(128) addnorm_kernel(
    const float* __restrict__ gamma, const float* __restrict__ beta, int addflag)
{
    int row = blockIdx.x;
    int tid = threadIdx.x;
    float v[3];
    float s = 0.f, s2 = 0.f;
#pragma unroll
    for (int j = 0; j < 3; j++) {
        int d = tid + j*128;
        float x = 0.f;
        if (d < DDIM) {
            x = g_h[(size_t)row*DDIM + d];
            if (addflag) x += g_res[(size_t)row*DDIM + d];
        }
        v[j] = x; s += x; s2 += x*x;
    }
#pragma unroll
    for (int o = 16; o > 0; o >>= 1) {
        s  += __shfl_down_sync(0xffffffffu, s,  o);
        s2 += __shfl_down_sync(0xffffffffu, s2, o);
    }
    __shared__ float ss[4], ss2[4];
    if ((tid & 31) == 0) { ss[tid >> 5] = s; ss2[tid >> 5] = s2; }
    __syncthreads();
    if (tid == 0) {
        float a  = ss[0]+ss[1]+ss[2]+ss[3];
        float a2 = ss2[0]+ss2[1]+ss2[2]+ss2[3];
        float mean = a * (1.f/DDIM);
        float var  = a2 * (1.f/DDIM) - mean*mean;
        ss[0] = mean;
        ss2[0] = rsqrtf(var + 1e-5f);
    }
    __syncthreads();
    float mean = ss[0], rstd = ss2[0];
#pragma unroll
    for (int j = 0; j < 3; j++) {
        int d = tid + j*128;
        if (d < DDIM) {
            g_res[(size_t)row*DDIM + d] = v[j];
            float hn = (v[j]-mean)*rstd*gamma[d] + beta[d];
            split_bf16(hn, g_hn_hi[(size_t)row*KPAD1 + d], g_hn_lo[(size_t)row*KPAD1 + d]);
        } else if (d < KPAD1) {
            g_hn_hi[(size_t)row*KPAD1 + d] = __float2bfloat16(0.f);
            g_hn_lo[(size_t)row*KPAD1 + d] = __float2bfloat16(0.f);
        }
    }
}

// ---------------- final add + layernorm -> output ----------------
__global__ void __launch_bounds__(128) final_kernel(
    const float* __restrict__ gamma, const float* __restrict__ beta,
    float* __restrict__ out)
{
    int rowo = blockIdx.x;
    int tid = threadIdx.x;
    int b = rowo / LQ, t = rowo % LQ;
    int m = b*TSEQ + t;
    float v[3];
    float s = 0.f, s2 = 0.f;
#pragma unroll
    for (int j = 0; j < 3; j++) {
        int d = tid + j*128;
        float x = 0.f;
        if (d < DDIM) x = g_h[(size_t)m*DDIM + d] + g_res[(size_t)m*DDIM + d];
        v[j] = x; s += x; s2 += x*x;
    }
#pragma unroll
    for (int o = 16; o > 0; o >>= 1) {
        s  += __shfl_down_sync(0xffffffffu, s,  o);
        s2 += __shfl_down_sync(0xffffffffu, s2, o);
    }
    __shared__ float ss[4], ss2[4];
    if ((tid & 31) == 0) { ss[tid >> 5] = s; ss2[tid >> 5] = s2; }
    __syncthreads();
    if (tid == 0) {
        float a  = ss[0]+ss[1]+ss[2]+ss[3];
        float a2 = ss2[0]+ss2[1]+ss2[2]+ss2[3];
        float mean = a * (1.f/DDIM);
        float var  = a2 * (1.f/DDIM) - mean*mean;
        ss[0] = mean;
        ss2[0] = rsqrtf(var + 1e-5f);
    }
    __syncthreads();
    float mean = ss[0], rstd = ss2[0];
#pragma unroll
    for (int j = 0; j < 3; j++) {
        int d = tid + j*128;
        if (d < DDIM)
            out[(size_t)rowo*DDIM + d] = (v[j]-mean)*rstd*gamma[d] + beta[d];
    }
}

// ---------------- bf16-split tensor-core GEMM: C[M,N] = A @ W^T ----------------
// A hi/lo: [M][Kpad] bf16, W hi/lo: [N][Kpad] bf16 (rows >= N are never read).
// BM=128, BN=64, BK=32. 256 threads, 8 warps (4x2), warp tile 32x32.
// C = Ahi*Whi + Ahi*Wlo + Alo*Whi  (fp32 accum).
#define SPAD 8
__global__ void __launch_bounds__(256) gemm_bf16split(
    const bf16* __restrict__ Ahi, const bf16* __restrict__ Alo,
    const bf16* __restrict__ Whi, const bf16* __restrict__ Wlo,
    float* __restrict__ C, int M, int N, int Kpad)
{
    __shared__ bf16 sAhi[128][32+SPAD];
    __shared__ bf16 sAlo[128][32+SPAD];
    __shared__ bf16 sWhi[64][32+SPAD];
    __shared__ bf16 sWlo[64][32+SPAD];

    int tid = threadIdx.x;
    int warp = tid >> 5;
    int wm = warp >> 1;          // 0..3
    int wn = warp & 1;           // 0..1
    int mb = blockIdx.y * 128;
    int nb = blockIdx.x * 64;

    // A loader: 512 uint4 per tile (128 rows x 4 u4), 2 per thread
    int ar0 = tid >> 1;                    // rows 0..127 (idx = tid*2 -> row tid/2? no)
    // idx = tid*2 + {0,1}: row = idx>>2, c4 = idx&3
    int aIdx0 = tid*2, aIdx1 = tid*2 + 1;
    int aRow0 = aIdx0 >> 2, aC0 = (aIdx0 & 3) * 8;
    int aRow1 = aIdx1 >> 2, aC1 = (aIdx1 & 3) * 8;
    (void)ar0;
    // W loader: 256 uint4, 1 per thread
    int wRow = tid >> 2, wC = (tid & 3) * 8;
    bool wvalid = (nb + wRow) < N;

    const uint4* pAhi0 = (const uint4*)(Ahi + (size_t)(mb + aRow0)*Kpad + aC0);
    const uint4* pAhi1 = (const uint4*)(Ahi + (size_t)(mb + aRow1)*Kpad + aC1);
    const uint4* pAlo0 = (const uint4*)(Alo + (size_t)(mb + aRow0)*Kpad + aC0);
    const uint4* pAlo1 = (const uint4*)(Alo + (size_t)(mb + aRow1)*Kpad + aC1);
    const uint4* pWhi  = (const uint4*)(Whi + (size_t)(nb + wRow)*Kpad + wC);
    const uint4* pWlo  = (const uint4*)(Wlo + (size_t)(nb + wRow)*Kpad + wC);
    uint4 z4 = make_uint4(0,0,0,0);

    wmma::fragment<wmma::accumulator,16,16,16,float> acc[2][2];
#pragma unroll
    for (int i = 0; i < 2; i++)
#pragma unroll
        for (int j = 0; j < 2; j++) wmma::fill_fragment(acc[i][j], 0.f);

    int ktiles = Kpad >> 5;   // Kpad % 32 == 0
    // prefetch tile 0
    uint4 rAhi0 = pAhi0[0], rAhi1 = pAhi1[0];
    uint4 rAlo0 = pAlo0[0], rAlo1 = pAlo1[0];
    uint4 rWhi  = wvalid ? pWhi[0] : z4;
    uint4 rWlo  = wvalid ? pWlo[0] : z4;

    for (int kt = 0; kt < ktiles; kt++) {
        __syncthreads();
        *(uint4*)&sAhi[aRow0][aC0] = rAhi0;
        *(uint4*)&sAhi[aRow1][aC1] = rAhi1;
        *(uint4*)&sAlo[aRow0][aC0] = rAlo0;
        *(uint4*)&sAlo[aRow1][aC1] = rAlo1;
        *(uint4*)&sWhi[wRow][wC]   = rWhi;
        *(uint4*)&sWlo[wRow][wC]   = rWlo;
        __syncthreads();
        if (kt + 1 < ktiles) {
            int o = (kt+1) * 4;       // uint4 stride along K: 32 bf16 = 4 uint4
            rAhi0 = pAhi0[o]; rAhi1 = pAhi1[o];
            rAlo0 = pAlo0[o]; rAlo1 = pAlo1[o];
            rWhi = wvalid ? pWhi[o] : z4;
            rWlo = wvalid ? pWlo[o] : z4;
        }
#pragma unroll
        for (int ks = 0; ks < 32; ks += 16) {
            wmma::fragment<wmma::matrix_a,16,16,16,bf16,wmma::row_major> ahi[2], alo[2];
            wmma::fragment<wmma::matrix_b,16,16,16,bf16,wmma::col_major> bhi[2], blo[2];
#pragma unroll
            for (int i = 0; i < 2; i++) {
                wmma::load_matrix_sync(ahi[i], &sAhi[wm*32 + i*16][ks], 32+SPAD);
                wmma::load_matrix_sync(alo[i], &sAlo[wm*32 + i*16][ks], 32+SPAD);
            }
#pragma unroll
            for (int j = 0; j < 2; j++) {
                wmma::load_matrix_sync(bhi[j], &sWhi[wn*32 + j*16][ks], 32+SPAD);
                wmma::load_matrix_sync(blo[j], &sWlo[wn*32 + j*16][ks], 32+SPAD);
            }
#pragma unroll
            for (int i = 0; i < 2; i++)
#pragma unroll
                for (int j = 0; j < 2; j++) {
                    wmma::mma_sync(acc[i][j], ahi[i], bhi[j], acc[i][j]);
                    wmma::mma_sync(acc[i][j], ahi[i], blo[j], acc[i][j]);
                    wmma::mma_sync(acc[i][j], alo[i], bhi[j], acc[i][j]);
                }
        }
    }
#pragma unroll
    for (int i = 0; i < 2; i++)
#pragma unroll
        for (int j = 0; j < 2; j++) {
            int n0 = nb + wn*32 + j*16;
            if (n0 < N)
                wmma::store_matrix_sync(C + (size_t)(mb + wm*32 + i*16)*N + n0,
                                        acc[i][j], N, wmma::mem_row_major);
        }
}

// ---------------- generic FFMA TN GEMM (kept for N=49 x_proj) ----------------
__global__ void __launch_bounds__(256) gemm_tn(
    const float* __restrict__ A, const float* __restrict__ W,
    float* __restrict__ C, int M, int N, int K)
{
    __shared__ float As[16][132];
    __shared__ float Ws[16][68];
    int tid = threadIdx.x;
    int mb = blockIdx.y * 128;
    int nb = blockIdx.x * 64;
    int lr = tid >> 2;
    int lk = (tid & 3) << 2;
    int ty = tid >> 4;
    int tx = tid & 15;

    float acc[8][4];
#pragma unroll
    for (int i = 0; i < 8; i++)
#pragma unroll
        for (int j = 0; j < 4; j++) acc[i][j] = 0.f;

    const float* Arow0 = A + (size_t)(mb + lr) * K + lk;
    const float* Arow1 = Arow0 + (size_t)64 * K;
    bool wvalid = (nb + lr) < N;
    const float* Wrow = W + (size_t)(nb + lr) * K + lk;

    int ktiles = K >> 4;
    for (int kt = 0; kt < ktiles; kt++) {
        float4 a0 = *(const float4*)(Arow0 + kt*16);
        float4 a1 = *(const float4*)(Arow1 + kt*16);
        float4 w0 = wvalid ? *(const float4*)(Wrow + kt*16)
                           : make_float4(0.f, 0.f, 0.f, 0.f);
        __syncthreads();
        As[lk+0][lr] = a0.x; As[lk+1][lr] = a0.y; As[lk+2][lr] = a0.z; As[lk+3][lr] = a0.w;
        As[lk+0][lr+64] = a1.x; As[lk+1][lr+64] = a1.y; As[lk+2][lr+64] = a1.z; As[lk+3][lr+64] = a1.w;
        Ws[lk+0][lr] = w0.x; Ws[lk+1][lr] = w0.y; Ws[lk+2][lr] = w0.z; Ws[lk+3][lr] = w0.w;
        __syncthreads();
#pragma unroll
        for (int kk = 0; kk < 16; kk++) {
            float ra[8], rw[4];
            *(float4*)&ra[0] = *(const float4*)&As[kk][ty*8];
            *(float4*)&ra[4] = *(const float4*)&As[kk][ty*8 + 4];
            *(float4*)&rw[0] = *(const float4*)&Ws[kk][tx*4];
#pragma unroll
            for (int i = 0; i < 8; i++)
#pragma unroll
                for (int j = 0; j < 4; j++)
                    acc[i][j] = fmaf(ra[i], rw[j], acc[i][j]);
        }
    }
#pragma unroll
    for (int i = 0; i < 8; i++) {
        int m = mb + ty*8 + i;
#pragma unroll
        for (int j = 0; j < 4; j++) {
            int n = nb + tx*4 + j;
            if (n < N) C[(size_t)m*N + n] = acc[i][j];
        }
    }
}

// ---------------- depthwise causal conv1d + bias + silu (sliding window) ----------------
__global__ void __launch_bounds__(DINNER) conv_kernel(
    const float* __restrict__ conv_w, const float* __restrict__ conv_b, int layer)
{
    int d = threadIdx.x;
    int t0 = blockIdx.x * CONVT;
    int b = blockIdx.y;
    const float* wp = conv_w + (size_t)(layer*DINNER + d)*DCONV;
    float w0 = wp[0], w1 = wp[1], w2 = wp[2], w3 = wp[3];
    float bias = conv_b[layer*DINNER + d];
    size_t base = (size_t)(b*TSEQ)*(2*DINNER) + d;
    float x0 = (t0-3 >= 0) ? g_xz[base + (size_t)(t0-3)*(2*DINNER)] : 0.f;
    float x1 = (t0-2 >= 0) ? g_xz[base + (size_t)(t0-2)*(2*DINNER)] : 0.f;
    float x2 = (t0-1 >= 0) ? g_xz[base + (size_t)(t0-1)*(2*DINNER)] : 0.f;
#pragma unroll
    for (int i = 0; i < CONVT; i++) {
        int t = t0 + i;
        float x3 = g_xz[base + (size_t)t*(2*DINNER)];
        float s = bias;
        s = fmaf(w0, x0, s);
        s = fmaf(w1, x1, s);
        s = fmaf(w2, x2, s);
        s = fmaf(w3, x3, s);
        float sl = s / (1.f + __expf(-s));
        g_xconv[(size_t)(b*TSEQ + t)*DINNER + d] = sl;
        x0 = x1; x1 = x2; x2 = x3;
    }
}

// ---------------- delta = softplus(dt @ dt_w^T + dt_b), K=17 ----------------
__global__ void __launch_bounds__(DINNER) delta_kernel(
    const float* __restrict__ dt_w, const float* __restrict__ dt_b, int layer)
{
    __shared__ float sdbl[16][DTRANK];
    int m0 = blockIdx.x * 16;
    int tid = threadIdx.x;
    if (tid < 16*DTRANK) {
        int mm = tid / DTRANK, r = tid % DTRANK;
        sdbl[mm][r] = g_dbl[(size_t)(m0+mm)*NDBL + r];
    }
    __syncthreads();
    int d = tid;
    float wreg[DTRANK];
#pragma unroll
    for (int r = 0; r < DTRANK; r++)
        wreg[r] = dt_w[(size_t)(layer*DINNER + d)*DTRANK + r];
    float bias = dt_b[layer*DINNER + d];
    for (int mm = 0; mm < 16; mm++) {
        float s = bias;
#pragma unroll
        for (int r = 0; r < DTRANK; r++) s = fmaf(sdbl[mm][r], wreg[r], s);
        float sp = fmaxf(s, 0.f) + log1pf(__expf(-fabsf(s)));
        g_delta[(size_t)(m0+mm)*DINNER + d] = sp;
    }
}

// ---------------- chunked selective scan ----------------
__global__ void __launch_bounds__(DINNER) scan1_kernel(
    const float* __restrict__ A_log, int layer)
{
    int c = blockIdx.x, b = blockIdx.y;
    int d = threadIdx.x;
    const float LOG2E = 1.4426950408889634f;
    float A2[DSTATE];
#pragma unroll
    for (int n = 0; n < DSTATE; n++)
        A2[n] = -__expf(A_log[(size_t)(layer*DINNER + d)*DSTATE + n]) * LOG2E;
    float base = A2[0];
    bool fast = true;
#pragma unroll
    for (int n = 1; n < DSTATE; n++)
        fast = fast && (fabsf(A2[n] - (float)(n+1)*base)
                        <= 1e-4f*fabsf((float)(n+1)*base) + 1e-6f);

    float h[DSTATE];
#pragma unroll
    for (int n = 0; n < DSTATE; n++) h[n] = 0.f;
    float sumd = 0.f;
    __shared__ float sB[2][DSTATE];

    int m0 = b*TSEQ + c*CHUNK;
    for (int i = 0; i < CHUNK; i++) {
        int m = m0 + i;
        if (d < DSTATE) sB[i & 1][d] = g_dbl[(size_t)m*NDBL + DTRANK + d];
        float delta = g_delta[(size_t)m*DINNER + d];
        float u     = g_xconv[(size_t)m*DINNER + d];
        __syncthreads();
        float du = delta * u;
        if (fast) {
            float e1 = ex2(delta * base);
            float p = e1;
#pragma unroll
            for (int n = 0; n < DSTATE; n++) {
                h[n] = fmaf(p, h[n], du * sB[i & 1][n]);
                p *= e1;
            }
        } else {
#pragma unroll
            for (int n = 0; n < DSTATE; n++) {
                float a = ex2(delta * A2[n]);
                h[n] = fmaf(a, h[n], du * sB[i & 1][n]);
            }
        }
        sumd += delta;
    }
    size_t o = ((size_t)(b*NCHUNK + c)*DINNER + d)*DSTATE;
#pragma unroll
    for (int n = 0; n < DSTATE; n++) {
        g_hend[o + n] = h[n];
        g_P[o + n] = ex2(A2[n] * sumd);
    }
}

__global__ void scan2_kernel()
{
    int idx = blockIdx.x*blockDim.x + threadIdx.x;
    if (idx >= BATCH*DINNER) return;
    int b = idx / DINNER, d = idx % DINNER;
    float H[DSTATE];
#pragma unroll
    for (int n = 0; n < DSTATE; n++) H[n] = 0.f;
    for (int c = 0; c < NCHUNK; c++) {
        size_t o = ((size_t)(b*NCHUNK + c)*DINNER + d)*DSTATE;
#pragma unroll
        for (int n = 0; n < DSTATE; n++) g_Hin[o + n] = H[n];
#pragma unroll
        for (int n = 0; n < DSTATE; n++) H[n] = fmaf(g_P[o + n], H[n], g_hend[o + n]);
    }
}

__global__ void __launch_bounds__(DINNER) scan3_kernel(
    const float* __restrict__ A_log, const float* __restrict__ D_param, int layer)
{
    int c = blockIdx.x, b = blockIdx.y;
    int d = threadIdx.x;
    const float LOG2E = 1.4426950408889634f;
    float A2[DSTATE];
#pragma unroll
    for (int n = 0; n < DSTATE; n++)
        A2[n] = -__expf(A_log[(size_t)(layer*DINNER + d)*DSTATE + n]) * LOG2E;
    float base = A2[0];
    bool fast = true;
#pragma unroll
    for (int n = 1; n < DSTATE; n++)
        fast = fast && (fabsf(A2[n] - (float)(n+1)*base)
                        <= 1e-4f*fabsf((float)(n+1)*base) + 1e-6f);

    float h[DSTATE];
    size_t oin = ((size_t)(b*NCHUNK + c)*DINNER + d)*DSTATE;
#pragma unroll
    for (int n = 0; n < DSTATE; n++) h[n] = g_Hin[oin + n];
    float Dp = D_param[layer*DINNER + d];

    __shared__ float sBC[2][2*DSTATE];
    int m0 = b*TSEQ + c*CHUNK;
    for (int i = 0; i < CHUNK; i++) {
        int m = m0 + i;
        if (d < 2*DSTATE) sBC[i & 1][d] = g_dbl[(size_t)m*NDBL + DTRANK + d];
        float delta = g_delta[(size_t)m*DINNER + d];
        float u     = g_xconv[(size_t)m*DINNER + d];
        float z     = g_xz[(size_t)m*(2*DINNER) + DINNER + d];
        __syncthreads();
        float du = delta * u;
        float y = 0.f;
        if (fast) {
            float e1 = ex2(delta * base);
            float p = e1;
#pragma unroll
            for (int n = 0; n < DSTATE; n++) {
                h[n] = fmaf(p, h[n], du * sBC[i & 1][n]);
                y = fmaf(h[n], sBC[i & 1][DSTATE + n], y);
                p *= e1;
            }
        } else {
#pragma unroll
            for (int n = 0; n < DSTATE; n++) {
                float a = ex2(delta * A2[n]);
                h[n] = fmaf(a, h[n], du * sBC[i & 1][n]);
                y = fmaf(h[n], sBC[i & 1][DSTATE + n], y);
            }
        }
        float silz = z / (1.f + __expf(-z));
        float yg = fmaf(u, Dp, y) * silz;
        size_t om = (size_t)m*DINNER + d;
        split_bf16(yg, g_yg_hi[om], g_yg_lo[om]);
    }
}

// ---------------- host launcher ----------------
extern "C" void kernel_launch(void* const* d_in, const int* in_sizes, int n_in,
                              void* d_out, int out_size)
{
    (void)in_sizes; (void)n_in; (void)out_size;
    const int*   type_seq = (const int*)  d_in[0];
    const float* time_seq = (const float*)d_in[1];
    const float* temp_seq = (const float*)d_in[2];
    const float* emb      = (const float*)d_in[3];
    const float* norm_w   = (const float*)d_in[4];
    const float* norm_b   = (const float*)d_in[5];
    const float* in_w     = (const float*)d_in[6];
    const float* conv_w   = (const float*)d_in[7];
    const float* conv_b   = (const float*)d_in[8];
    const float* xproj_w  = (const float*)d_in[9];
    const float* dt_w     = (const float*)d_in[10];
    const float* dt_b     = (const float*)d_in[11];
    const float* A_log    = (const float*)d_in[12];
    const float* D_param  = (const float*)d_in[13];
    const float* out_w    = (const float*)d_in[14];
    const float* normf_w  = (const float*)d_in[15];
    const float* normf_b  = (const float*)d_in[16];
    float* out = (float*)d_out;

    float *p_xz, *p_xconv, *p_dbl, *p_h;
    cudaGetSymbolAddress((void**)&p_xz,    g_xz);
    cudaGetSymbolAddress((void**)&p_xconv, g_xconv);
    cudaGetSymbolAddress((void**)&p_dbl,   g_dbl);
    cudaGetSymbolAddress((void**)&p_h,     g_h);
    bf16 *p_hnh, *p_hnl, *p_ygh, *p_ygl, *p_w1h, *p_w1l, *p_w2h, *p_w2l;
    cudaGetSymbolAddress((void**)&p_hnh, g_hn_hi);
    cudaGetSymbolAddress((void**)&p_hnl, g_hn_lo);
    cudaGetSymbolAddress((void**)&p_ygh, g_yg_hi);
    cudaGetSymbolAddress((void**)&p_ygl, g_yg_lo);
    cudaGetSymbolAddress((void**)&p_w1h, g_w1_hi);
    cudaGetSymbolAddress((void**)&p_w1l, g_w1_lo);
    cudaGetSymbolAddress((void**)&p_w2h, g_w2_hi);
    cudaGetSymbolAddress((void**)&p_w2l, g_w2_lo);

    embed_kernel<<<MROWS, DDIM>>>(type_seq, time_seq, temp_seq, emb);

    for (int l = 0; l < NLAYER; l++) {
        addnorm_kernel<<<MROWS, 128>>>(norm_w + l*DDIM, norm_b + l*DDIM, l > 0);

        // weight split for in_proj: (1088, 272) -> (1088, 288)
        convert_w<<<(2*DINNER*KPAD1 + 255)/256, 256>>>(
            in_w + (size_t)l*2*DINNER*DDIM, p_w1h, p_w1l, 2*DINNER, DDIM, KPAD1);

        // xz = hn @ in_w^T : (8192,288)x(1088,288)^T  [bf16-split tensor cores]
        gemm_bf16split<<<dim3((2*DINNER + 63)/64, MROWS/128), 256>>>(
            p_hnh, p_hnl, p_w1h, p_w1l, p_xz, MROWS, 2*DINNER, KPAD1);

        conv_kernel<<<dim3(TSEQ/CONVT, BATCH), DINNER>>>(conv_w, conv_b, l);

        // dbl = xconv @ xproj_w^T : (8192,544)x(49,544)^T  [FFMA, tiny N]
        gemm_tn<<<dim3((NDBL + 63)/64, MROWS/128), 256>>>(
            p_xconv, xproj_w + (size_t)l*NDBL*DINNER, p_dbl, MROWS, NDBL, DINNER);

        delta_kernel<<<MROWS/16, DINNER>>>(dt_w, dt_b, l);

        scan1_kernel<<<dim3(NCHUNK, BATCH), DINNER>>>(A_log, l);
        scan2_kernel<<<(BATCH*DINNER + 255)/256, 256>>>();
        scan3_kernel<<<dim3(NCHUNK, BATCH), DINNER>>>(A_log, D_param, l);

        // weight split for out_proj: (272, 544) -> (272, 544)
        convert_w<<<(DDIM*DINNER + 255)/256, 256>>>(
            out_w + (size_t)l*DDIM*DINNER, p_w2h, p_w2l, DDIM, DINNER, DINNER);

        // h = yg @ out_w^T : (8192,544)x(272,544)^T  [bf16-split tensor cores]
        gemm_bf16split<<<dim3((DDIM + 63)/64, MROWS/128), 256>>>(
            p_ygh, p_ygl, p_w2h, p_w2l, p_h, MROWS, DDIM, DINNER);
    }

    final_kernel<<<BATCH*LQ, 128>>>(normf_w, normf_b, out);
}

// round 4
// speedup vs baseline: 1.3603x; 1.0589x over previous
#include <cuda_runtime.h>
#include <cuda_bf16.h>
#include <math.h>
#include <stdint.h>
#include <mma.h>

using namespace nvcuda;

#define BATCH   4
#define LQ      1024
#define TSEQ    2048
#define DMODEL  256
#define DTIME   16
#define DDIM    272
#define KPAD1   288
#define NLAYER  4
#define DINNER  544
#define DSTATE  16
#define DCONV   4
#define DTRANK  17
#define NDBL    (DTRANK + 2*DSTATE)   // 49
#define MROWS   (BATCH*TSEQ)          // 8192
#define NCHUNK  32
#define CHUNK   (TSEQ/NCHUNK)         // 64
#define CONVT   16

typedef __nv_bfloat16 bf16;

// ---------------- scratch ----------------
__device__ float g_h   [MROWS*DDIM];
__device__ float g_res [MROWS*DDIM];
__device__ float g_xz  [MROWS*2*DINNER];
__device__ float g_xconv[MROWS*DINNER];
__device__ float g_dbl [MROWS*NDBL];
__device__ float g_delta[MROWS*DINNER];
__device__ float g_hend[BATCH*NCHUNK*DINNER*DSTATE];
__device__ float g_P   [BATCH*NCHUNK*DINNER*DSTATE];
__device__ float g_Hin [BATCH*NCHUNK*DINNER*DSTATE];
__device__ float g_A2  [NLAYER*DINNER*DSTATE];
// bf16 split activation buffers
__device__ bf16 g_hn_hi[MROWS*KPAD1];
__device__ bf16 g_hn_lo[MROWS*KPAD1];
__device__ bf16 g_yg_hi[MROWS*DINNER];
__device__ bf16 g_yg_lo[MROWS*DINNER];
// bf16 split weight buffers, all layers
__device__ bf16 g_w1_hi[NLAYER*2*DINNER*KPAD1];
__device__ bf16 g_w1_lo[NLAYER*2*DINNER*KPAD1];
__device__ bf16 g_w2_hi[NLAYER*DDIM*DINNER];
__device__ bf16 g_w2_lo[NLAYER*DDIM*DINNER];

__device__ __forceinline__ float ex2(float x) {
    float y; asm("ex2.approx.ftz.f32 %0, %1;" : "=f"(y) : "f"(x)); return y;
}
__device__ __forceinline__ void split_bf16(float v, bf16& hi, bf16& lo) {
    hi = __float2bfloat16_rn(v);
    lo = __float2bfloat16_rn(v - __bfloat162float(hi));
}

// ---------------- embedding ----------------
__global__ void __launch_bounds__(DDIM) embed_kernel(
    const int* __restrict__ type_seq, const float* __restrict__ time_seq,
    const float* __restrict__ temp_seq, const float* __restrict__ emb)
{
    int row = blockIdx.x;
    int d = threadIdx.x;
    int b = row / TSEQ, t = row % TSEQ;
    float v;
    if (t < LQ) {
        if (d < DMODEL) {
            v = tanhf(emb[(size_t)type_seq[b*LQ + t]*DMODEL + d]);
        } else {
            int j = d - DMODEL;
            int i = j >> 1;
            float div = expf(-0.57564627324851142f * (float)(2*i));
            float arg = time_seq[b*LQ + t] * div;
            v = (j & 1) ? cosf(arg) : sinf(arg);
        }
    } else {
        v = (d < DMODEL) ? 0.f
                         : temp_seq[(size_t)(b*LQ + (t - LQ))*DTIME + (d - DMODEL)];
    }
    g_h[(size_t)row*DDIM + d] = v;
}

// ---------------- one-time prep: weight splits + A2 ----------------
__global__ void __launch_bounds__(256) convert_w1_all(const float* __restrict__ in_w)
{
    int idx = blockIdx.x*256 + threadIdx.x;
    const int per = 2*DINNER*KPAD1;
    if (idx >= NLAYER*per) return;
    int l = idx / per, rem = idx - l*per;
    int r = rem / KPAD1, c = rem - r*KPAD1;
    float v = (c < DDIM) ? in_w[((size_t)l*2*DINNER + r)*DDIM + c] : 0.f;
    split_bf16(v, g_w1_hi[idx], g_w1_lo[idx]);
}
__global__ void __launch_bounds__(256) convert_w2_all(const float* __restrict__ out_w)
{
    int idx = blockIdx.x*256 + threadIdx.x;
    if (idx >= NLAYER*DDIM*DINNER) return;
    split_bf16(out_w[idx], g_w2_hi[idx], g_w2_lo[idx]);
}
__global__ void __launch_bounds__(256) prep_A2(const float* __restrict__ A_log)
{
    int idx = blockIdx.x*256 + threadIdx.x;
    if (idx >= NLAYER*DINNER*DSTATE) return;
    g_A2[idx] = -__expf(A_log[idx]) * 1.4426950408889634f;
}

// ---------------- residual add + layernorm -> bf16 split hn ----------------
__global__ void __launch_bounds__(128) addnorm_kernel(
    const float* __restrict__ gamma, const float* __restrict__ beta, int addflag)
{
    int row = blockIdx.x;
    int tid = threadIdx.x;
    float v[3];
    float s = 0.f, s2 = 0.f;
#pragma unroll
    for (int j = 0; j < 3; j++) {
        int d = tid + j*128;
        float x = 0.f;
        if (d < DDIM) {
            x = g_h[(size_t)row*DDIM + d];
            if (addflag) x += g_res[(size_t)row*DDIM + d];
        }
        v[j] = x; s += x; s2 += x*x;
    }
#pragma unroll
    for (int o = 16; o > 0; o >>= 1) {
        s  += __shfl_down_sync(0xffffffffu, s,  o);
        s2 += __shfl_down_sync(0xffffffffu, s2, o);
    }
    __shared__ float ss[4], ss2[4];
    if ((tid & 31) == 0) { ss[tid >> 5] = s; ss2[tid >> 5] = s2; }
    __syncthreads();
    if (tid == 0) {
        float a  = ss[0]+ss[1]+ss[2]+ss[3];
        float a2 = ss2[0]+ss2[1]+ss2[2]+ss2[3];
        float mean = a * (1.f/DDIM);
        float var  = a2 * (1.f/DDIM) - mean*mean;
        ss[0] = mean;
        ss2[0] = rsqrtf(var + 1e-5f);
    }
    __syncthreads();
    float mean = ss[0], rstd = ss2[0];
#pragma unroll
    for (int j = 0; j < 3; j++) {
        int d = tid + j*128;
        if (d < DDIM) {
            g_res[(size_t)row*DDIM + d] = v[j];
            float hn = (v[j]-mean)*rstd*gamma[d] + beta[d];
            split_bf16(hn, g_hn_hi[(size_t)row*KPAD1 + d], g_hn_lo[(size_t)row*KPAD1 + d]);
        } else if (d < KPAD1) {
            g_hn_hi[(size_t)row*KPAD1 + d] = __float2bfloat16(0.f);
            g_hn_lo[(size_t)row*KPAD1 + d] = __float2bfloat16(0.f);
        }
    }
}

// ---------------- final add + layernorm -> output ----------------
__global__ void __launch_bounds__(128) final_kernel(
    const float* __restrict__ gamma, const float* __restrict__ beta,
    float* __restrict__ out)
{
    int rowo = blockIdx.x;
    int tid = threadIdx.x;
    int b = rowo / LQ, t = rowo % LQ;
    int m = b*TSEQ + t;
    float v[3];
    float s = 0.f, s2 = 0.f;
#pragma unroll
    for (int j = 0; j < 3; j++) {
        int d = tid + j*128;
        float x = 0.f;
        if (d < DDIM) x = g_h[(size_t)m*DDIM + d] + g_res[(size_t)m*DDIM + d];
        v[j] = x; s += x; s2 += x*x;
    }
#pragma unroll
    for (int o = 16; o > 0; o >>= 1) {
        s  += __shfl_down_sync(0xffffffffu, s,  o);
        s2 += __shfl_down_sync(0xffffffffu, s2, o);
    }
    __shared__ float ss[4], ss2[4];
    if ((tid & 31) == 0) { ss[tid >> 5] = s; ss2[tid >> 5] = s2; }
    __syncthreads();
    if (tid == 0) {
        float a  = ss[0]+ss[1]+ss[2]+ss[3];
        float a2 = ss2[0]+ss2[1]+ss2[2]+ss2[3];
        float mean = a * (1.f/DDIM);
        float var  = a2 * (1.f/DDIM) - mean*mean;
        ss[0] = mean;
        ss2[0] = rsqrtf(var + 1e-5f);
    }
    __syncthreads();
    float mean = ss[0], rstd = ss2[0];
#pragma unroll
    for (int j = 0; j < 3; j++) {
        int d = tid + j*128;
        if (d < DDIM)
            out[(size_t)rowo*DDIM + d] = (v[j]-mean)*rstd*gamma[d] + beta[d];
    }
}

// ---------------- bf16-split tensor-core GEMM: C[M,N] = A @ W^T ----------------
// BM=128, BN=128, BK=32, 256 threads, 8 warps (2 in M x 4 in N), warp tile 64x32.
// C = Ahi*Whi + Ahi*Wlo + Alo*Whi  (fp32 accum).
#define SPAD 8
__global__ void __launch_bounds__(256) gemm_bf16split(
    const bf16* __restrict__ Ahi, const bf16* __restrict__ Alo,
    const bf16* __restrict__ Whi, const bf16* __restrict__ Wlo,
    float* __restrict__ C, int M, int N, int Kpad)
{
    __shared__ bf16 sAhi[128][32+SPAD];
    __shared__ bf16 sAlo[128][32+SPAD];
    __shared__ bf16 sWhi[128][32+SPAD];
    __shared__ bf16 sWlo[128][32+SPAD];

    int tid = threadIdx.x;
    int warp = tid >> 5;
    int wm = warp >> 2;          // 0..1  (64-row slab)
    int wn = warp & 3;           // 0..3  (32-col slab)
    int mb = blockIdx.y * 128;
    int nb = blockIdx.x * 128;

    // loaders: 512 uint4 per array, 2 per thread
    int aIdx0 = tid*2, aIdx1 = tid*2 + 1;
    int r0 = aIdx0 >> 2, c0 = (aIdx0 & 3) * 8;
    int r1 = aIdx1 >> 2, c1 = (aIdx1 & 3) * 8;
    bool wv0 = (nb + r0) < N;
    bool wv1 = (nb + r1) < N;

    const uint4* pAhi0 = (const uint4*)(Ahi + (size_t)(mb + r0)*Kpad + c0);
    const uint4* pAhi1 = (const uint4*)(Ahi + (size_t)(mb + r1)*Kpad + c1);
    const uint4* pAlo0 = (const uint4*)(Alo + (size_t)(mb + r0)*Kpad + c0);
    const uint4* pAlo1 = (const uint4*)(Alo + (size_t)(mb + r1)*Kpad + c1);
    const uint4* pWhi0 = (const uint4*)(Whi + (size_t)(nb + r0)*Kpad + c0);
    const uint4* pWhi1 = (const uint4*)(Whi + (size_t)(nb + r1)*Kpad + c1);
    const uint4* pWlo0 = (const uint4*)(Wlo + (size_t)(nb + r0)*Kpad + c0);
    const uint4* pWlo1 = (const uint4*)(Wlo + (size_t)(nb + r1)*Kpad + c1);
    uint4 z4 = make_uint4(0,0,0,0);

    wmma::fragment<wmma::accumulator,16,16,16,float> acc[4][2];
#pragma unroll
    for (int i = 0; i < 4; i++)
#pragma unroll
        for (int j = 0; j < 2; j++) wmma::fill_fragment(acc[i][j], 0.f);

    int ktiles = Kpad >> 5;
    uint4 rAh0 = pAhi0[0], rAh1 = pAhi1[0];
    uint4 rAl0 = pAlo0[0], rAl1 = pAlo1[0];
    uint4 rWh0 = wv0 ? pWhi0[0] : z4, rWh1 = wv1 ? pWhi1[0] : z4;
    uint4 rWl0 = wv0 ? pWlo0[0] : z4, rWl1 = wv1 ? pWlo1[0] : z4;

    for (int kt = 0; kt < ktiles; kt++) {
        __syncthreads();
        *(uint4*)&sAhi[r0][c0] = rAh0;
        *(uint4*)&sAhi[r1][c1] = rAh1;
        *(uint4*)&sAlo[r0][c0] = rAl0;
        *(uint4*)&sAlo[r1][c1] = rAl1;
        *(uint4*)&sWhi[r0][c0] = rWh0;
        *(uint4*)&sWhi[r1][c1] = rWh1;
        *(uint4*)&sWlo[r0][c0] = rWl0;
        *(uint4*)&sWlo[r1][c1] = rWl1;
        __syncthreads();
        if (kt + 1 < ktiles) {
            int o = (kt+1) * 4;
            rAh0 = pAhi0[o]; rAh1 = pAhi1[o];
            rAl0 = pAlo0[o]; rAl1 = pAlo1[o];
            rWh0 = wv0 ? pWhi0[o] : z4; rWh1 = wv1 ? pWhi1[o] : z4;
            rWl0 = wv0 ? pWlo0[o] : z4; rWl1 = wv1 ? pWlo1[o] : z4;
        }
#pragma unroll
        for (int ks = 0; ks < 32; ks += 16) {
            wmma::fragment<wmma::matrix_a,16,16,16,bf16,wmma::row_major> ahi[4], alo[4];
            wmma::fragment<wmma::matrix_b,16,16,16,bf16,wmma::col_major> bhi[2], blo[2];
#pragma unroll
            for (int i = 0; i < 4; i++) {
                wmma::load_matrix_sync(ahi[i], &sAhi[wm*64 + i*16][ks], 32+SPAD);
                wmma::load_matrix_sync(alo[i], &sAlo[wm*64 + i*16][ks], 32+SPAD);
            }
#pragma unroll
            for (int j = 0; j < 2; j++) {
                wmma::load_matrix_sync(bhi[j], &sWhi[wn*32 + j*16][ks], 32+SPAD);
                wmma::load_matrix_sync(blo[j], &sWlo[wn*32 + j*16][ks], 32+SPAD);
            }
#pragma unroll
            for (int i = 0; i < 4; i++)
#pragma unroll
                for (int j = 0; j < 2; j++) {
                    wmma::mma_sync(acc[i][j], ahi[i], bhi[j], acc[i][j]);
                    wmma::mma_sync(acc[i][j], ahi[i], blo[j], acc[i][j]);
                    wmma::mma_sync(acc[i][j], alo[i], bhi[j], acc[i][j]);
                }
        }
    }
#pragma unroll
    for (int i = 0; i < 4; i++)
#pragma unroll
        for (int j = 0; j < 2; j++) {
            int n0 = nb + wn*32 + j*16;
            if (n0 < N)
                wmma::store_matrix_sync(C + (size_t)(mb + wm*64 + i*16)*N + n0,
                                        acc[i][j], N, wmma::mem_row_major);
        }
}

// ---------------- FFMA TN GEMM (x_proj, N=49) ----------------
__global__ void __launch_bounds__(256) gemm_tn(
    const float* __restrict__ A, const float* __restrict__ W,
    float* __restrict__ C, int M, int N, int K)
{
    __shared__ float As[16][132];
    __shared__ float Ws[16][68];
    int tid = threadIdx.x;
    int mb = blockIdx.y * 128;
    int nb = blockIdx.x * 64;
    int lr = tid >> 2;
    int lk = (tid & 3) << 2;
    int ty = tid >> 4;
    int tx = tid & 15;

    float acc[8][4];
#pragma unroll
    for (int i = 0; i < 8; i++)
#pragma unroll
        for (int j = 0; j < 4; j++) acc[i][j] = 0.f;

    const float* Arow0 = A + (size_t)(mb + lr) * K + lk;
    const float* Arow1 = Arow0 + (size_t)64 * K;
    bool wvalid = (nb + lr) < N;
    const float* Wrow = W + (size_t)(nb + lr) * K + lk;

    int ktiles = K >> 4;
    for (int kt = 0; kt < ktiles; kt++) {
        float4 a0 = *(const float4*)(Arow0 + kt*16);
        float4 a1 = *(const float4*)(Arow1 + kt*16);
        float4 w0 = wvalid ? *(const float4*)(Wrow + kt*16)
                           : make_float4(0.f, 0.f, 0.f, 0.f);
        __syncthreads();
        As[lk+0][lr] = a0.x; As[lk+1][lr] = a0.y; As[lk+2][lr] = a0.z; As[lk+3][lr] = a0.w;
        As[lk+0][lr+64] = a1.x; As[lk+1][lr+64] = a1.y; As[lk+2][lr+64] = a1.z; As[lk+3][lr+64] = a1.w;
        Ws[lk+0][lr] = w0.x; Ws[lk+1][lr] = w0.y; Ws[lk+2][lr] = w0.z; Ws[lk+3][lr] = w0.w;
        __syncthreads();
#pragma unroll
        for (int kk = 0; kk < 16; kk++) {
            float ra[8], rw[4];
            *(float4*)&ra[0] = *(const float4*)&As[kk][ty*8];
            *(float4*)&ra[4] = *(const float4*)&As[kk][ty*8 + 4];
            *(float4*)&rw[0] = *(const float4*)&Ws[kk][tx*4];
#pragma unroll
            for (int i = 0; i < 8; i++)
#pragma unroll
                for (int j = 0; j < 4; j++)
                    acc[i][j] = fmaf(ra[i], rw[j], acc[i][j]);
        }
    }
#pragma unroll
    for (int i = 0; i < 8; i++) {
        int m = mb + ty*8 + i;
#pragma unroll
        for (int j = 0; j < 4; j++) {
            int n = nb + tx*4 + j;
            if (n < N) C[(size_t)m*N + n] = acc[i][j];
        }
    }
}

// ---------------- depthwise causal conv1d + bias + silu ----------------
__global__ void __launch_bounds__(DINNER) conv_kernel(
    const float* __restrict__ conv_w, const float* __restrict__ conv_b, int layer)
{
    int d = threadIdx.x;
    int t0 = blockIdx.x * CONVT;
    int b = blockIdx.y;
    const float* wp = conv_w + (size_t)(layer*DINNER + d)*DCONV;
    float w0 = wp[0], w1 = wp[1], w2 = wp[2], w3 = wp[3];
    float bias = conv_b[layer*DINNER + d];
    size_t base = (size_t)(b*TSEQ)*(2*DINNER) + d;
    float x0 = (t0-3 >= 0) ? g_xz[base + (size_t)(t0-3)*(2*DINNER)] : 0.f;
    float x1 = (t0-2 >= 0) ? g_xz[base + (size_t)(t0-2)*(2*DINNER)] : 0.f;
    float x2 = (t0-1 >= 0) ? g_xz[base + (size_t)(t0-1)*(2*DINNER)] : 0.f;
#pragma unroll
    for (int i = 0; i < CONVT; i++) {
        int t = t0 + i;
        float x3 = g_xz[base + (size_t)t*(2*DINNER)];
        float s = bias;
        s = fmaf(w0, x0, s);
        s = fmaf(w1, x1, s);
        s = fmaf(w2, x2, s);
        s = fmaf(w3, x3, s);
        float sl = s / (1.f + __expf(-s));
        g_xconv[(size_t)(b*TSEQ + t)*DINNER + d] = sl;
        x0 = x1; x1 = x2; x2 = x3;
    }
}

// ---------------- delta = softplus(dt @ dt_w^T + dt_b) ----------------
__global__ void __launch_bounds__(DINNER) delta_kernel(
    const float* __restrict__ dt_w, const float* __restrict__ dt_b, int layer)
{
    __shared__ float sdbl[16][DTRANK];
    int m0 = blockIdx.x * 16;
    int tid = threadIdx.x;
    if (tid < 16*DTRANK) {
        int mm = tid / DTRANK, r = tid % DTRANK;
        sdbl[mm][r] = g_dbl[(size_t)(m0+mm)*NDBL + r];
    }
    __syncthreads();
    int d = tid;
    float wreg[DTRANK];
#pragma unroll
    for (int r = 0; r < DTRANK; r++)
        wreg[r] = dt_w[(size_t)(layer*DINNER + d)*DTRANK + r];
    float bias = dt_b[layer*DINNER + d];
    for (int mm = 0; mm < 16; mm++) {
        float s = bias;
#pragma unroll
        for (int r = 0; r < DTRANK; r++) s = fmaf(sdbl[mm][r], wreg[r], s);
        float sp = fmaxf(s, 0.f) + log1pf(__expf(-fabsf(s)));
        g_delta[(size_t)(m0+mm)*DINNER + d] = sp;
    }
}

// ---------------- chunked selective scan ----------------
__global__ void __launch_bounds__(DINNER) scan1_kernel(int layer)
{
    int c = blockIdx.x, b = blockIdx.y;
    int d = threadIdx.x;
    __shared__ float sB[CHUNK][DSTATE];
    int m0 = b*TSEQ + c*CHUNK;
    for (int idx = d; idx < CHUNK*DSTATE; idx += DINNER) {
        int i = idx >> 4, n = idx & 15;
        sB[i][n] = g_dbl[(size_t)(m0+i)*NDBL + DTRANK + n];
    }
    float A2[DSTATE];
#pragma unroll
    for (int n = 0; n < DSTATE; n++)
        A2[n] = g_A2[(size_t)(layer*DINNER + d)*DSTATE + n];
    float base = A2[0];
    bool fast = true;
#pragma unroll
    for (int n = 1; n < DSTATE; n++)
        fast = fast && (fabsf(A2[n] - (float)(n+1)*base)
                        <= 1e-4f*fabsf((float)(n+1)*base) + 1e-6f);

    float h[DSTATE];
#pragma unroll
    for (int n = 0; n < DSTATE; n++) h[n] = 0.f;
    float sumd = 0.f;
    __syncthreads();

    for (int i = 0; i < CHUNK; i++) {
        int m = m0 + i;
        float delta = g_delta[(size_t)m*DINNER + d];
        float u     = g_xconv[(size_t)m*DINNER + d];
        float du = delta * u;
        if (fast) {
            float e1 = ex2(delta * base);
            float p = e1;
#pragma unroll
            for (int n = 0; n < DSTATE; n++) {
                h[n] = fmaf(p, h[n], du * sB[i][n]);
                p *= e1;
            }
        } else {
#pragma unroll
            for (int n = 0; n < DSTATE; n++) {
                float a = ex2(delta * A2[n]);
                h[n] = fmaf(a, h[n], du * sB[i][n]);
            }
        }
        sumd += delta;
    }
    size_t o = ((size_t)(b*NCHUNK + c)*DINNER + d)*DSTATE;
#pragma unroll
    for (int n = 0; n < DSTATE; n++) {
        g_hend[o + n] = h[n];
        g_P[o + n] = ex2(A2[n] * sumd);
    }
}

__global__ void scan2_kernel()
{
    int idx = blockIdx.x*blockDim.x + threadIdx.x;
    if (idx >= BATCH*DINNER) return;
    int b = idx / DINNER, d = idx % DINNER;
    float H[DSTATE];
#pragma unroll
    for (int n = 0; n < DSTATE; n++) H[n] = 0.f;
    for (int c = 0; c < NCHUNK; c++) {
        size_t o = ((size_t)(b*NCHUNK + c)*DINNER + d)*DSTATE;
#pragma unroll
        for (int n = 0; n < DSTATE; n++) g_Hin[o + n] = H[n];
#pragma unroll
        for (int n = 0; n < DSTATE; n++) H[n] = fmaf(g_P[o + n], H[n], g_hend[o + n]);
    }
}

__global__ void __launch_bounds__(DINNER) scan3_kernel(
    const float* __restrict__ D_param, int layer)
{
    int c = blockIdx.x, b = blockIdx.y;
    int d = threadIdx.x;
    __shared__ float sBC[CHUNK][2*DSTATE];
    int m0 = b*TSEQ + c*CHUNK;
    for (int idx = d; idx < CHUNK*2*DSTATE; idx += DINNER) {
        int i = idx >> 5, n = idx & 31;
        sBC[i][n] = g_dbl[(size_t)(m0+i)*NDBL + DTRANK + n];
    }
    float A2[DSTATE];
#pragma unroll
    for (int n = 0; n < DSTATE; n++)
        A2[n] = g_A2[(size_t)(layer*DINNER + d)*DSTATE + n];
    float base = A2[0];
    bool fast = true;
#pragma unroll
    for (int n = 1; n < DSTATE; n++)
        fast = fast && (fabsf(A2[n] - (float)(n+1)*base)
                        <= 1e-4f*fabsf((float)(n+1)*base) + 1e-6f);

    float h[DSTATE];
    size_t oin = ((size_t)(b*NCHUNK + c)*DINNER + d)*DSTATE;
#pragma unroll
    for (int n = 0; n < DSTATE; n++) h[n] = g_Hin[oin + n];
    float Dp = D_param[layer*DINNER + d];
    __syncthreads();

    for (int i = 0; i < CHUNK; i++) {
        int m = m0 + i;
        float delta = g_delta[(size_t)m*DINNER + d];
        float u     = g_xconv[(size_t)m*DINNER + d];
        float z     = g_xz[(size_t)m*(2*DINNER) + DINNER + d];
        float du = delta * u;
        float y = 0.f;
        if (fast) {
            float e1 = ex2(delta * base);
            float p = e1;
#pragma unroll
            for (int n = 0; n < DSTATE; n++) {
                h[n] = fmaf(p, h[n], du * sBC[i][n]);
                y = fmaf(h[n], sBC[i][DSTATE + n], y);
                p *= e1;
            }
        } else {
#pragma unroll
            for (int n = 0; n < DSTATE; n++) {
                float a = ex2(delta * A2[n]);
                h[n] = fmaf(a, h[n], du * sBC[i][n]);
                y = fmaf(h[n], sBC[i][DSTATE + n], y);
            }
        }
        float silz = z / (1.f + __expf(-z));
        float yg = fmaf(u, Dp, y) * silz;
        size_t om = (size_t)m*DINNER + d;
        split_bf16(yg, g_yg_hi[om], g_yg_lo[om]);
    }
}

// ---------------- host launcher ----------------
extern "C" void kernel_launch(void* const* d_in, const int* in_sizes, int n_in,
                              void* d_out, int out_size)
{
    (void)in_sizes; (void)n_in; (void)out_size;
    const int*   type_seq = (const int*)  d_in[0];
    const float* time_seq = (const float*)d_in[1];
    const float* temp_seq = (const float*)d_in[2];
    const float* emb      = (const float*)d_in[3];
    const float* norm_w   = (const float*)d_in[4];
    const float* norm_b   = (const float*)d_in[5];
    const float* in_w     = (const float*)d_in[6];
    const float* conv_w   = (const float*)d_in[7];
    const float* conv_b   = (const float*)d_in[8];
    const float* xproj_w  = (const float*)d_in[9];
    const float* dt_w     = (const float*)d_in[10];
    const float* dt_b     = (const float*)d_in[11];
    const float* A_log    = (const float*)d_in[12];
    const float* D_param  = (const float*)d_in[13];
    const float* out_w    = (const float*)d_in[14];
    const float* normf_w  = (const float*)d_in[15];
    const float* normf_b  = (const float*)d_in[16];
    float* out = (float*)d_out;

    float *p_xz, *p_xconv, *p_dbl, *p_h;
    cudaGetSymbolAddress((void**)&p_xz,    g_xz);
    cudaGetSymbolAddress((void**)&p_xconv, g_xconv);
    cudaGetSymbolAddress((void**)&p_dbl,   g_dbl);
    cudaGetSymbolAddress((void**)&p_h,     g_h);
    bf16 *p_hnh, *p_hnl, *p_ygh, *p_ygl, *p_w1h, *p_w1l, *p_w2h, *p_w2l;
    cudaGetSymbolAddress((void**)&p_hnh, g_hn_hi);
    cudaGetSymbolAddress((void**)&p_hnl, g_hn_lo);
    cudaGetSymbolAddress((void**)&p_ygh, g_yg_hi);
    cudaGetSymbolAddress((void**)&p_ygl, g_yg_lo);
    cudaGetSymbolAddress((void**)&p_w1h, g_w1_hi);
    cudaGetSymbolAddress((void**)&p_w1l, g_w1_lo);
    cudaGetSymbolAddress((void**)&p_w2h, g_w2_hi);
    cudaGetSymbolAddress((void**)&p_w2l, g_w2_lo);

    embed_kernel<<<MROWS, DDIM>>>(type_seq, time_seq, temp_seq, emb);
    convert_w1_all<<<(NLAYER*2*DINNER*KPAD1 + 255)/256, 256>>>(in_w);
    convert_w2_all<<<(NLAYER*DDIM*DINNER + 255)/256, 256>>>(out_w);
    prep_A2<<<(NLAYER*DINNER*DSTATE + 255)/256, 256>>>(A_log);

    for (int l = 0; l < NLAYER; l++) {
        addnorm_kernel<<<MROWS, 128>>>(norm_w + l*DDIM, norm_b + l*DDIM, l > 0);

        // xz = hn @ in_w^T : (8192,288)x(1088,288)^T
        gemm_bf16split<<<dim3((2*DINNER + 127)/128, MROWS/128), 256>>>(
            p_hnh, p_hnl,
            p_w1h + (size_t)l*2*DINNER*KPAD1, p_w1l + (size_t)l*2*DINNER*KPAD1,
            p_xz, MROWS, 2*DINNER, KPAD1);

        conv_kernel<<<dim3(TSEQ/CONVT, BATCH), DINNER>>>(conv_w, conv_b, l);

        // dbl = xconv @ xproj_w^T : (8192,544)x(49,544)^T
        gemm_tn<<<dim3(1, MROWS/128), 256>>>(
            p_xconv, xproj_w + (size_t)l*NDBL*DINNER, p_dbl, MROWS, NDBL, DINNER);

        delta_kernel<<<MROWS/16, DINNER>>>(dt_w, dt_b, l);

        scan1_kernel<<<dim3(NCHUNK, BATCH), DINNER>>>(l);
        scan2_kernel<<<(BATCH*DINNER + 255)/256, 256>>>();
        scan3_kernel<<<dim3(NCHUNK, BATCH), DINNER>>>(D_param, l);

        // h = yg @ out_w^T : (8192,544)x(272,544)^T
        gemm_bf16split<<<dim3((DDIM + 127)/128, MROWS/128), 256>>>(
            p_ygh, p_ygl,
            p_w2h + (size_t)l*DDIM*DINNER, p_w2l + (size_t)l*DDIM*DINNER,
            p_h, MROWS, DDIM, DINNER);
    }

    final_kernel<<<BATCH*LQ, 128>>>(normf_w, normf_b, out);
}

// round 5
// speedup vs baseline: 2.0995x; 1.5434x over previous
#include <cuda_runtime.h>
#include <cuda_bf16.h>
#include <math.h>
#include <stdint.h>
#include <mma.h>

using namespace nvcuda;

#define BATCH   4
#define LQ      1024
#define TSEQ    2048
#define DMODEL  256
#define DTIME   16
#define DDIM    272
#define KPAD1   288
#define NLAYER  4
#define DINNER  544
#define DSTATE  16
#define DCONV   4
#define DTRANK  17
#define NDBL    (DTRANK + 2*DSTATE)   // 49
#define MROWS   (BATCH*TSEQ)          // 8192
#define NCHUNK  32
#define CHUNK   (TSEQ/NCHUNK)         // 64
#define CONVT   16

typedef __nv_bfloat16 bf16;

// ---------------- scratch ----------------
__device__ float g_h   [MROWS*DDIM];
__device__ float g_res [MROWS*DDIM];
__device__ float g_xz  [MROWS*2*DINNER];
__device__ float g_xconv[MROWS*DINNER];
__device__ float g_dbl [MROWS*NDBL];
__device__ float g_hend[BATCH*NCHUNK*DINNER*DSTATE];
__device__ float g_P   [BATCH*NCHUNK*DINNER*DSTATE];
__device__ float g_Hin [BATCH*NCHUNK*DINNER*DSTATE];
__device__ float g_A2  [NLAYER*DINNER*DSTATE];
__device__ bf16 g_hn_hi[MROWS*KPAD1];
__device__ bf16 g_hn_lo[MROWS*KPAD1];
__device__ bf16 g_yg_hi[MROWS*DINNER];
__device__ bf16 g_yg_lo[MROWS*DINNER];
__device__ bf16 g_w1_hi[NLAYER*2*DINNER*KPAD1];
__device__ bf16 g_w1_lo[NLAYER*2*DINNER*KPAD1];
__device__ bf16 g_w2_hi[NLAYER*DDIM*DINNER];
__device__ bf16 g_w2_lo[NLAYER*DDIM*DINNER];

__device__ __forceinline__ float ex2(float x) {
    float y; asm("ex2.approx.ftz.f32 %0, %1;" : "=f"(y) : "f"(x)); return y;
}
__device__ __forceinline__ void split_bf16(float v, bf16& hi, bf16& lo) {
    hi = __float2bfloat16_rn(v);
    lo = __float2bfloat16_rn(v - __bfloat162float(hi));
}
__device__ __forceinline__ void cp16(uint32_t saddr, const void* g, int srcsz) {
    asm volatile("cp.async.ca.shared.global [%0], [%1], 16, %2;\n"
                 :: "r"(saddr), "l"(g), "r"(srcsz));
}
__device__ __forceinline__ void cp_commit() { asm volatile("cp.async.commit_group;\n"); }
template<int NN> __device__ __forceinline__ void cp_wait() {
    asm volatile("cp.async.wait_group %0;\n" :: "n"(NN));
}

// ---------------- embedding ----------------
__global__ void __launch_bounds__(DDIM) embed_kernel(
    const int* __restrict__ type_seq, const float* __restrict__ time_seq,
    const float* __restrict__ temp_seq, const float* __restrict__ emb)
{
    int row = blockIdx.x;
    int d = threadIdx.x;
    int b = row / TSEQ, t = row % TSEQ;
    float v;
    if (t < LQ) {
        if (d < DMODEL) {
            v = tanhf(emb[(size_t)type_seq[b*LQ + t]*DMODEL + d]);
        } else {
            int j = d - DMODEL;
            int i = j >> 1;
            float div = expf(-0.57564627324851142f * (float)(2*i));
            float arg = time_seq[b*LQ + t] * div;
            v = (j & 1) ? cosf(arg) : sinf(arg);
        }
    } else {
        v = (d < DMODEL) ? 0.f
                         : temp_seq[(size_t)(b*LQ + (t - LQ))*DTIME + (d - DMODEL)];
    }
    g_h[(size_t)row*DDIM + d] = v;
}

// ---------------- one-time prep: all weight splits + A2 in one kernel ----------------
#define W1TOT (NLAYER*2*DINNER*KPAD1)
#define W2TOT (NLAYER*DDIM*DINNER)
#define A2TOT (NLAYER*DINNER*DSTATE)
__global__ void __launch_bounds__(256) prep_all(
    const float* __restrict__ in_w, const float* __restrict__ out_w,
    const float* __restrict__ A_log)
{
    int idx = blockIdx.x*256 + threadIdx.x;
    if (idx < W1TOT) {
        const int per = 2*DINNER*KPAD1;
        int l = idx / per, rem = idx - l*per;
        int r = rem / KPAD1, c = rem - r*KPAD1;
        float v = (c < DDIM) ? in_w[((size_t)l*2*DINNER + r)*DDIM + c] : 0.f;
        split_bf16(v, g_w1_hi[idx], g_w1_lo[idx]);
    } else if (idx < W1TOT + W2TOT) {
        int j = idx - W1TOT;
        split_bf16(out_w[j], g_w2_hi[j], g_w2_lo[j]);
    } else if (idx < W1TOT + W2TOT + A2TOT) {
        int j = idx - W1TOT - W2TOT;
        g_A2[j] = -__expf(A_log[j]) * 1.4426950408889634f;
    }
}

// ---------------- residual add + layernorm -> bf16 split hn ----------------
__global__ void __launch_bounds__(128) addnorm_kernel(
    const float* __restrict__ gamma, const float* __restrict__ beta, int addflag)
{
    int row = blockIdx.x;
    int tid = threadIdx.x;
    float v[3];
    float s = 0.f, s2 = 0.f;
#pragma unroll
    for (int j = 0; j < 3; j++) {
        int d = tid + j*128;
        float x = 0.f;
        if (d < DDIM) {
            x = g_h[(size_t)row*DDIM + d];
            if (addflag) x += g_res[(size_t)row*DDIM + d];
        }
        v[j] = x; s += x; s2 += x*x;
    }
#pragma unroll
    for (int o = 16; o > 0; o >>= 1) {
        s  += __shfl_down_sync(0xffffffffu, s,  o);
        s2 += __shfl_down_sync(0xffffffffu, s2, o);
    }
    __shared__ float ss[4], ss2[4];
    if ((tid & 31) == 0) { ss[tid >> 5] = s; ss2[tid >> 5] = s2; }
    __syncthreads();
    if (tid == 0) {
        float a  = ss[0]+ss[1]+ss[2]+ss[3];
        float a2 = ss2[0]+ss2[1]+ss2[2]+ss2[3];
        float mean = a * (1.f/DDIM);
        float var  = a2 * (1.f/DDIM) - mean*mean;
        ss[0] = mean;
        ss2[0] = rsqrtf(var + 1e-5f);
    }
    __syncthreads();
    float mean = ss[0], rstd = ss2[0];
#pragma unroll
    for (int j = 0; j < 3; j++) {
        int d = tid + j*128;
        if (d < DDIM) {
            g_res[(size_t)row*DDIM + d] = v[j];
            float hn = (v[j]-mean)*rstd*gamma[d] + beta[d];
            split_bf16(hn, g_hn_hi[(size_t)row*KPAD1 + d], g_hn_lo[(size_t)row*KPAD1 + d]);
        } else if (d < KPAD1) {
            g_hn_hi[(size_t)row*KPAD1 + d] = __float2bfloat16(0.f);
            g_hn_lo[(size_t)row*KPAD1 + d] = __float2bfloat16(0.f);
        }
    }
}

// ---------------- final add + layernorm ----------------
__global__ void __launch_bounds__(128) final_kernel(
    const float* __restrict__ gamma, const float* __restrict__ beta,
    float* __restrict__ out)
{
    int rowo = blockIdx.x;
    int tid = threadIdx.x;
    int b = rowo / LQ, t = rowo % LQ;
    int m = b*TSEQ + t;
    float v[3];
    float s = 0.f, s2 = 0.f;
#pragma unroll
    for (int j = 0; j < 3; j++) {
        int d = tid + j*128;
        float x = 0.f;
        if (d < DDIM) x = g_h[(size_t)m*DDIM + d] + g_res[(size_t)m*DDIM + d];
        v[j] = x; s += x; s2 += x*x;
    }
#pragma unroll
    for (int o = 16; o > 0; o >>= 1) {
        s  += __shfl_down_sync(0xffffffffu, s,  o);
        s2 += __shfl_down_sync(0xffffffffu, s2, o);
    }
    __shared__ float ss[4], ss2[4];
    if ((tid & 31) == 0) { ss[tid >> 5] = s; ss2[tid >> 5] = s2; }
    __syncthreads();
    if (tid == 0) {
        float a  = ss[0]+ss[1]+ss[2]+ss[3];
        float a2 = ss2[0]+ss2[1]+ss2[2]+ss2[3];
        float mean = a * (1.f/DDIM);
        float var  = a2 * (1.f/DDIM) - mean*mean;
        ss[0] = mean;
        ss2[0] = rsqrtf(var + 1e-5f);
    }
    __syncthreads();
    float mean = ss[0], rstd = ss2[0];
#pragma unroll
    for (int j = 0; j < 3; j++) {
        int d = tid + j*128;
        if (d < DDIM)
            out[(size_t)rowo*DDIM + d] = (v[j]-mean)*rstd*gamma[d] + beta[d];
    }
}

// ---------------- bf16-split GEMM with cp.async 2-stage pipeline ----------------
// C[M,N] = Ahi*Whi + Ahi*Wlo + Alo*Whi. BM=128,BN=128,BK=32. 8 warps (2x4), 64x32 tiles.
#define SPAD 8
#define SROW (32+SPAD)
// smem: buf[2 stages][4 arrays][128 rows][SROW]
__global__ void __launch_bounds__(256) gemm_bf16split(
    const bf16* __restrict__ Ahi, const bf16* __restrict__ Alo,
    const bf16* __restrict__ Whi, const bf16* __restrict__ Wlo,
    float* __restrict__ C, int M, int N, int Kpad)
{
    extern __shared__ bf16 sm[];
    int tid = threadIdx.x;
    int warp = tid >> 5;
    int wm = warp >> 2;          // 0..1
    int wn = warp & 3;           // 0..3
    int mb = blockIdx.y * 128;
    int nb = blockIdx.x * 128;

    int aIdx0 = tid*2, aIdx1 = tid*2 + 1;
    int r0 = aIdx0 >> 2, c0 = (aIdx0 & 3) * 8;
    int r1 = aIdx1 >> 2, c1 = (aIdx1 & 3) * 8;
    int wsz0 = ((nb + r0) < N) ? 16 : 0;
    int wsz1 = ((nb + r1) < N) ? 16 : 0;

    const bf16* pA0 = Ahi + (size_t)(mb + r0)*Kpad + c0;
    const bf16* pA1 = Ahi + (size_t)(mb + r1)*Kpad + c1;
    const bf16* pL0 = Alo + (size_t)(mb + r0)*Kpad + c0;
    const bf16* pL1 = Alo + (size_t)(mb + r1)*Kpad + c1;
    const bf16* pW0 = Whi + (size_t)(nb + r0)*Kpad + c0;
    const bf16* pW1 = Whi + (size_t)(nb + r1)*Kpad + c1;
    const bf16* pV0 = Wlo + (size_t)(nb + r0)*Kpad + c0;
    const bf16* pV1 = Wlo + (size_t)(nb + r1)*Kpad + c1;

    uint32_t sbase = (uint32_t)__cvta_generic_to_shared(sm);
    // element offsets in smem
    auto soff = [&](int stage, int arr, int row, int col) -> uint32_t {
        return (uint32_t)((((stage*4 + arr)*128) + row)*SROW + col);
    };
    uint32_t dA0 = soff(0,0,r0,c0), dA1 = soff(0,0,r1,c1);
    uint32_t dL0 = soff(0,1,r0,c0), dL1 = soff(0,1,r1,c1);
    uint32_t dW0 = soff(0,2,r0,c0), dW1 = soff(0,2,r1,c1);
    uint32_t dV0 = soff(0,3,r0,c0), dV1 = soff(0,3,r1,c1);
    const uint32_t STG = 4*128*SROW;     // elements per stage

    wmma::fragment<wmma::accumulator,16,16,16,float> acc[4][2];
#pragma unroll
    for (int i = 0; i < 4; i++)
#pragma unroll
        for (int j = 0; j < 2; j++) wmma::fill_fragment(acc[i][j], 0.f);

    int ktiles = Kpad >> 5;

    // issue stage 0
    {
        cp16(sbase + 2*dA0, pA0, 16); cp16(sbase + 2*dA1, pA1, 16);
        cp16(sbase + 2*dL0, pL0, 16); cp16(sbase + 2*dL1, pL1, 16);
        cp16(sbase + 2*dW0, pW0, wsz0); cp16(sbase + 2*dW1, pW1, wsz1);
        cp16(sbase + 2*dV0, pV0, wsz0); cp16(sbase + 2*dV1, pV1, wsz1);
        cp_commit();
    }

    for (int kt = 0; kt < ktiles; kt++) {
        if (kt + 1 < ktiles) {
            int st = (kt+1) & 1;
            int go = (kt+1) * 32;
            uint32_t so = st * STG;
            cp16(sbase + 2*(dA0+so), pA0 + go, 16); cp16(sbase + 2*(dA1+so), pA1 + go, 16);
            cp16(sbase + 2*(dL0+so), pL0 + go, 16); cp16(sbase + 2*(dL1+so), pL1 + go, 16);
            cp16(sbase + 2*(dW0+so), pW0 + go, wsz0); cp16(sbase + 2*(dW1+so), pW1 + go, wsz1);
            cp16(sbase + 2*(dV0+so), pV0 + go, wsz0); cp16(sbase + 2*(dV1+so), pV1 + go, wsz1);
            cp_commit();
            cp_wait<1>();
        } else {
            cp_wait<0>();
        }
        __syncthreads();

        const bf16* bAhi = sm + (size_t)(kt&1)*STG + 0*128*SROW;
        const bf16* bAlo = sm + (size_t)(kt&1)*STG + 1*128*SROW;
        const bf16* bWhi = sm + (size_t)(kt&1)*STG + 2*128*SROW;
        const bf16* bWlo = sm + (size_t)(kt&1)*STG + 3*128*SROW;
#pragma unroll
        for (int ks = 0; ks < 32; ks += 16) {
            wmma::fragment<wmma::matrix_a,16,16,16,bf16,wmma::row_major> ahi[4], alo[4];
            wmma::fragment<wmma::matrix_b,16,16,16,bf16,wmma::col_major> bhi[2], blo[2];
#pragma unroll
            for (int i = 0; i < 4; i++) {
                wmma::load_matrix_sync(ahi[i], bAhi + (wm*64 + i*16)*SROW + ks, SROW);
                wmma::load_matrix_sync(alo[i], bAlo + (wm*64 + i*16)*SROW + ks, SROW);
            }
#pragma unroll
            for (int j = 0; j < 2; j++) {
                wmma::load_matrix_sync(bhi[j], bWhi + (wn*32 + j*16)*SROW + ks, SROW);
                wmma::load_matrix_sync(blo[j], bWlo + (wn*32 + j*16)*SROW + ks, SROW);
            }
#pragma unroll
            for (int i = 0; i < 4; i++)
#pragma unroll
                for (int j = 0; j < 2; j++) {
                    wmma::mma_sync(acc[i][j], ahi[i], bhi[j], acc[i][j]);
                    wmma::mma_sync(acc[i][j], ahi[i], blo[j], acc[i][j]);
                    wmma::mma_sync(acc[i][j], alo[i], bhi[j], acc[i][j]);
                }
        }
        __syncthreads();
    }
#pragma unroll
    for (int i = 0; i < 4; i++)
#pragma unroll
        for (int j = 0; j < 2; j++) {
            int n0 = nb + wn*32 + j*16;
            if (n0 < N)
                wmma::store_matrix_sync(C + (size_t)(mb + wm*64 + i*16)*N + n0,
                                        acc[i][j], N, wmma::mem_row_major);
        }
}
#define GEMM_SMEM (2*4*128*SROW*2)   // bytes

// ---------------- FFMA TN GEMM, BM=64 (x_proj, N=49) ----------------
__global__ void __launch_bounds__(256) gemm_tn64(
    const float* __restrict__ A, const float* __restrict__ W,
    float* __restrict__ C, int M, int N, int K)
{
    __shared__ float As[16][68];
    __shared__ float Ws[16][68];
    int tid = threadIdx.x;
    int mb = blockIdx.y * 64;
    int lr = tid >> 2;
    int lk = (tid & 3) << 2;
    int ty = tid >> 4;
    int tx = tid & 15;

    float acc[4][4];
#pragma unroll
    for (int i = 0; i < 4; i++)
#pragma unroll
        for (int j = 0; j < 4; j++) acc[i][j] = 0.f;

    const float* Arow = A + (size_t)(mb + lr) * K + lk;
    bool wvalid = lr < N;
    const float* Wrow = W + (size_t)lr * K + lk;

    int ktiles = K >> 4;
    for (int kt = 0; kt < ktiles; kt++) {
        float4 a0 = *(const float4*)(Arow + kt*16);
        float4 w0 = wvalid ? *(const float4*)(Wrow + kt*16)
                           : make_float4(0.f, 0.f, 0.f, 0.f);
        __syncthreads();
        As[lk+0][lr] = a0.x; As[lk+1][lr] = a0.y; As[lk+2][lr] = a0.z; As[lk+3][lr] = a0.w;
        Ws[lk+0][lr] = w0.x; Ws[lk+1][lr] = w0.y; Ws[lk+2][lr] = w0.z; Ws[lk+3][lr] = w0.w;
        __syncthreads();
#pragma unroll
        for (int kk = 0; kk < 16; kk++) {
            float ra[4], rw[4];
            *(float4*)&ra[0] = *(const float4*)&As[kk][ty*4];
            *(float4*)&rw[0] = *(const float4*)&Ws[kk][tx*4];
#pragma unroll
            for (int i = 0; i < 4; i++)
#pragma unroll
                for (int j = 0; j < 4; j++)
                    acc[i][j] = fmaf(ra[i], rw[j], acc[i][j]);
        }
    }
#pragma unroll
    for (int i = 0; i < 4; i++) {
        int m = mb + ty*4 + i;
#pragma unroll
        for (int j = 0; j < 4; j++) {
            int n = tx*4 + j;
            if (n < N) C[(size_t)m*N + n] = acc[i][j];
        }
    }
}

// ---------------- depthwise causal conv1d + bias + silu ----------------
__global__ void __launch_bounds__(DINNER) conv_kernel(
    const float* __restrict__ conv_w, const float* __restrict__ conv_b, int layer)
{
    int d = threadIdx.x;
    int t0 = blockIdx.x * CONVT;
    int b = blockIdx.y;
    const float* wp = conv_w + (size_t)(layer*DINNER + d)*DCONV;
    float w0 = wp[0], w1 = wp[1], w2 = wp[2], w3 = wp[3];
    float bias = conv_b[layer*DINNER + d];
    size_t base = (size_t)(b*TSEQ)*(2*DINNER) + d;
    float x0 = (t0-3 >= 0) ? g_xz[base + (size_t)(t0-3)*(2*DINNER)] : 0.f;
    float x1 = (t0-2 >= 0) ? g_xz[base + (size_t)(t0-2)*(2*DINNER)] : 0.f;
    float x2 = (t0-1 >= 0) ? g_xz[base + (size_t)(t0-1)*(2*DINNER)] : 0.f;
#pragma unroll
    for (int i = 0; i < CONVT; i++) {
        int t = t0 + i;
        float x3 = g_xz[base + (size_t)t*(2*DINNER)];
        float s = bias;
        s = fmaf(w0, x0, s);
        s = fmaf(w1, x1, s);
        s = fmaf(w2, x2, s);
        s = fmaf(w3, x3, s);
        float sl = s / (1.f + __expf(-s));
        g_xconv[(size_t)(b*TSEQ + t)*DINNER + d] = sl;
        x0 = x1; x1 = x2; x2 = x3;
    }
}

// ---------------- chunked selective scan (delta fused) ----------------
__global__ void __launch_bounds__(DINNER) scan1_kernel(
    const float* __restrict__ dt_w, const float* __restrict__ dt_b, int layer)
{
    int c = blockIdx.x, b = blockIdx.y;
    int d = threadIdx.x;
    __shared__ float sD[CHUNK][DTRANK+DSTATE+1];   // dt(17)+B(16)
    int m0 = b*TSEQ + c*CHUNK;
    for (int idx = d; idx < CHUNK*(DTRANK+DSTATE); idx += DINNER) {
        int i = idx / (DTRANK+DSTATE), j = idx - i*(DTRANK+DSTATE);
        sD[i][j] = g_dbl[(size_t)(m0+i)*NDBL + j];
    }
    float wreg[DTRANK];
#pragma unroll
    for (int r = 0; r < DTRANK; r++)
        wreg[r] = dt_w[(size_t)(layer*DINNER + d)*DTRANK + r];
    float dbias = dt_b[layer*DINNER + d];
    float A2[DSTATE];
#pragma unroll
    for (int n = 0; n < DSTATE; n++)
        A2[n] = g_A2[(size_t)(layer*DINNER + d)*DSTATE + n];
    float base = A2[0];
    bool fast = true;
#pragma unroll
    for (int n = 1; n < DSTATE; n++)
        fast = fast && (fabsf(A2[n] - (float)(n+1)*base)
                        <= 1e-4f*fabsf((float)(n+1)*base) + 1e-6f);

    float h[DSTATE];
#pragma unroll
    for (int n = 0; n < DSTATE; n++) h[n] = 0.f;
    float sumd = 0.f;
    __syncthreads();

    for (int i = 0; i < CHUNK; i++) {
        int m = m0 + i;
        float sdt = dbias;
#pragma unroll
        for (int r = 0; r < DTRANK; r++) sdt = fmaf(sD[i][r], wreg[r], sdt);
        float delta = fmaxf(sdt, 0.f) + log1pf(__expf(-fabsf(sdt)));
        float u = g_xconv[(size_t)m*DINNER + d];
        float du = delta * u;
        if (fast) {
            float e1 = ex2(delta * base);
            float p = e1;
#pragma unroll
            for (int n = 0; n < DSTATE; n++) {
                h[n] = fmaf(p, h[n], du * sD[i][DTRANK + n]);
                p *= e1;
            }
        } else {
#pragma unroll
            for (int n = 0; n < DSTATE; n++) {
                float a = ex2(delta * A2[n]);
                h[n] = fmaf(a, h[n], du * sD[i][DTRANK + n]);
            }
        }
        sumd += delta;
    }
    size_t o = ((size_t)(b*NCHUNK + c)*DINNER + d)*DSTATE;
#pragma unroll
    for (int n = 0; n < DSTATE; n++) {
        g_hend[o + n] = h[n];
        g_P[o + n] = ex2(A2[n] * sumd);
    }
}

// scan2: warp-parallel combine; lane = (d offset 0/1)*16 + n, fully coalesced
__global__ void __launch_bounds__(256) scan2_kernel()
{
    int gw = (blockIdx.x*256 + threadIdx.x) >> 5;     // warp id: 0..1087
    int lane = threadIdx.x & 31;
    if (gw >= BATCH*(DINNER/2)) return;
    int b = gw / (DINNER/2);
    int dp = gw - b*(DINNER/2);
    float H = 0.f;
    for (int c = 0; c < NCHUNK; c++) {
        size_t o = ((size_t)(b*NCHUNK + c)*DINNER + dp*2)*DSTATE + lane;
        float P = g_P[o];
        float E = g_hend[o];
        g_Hin[o] = H;
        H = fmaf(P, H, E);
    }
}

__global__ void __launch_bounds__(DINNER) scan3_kernel(
    const float* __restrict__ dt_w, const float* __restrict__ dt_b,
    const float* __restrict__ D_param, int layer)
{
    int c = blockIdx.x, b = blockIdx.y;
    int d = threadIdx.x;
    __shared__ float sD[CHUNK][NDBL+1];               // dt(17)+B(16)+C(16)
    int m0 = b*TSEQ + c*CHUNK;
    for (int idx = d; idx < CHUNK*NDBL; idx += DINNER) {
        int i = idx / NDBL, j = idx - i*NDBL;
        sD[i][j] = g_dbl[(size_t)(m0+i)*NDBL + j];
    }
    float wreg[DTRANK];
#pragma unroll
    for (int r = 0; r < DTRANK; r++)
        wreg[r] = dt_w[(size_t)(layer*DINNER + d)*DTRANK + r];
    float dbias = dt_b[layer*DINNER + d];
    float A2[DSTATE];
#pragma unroll
    for (int n = 0; n < DSTATE; n++)
        A2[n] = g_A2[(size_t)(layer*DINNER + d)*DSTATE + n];
    float base = A2[0];
    bool fast = true;
#pragma unroll
    for (int n = 1; n < DSTATE; n++)
        fast = fast && (fabsf(A2[n] - (float)(n+1)*base)
                        <= 1e-4f*fabsf((float)(n+1)*base) + 1e-6f);

    float h[DSTATE];
    size_t oin = ((size_t)(b*NCHUNK + c)*DINNER + d)*DSTATE;
#pragma unroll
    for (int n = 0; n < DSTATE; n++) h[n] = g_Hin[oin + n];
    float Dp = D_param[layer*DINNER + d];
    __syncthreads();

    for (int i = 0; i < CHUNK; i++) {
        int m = m0 + i;
        float sdt = dbias;
#pragma unroll
        for (int r = 0; r < DTRANK; r++) sdt = fmaf(sD[i][r], wreg[r], sdt);
        float delta = fmaxf(sdt, 0.f) + log1pf(__expf(-fabsf(sdt)));
        float u = g_xconv[(size_t)m*DINNER + d];
        float z = g_xz[(size_t)m*(2*DINNER) + DINNER + d];
        float du = delta * u;
        float y = 0.f;
        if (fast) {
            float e1 = ex2(delta * base);
            float p = e1;
#pragma unroll
            for (int n = 0; n < DSTATE; n++) {
                h[n] = fmaf(p, h[n], du * sD[i][DTRANK + n]);
                y = fmaf(h[n], sD[i][DTRANK + DSTATE + n], y);
                p *= e1;
            }
        } else {
#pragma unroll
            for (int n = 0; n < DSTATE; n++) {
                float a = ex2(delta * A2[n]);
                h[n] = fmaf(a, h[n], du * sD[i][DTRANK + n]);
                y = fmaf(h[n], sD[i][DTRANK + DSTATE + n], y);
            }
        }
        float silz = z / (1.f + __expf(-z));
        float yg = fmaf(u, Dp, y) * silz;
        size_t om = (size_t)m*DINNER + d;
        split_bf16(yg, g_yg_hi[om], g_yg_lo[om]);
    }
}

// ---------------- host launcher ----------------
extern "C" void kernel_launch(void* const* d_in, const int* in_sizes, int n_in,
                              void* d_out, int out_size)
{
    (void)in_sizes; (void)n_in; (void)out_size;
    const int*   type_seq = (const int*)  d_in[0];
    const float* time_seq = (const float*)d_in[1];
    const float* temp_seq = (const float*)d_in[2];
    const float* emb      = (const float*)d_in[3];
    const float* norm_w   = (const float*)d_in[4];
    const float* norm_b   = (const float*)d_in[5];
    const float* in_w     = (const float*)d_in[6];
    const float* conv_w   = (const float*)d_in[7];
    const float* conv_b   = (const float*)d_in[8];
    const float* xproj_w  = (const float*)d_in[9];
    const float* dt_w     = (const float*)d_in[10];
    const float* dt_b     = (const float*)d_in[11];
    const float* A_log    = (const float*)d_in[12];
    const float* D_param  = (const float*)d_in[13];
    const float* out_w    = (const float*)d_in[14];
    const float* normf_w  = (const float*)d_in[15];
    const float* normf_b  = (const float*)d_in[16];
    float* out = (float*)d_out;

    float *p_xz, *p_xconv, *p_dbl, *p_h;
    cudaGetSymbolAddress((void**)&p_xz,    g_xz);
    cudaGetSymbolAddress((void**)&p_xconv, g_xconv);
    cudaGetSymbolAddress((void**)&p_dbl,   g_dbl);
    cudaGetSymbolAddress((void**)&p_h,     g_h);
    bf16 *p_hnh, *p_hnl, *p_ygh, *p_ygl, *p_w1h, *p_w1l, *p_w2h, *p_w2l;
    cudaGetSymbolAddress((void**)&p_hnh, g_hn_hi);
    cudaGetSymbolAddress((void**)&p_hnl, g_hn_lo);
    cudaGetSymbolAddress((void**)&p_ygh, g_yg_hi);
    cudaGetSymbolAddress((void**)&p_ygl, g_yg_lo);
    cudaGetSymbolAddress((void**)&p_w1h, g_w1_hi);
    cudaGetSymbolAddress((void**)&p_w1l, g_w1_lo);
    cudaGetSymbolAddress((void**)&p_w2h, g_w2_hi);
    cudaGetSymbolAddress((void**)&p_w2l, g_w2_lo);

    cudaFuncSetAttribute(gemm_bf16split,
                         cudaFuncAttributeMaxDynamicSharedMemorySize, GEMM_SMEM);

    embed_kernel<<<MROWS, DDIM>>>(type_seq, time_seq, temp_seq, emb);
    prep_all<<<(W1TOT + W2TOT + A2TOT + 255)/256, 256>>>(in_w, out_w, A_log);

    for (int l = 0; l < NLAYER; l++) {
        addnorm_kernel<<<MROWS, 128>>>(norm_w + l*DDIM, norm_b + l*DDIM, l > 0);

        // xz = hn @ in_w^T : (8192,288)x(1088,288)^T
        gemm_bf16split<<<dim3((2*DINNER + 127)/128, MROWS/128), 256, GEMM_SMEM>>>(
            p_hnh, p_hnl,
            p_w1h + (size_t)l*2*DINNER*KPAD1, p_w1l + (size_t)l*2*DINNER*KPAD1,
            p_xz, MROWS, 2*DINNER, KPAD1);

        conv_kernel<<<dim3(TSEQ/CONVT, BATCH), DINNER>>>(conv_w, conv_b, l);

        // dbl = xconv @ xproj_w^T : (8192,544)x(49,544)^T
        gemm_tn64<<<dim3(1, MROWS/64), 256>>>(
            p_xconv, xproj_w + (size_t)l*NDBL*DINNER, p_dbl, MROWS, NDBL, DINNER);

        scan1_kernel<<<dim3(NCHUNK, BATCH), DINNER>>>(dt_w, dt_b, l);
        scan2_kernel<<<(BATCH*(DINNER/2)*32 + 255)/256, 256>>>();
        scan3_kernel<<<dim3(NCHUNK, BATCH), DINNER>>>(dt_w, dt_b, D_param, l);

        // h = yg @ out_w^T : (8192,544)x(272,544)^T
        gemm_bf16split<<<dim3((DDIM + 127)/128, MROWS/128), 256, GEMM_SMEM>>>(
            p_ygh, p_ygl,
            p_w2h + (size_t)l*DDIM*DINNER, p_w2l + (size_t)l*DDIM*DINNER,
            p_h, MROWS, DDIM, DINNER);
    }

    final_kernel<<<BATCH*LQ, 128>>>(normf_w, normf_b, out);
}

// round 7
// speedup vs baseline: 2.2277x; 1.0611x over previous
#include <cuda_runtime.h>
#include <cuda_bf16.h>
#include <math.h>
#include <stdint.h>
#include <mma.h>

using namespace nvcuda;

#define BATCH   4
#define LQ      1024
#define TSEQ    2048
#define DMODEL  256
#define DTIME   16
#define DDIM    272
#define KPAD1   288
#define NLAYER  4
#define DINNER  544
#define DSTATE  16
#define DCONV   4
#define DTRANK  17
#define NDBL    (DTRANK + 2*DSTATE)   // 49
#define MROWS   (BATCH*TSEQ)          // 8192
#define NCHUNK  32
#define CHUNK   (TSEQ/NCHUNK)         // 64
#define CONVT   16

typedef __nv_bfloat16 bf16;

// ---------------- scratch ----------------
__device__ float g_h   [MROWS*DDIM];
__device__ float g_res [MROWS*DDIM];
__device__ float g_xz  [MROWS*2*DINNER];
__device__ float g_xconv[MROWS*DINNER];
__device__ float g_dbl [MROWS*NDBL];
__device__ float g_hend[BATCH*NCHUNK*DINNER*DSTATE];
__device__ float g_P   [BATCH*NCHUNK*DINNER*DSTATE];
__device__ float g_Hin [BATCH*NCHUNK*DINNER*DSTATE];
__device__ float g_A2  [NLAYER*DINNER*DSTATE];
__device__ bf16 g_hn_hi[MROWS*KPAD1];
__device__ bf16 g_hn_lo[MROWS*KPAD1];
__device__ bf16 g_yg_hi[MROWS*DINNER];
__device__ bf16 g_yg_lo[MROWS*DINNER];
__device__ bf16 g_w1_hi[NLAYER*2*DINNER*KPAD1];
__device__ bf16 g_w1_lo[NLAYER*2*DINNER*KPAD1];
__device__ bf16 g_w2_hi[NLAYER*DDIM*DINNER];
__device__ bf16 g_w2_lo[NLAYER*DDIM*DINNER];

__device__ __forceinline__ float ex2(float x) {
    float y; asm("ex2.approx.ftz.f32 %0, %1;" : "=f"(y) : "f"(x)); return y;
}
__device__ __forceinline__ void split_bf16(float v, bf16& hi, bf16& lo) {
    hi = __float2bfloat16_rn(v);
    lo = __float2bfloat16_rn(v - __bfloat162float(hi));
}
__device__ __forceinline__ void cp16(uint32_t saddr, const void* g, int srcsz) {
    asm volatile("cp.async.ca.shared.global [%0], [%1], 16, %2;\n"
                 :: "r"(saddr), "l"(g), "r"(srcsz));
}
__device__ __forceinline__ void cp_commit() { asm volatile("cp.async.commit_group;\n"); }
template<int NN> __device__ __forceinline__ void cp_wait() {
    asm volatile("cp.async.wait_group %0;\n" :: "n"(NN));
}

// ---------------- embedding ----------------
__global__ void __launch_bounds__(DDIM) embed_kernel(
    const int* __restrict__ type_seq, const float* __restrict__ time_seq,
    const float* __restrict__ temp_seq, const float* __restrict__ emb)
{
    int row = blockIdx.x;
    int d = threadIdx.x;
    int b = row / TSEQ, t = row % TSEQ;
    float v;
    if (t < LQ) {
        if (d < DMODEL) {
            v = tanhf(emb[(size_t)type_seq[b*LQ + t]*DMODEL + d]);
        } else {
            int j = d - DMODEL;
            int i = j >> 1;
            float div = expf(-0.57564627324851142f * (float)(2*i));
            float arg = time_seq[b*LQ + t] * div;
            v = (j & 1) ? cosf(arg) : sinf(arg);
        }
    } else {
        v = (d < DMODEL) ? 0.f
                         : temp_seq[(size_t)(b*LQ + (t - LQ))*DTIME + (d - DMODEL)];
    }
    g_h[(size_t)row*DDIM + d] = v;
}

// ---------------- one-time prep: all weight splits + A2 ----------------
#define W1TOT (NLAYER*2*DINNER*KPAD1)
#define W2TOT (NLAYER*DDIM*DINNER)
#define A2TOT (NLAYER*DINNER*DSTATE)
__global__ void __launch_bounds__(256) prep_all(
    const float* __restrict__ in_w, const float* __restrict__ out_w,
    const float* __restrict__ A_log)
{
    int idx = blockIdx.x*256 + threadIdx.x;
    if (idx < W1TOT) {
        const int per = 2*DINNER*KPAD1;
        int l = idx / per, rem = idx - l*per;
        int r = rem / KPAD1, c = rem - r*KPAD1;
        float v = (c < DDIM) ? in_w[((size_t)l*2*DINNER + r)*DDIM + c] : 0.f;
        split_bf16(v, g_w1_hi[idx], g_w1_lo[idx]);
    } else if (idx < W1TOT + W2TOT) {
        int j = idx - W1TOT;
        split_bf16(out_w[j], g_w2_hi[j], g_w2_lo[j]);
    } else if (idx < W1TOT + W2TOT + A2TOT) {
        int j = idx - W1TOT - W2TOT;
        g_A2[j] = -__expf(A_log[j]) * 1.4426950408889634f;
    }
}

// ---------------- residual add + layernorm -> bf16 split hn ----------------
__global__ void __launch_bounds__(128) addnorm_kernel(
    const float* __restrict__ gamma, const float* __restrict__ beta, int addflag)
{
    int row = blockIdx.x;
    int tid = threadIdx.x;
    float v[3];
    float s = 0.f, s2 = 0.f;
#pragma unroll
    for (int j = 0; j < 3; j++) {
        int d = tid + j*128;
        float x = 0.f;
        if (d < DDIM) {
            x = g_h[(size_t)row*DDIM + d];
            if (addflag) x += g_res[(size_t)row*DDIM + d];
        }
        v[j] = x; s += x; s2 += x*x;
    }
#pragma unroll
    for (int o = 16; o > 0; o >>= 1) {
        s  += __shfl_down_sync(0xffffffffu, s,  o);
        s2 += __shfl_down_sync(0xffffffffu, s2, o);
    }
    __shared__ float ss[4], ss2[4];
    if ((tid & 31) == 0) { ss[tid >> 5] = s; ss2[tid >> 5] = s2; }
    __syncthreads();
    if (tid == 0) {
        float a  = ss[0]+ss[1]+ss[2]+ss[3];
        float a2 = ss2[0]+ss2[1]+ss2[2]+ss2[3];
        float mean = a * (1.f/DDIM);
        float var  = a2 * (1.f/DDIM) - mean*mean;
        ss[0] = mean;
        ss2[0] = rsqrtf(var + 1e-5f);
    }
    __syncthreads();
    float mean = ss[0], rstd = ss2[0];
#pragma unroll
    for (int j = 0; j < 3; j++) {
        int d = tid + j*128;
        if (d < DDIM) {
            g_res[(size_t)row*DDIM + d] = v[j];
            float hn = (v[j]-mean)*rstd*gamma[d] + beta[d];
            split_bf16(hn, g_hn_hi[(size_t)row*KPAD1 + d], g_hn_lo[(size_t)row*KPAD1 + d]);
        } else if (d < KPAD1) {
            g_hn_hi[(size_t)row*KPAD1 + d] = __float2bfloat16(0.f);
            g_hn_lo[(size_t)row*KPAD1 + d] = __float2bfloat16(0.f);
        }
    }
}

// ---------------- final add + layernorm ----------------
__global__ void __launch_bounds__(128) final_kernel(
    const float* __restrict__ gamma, const float* __restrict__ beta,
    float* __restrict__ out)
{
    int rowo = blockIdx.x;
    int tid = threadIdx.x;
    int b = rowo / LQ, t = rowo % LQ;
    int m = b*TSEQ + t;
    float v[3];
    float s = 0.f, s2 = 0.f;
#pragma unroll
    for (int j = 0; j < 3; j++) {
        int d = tid + j*128;
        float x = 0.f;
        if (d < DDIM) x = g_h[(size_t)m*DDIM + d] + g_res[(size_t)m*DDIM + d];
        v[j] = x; s += x; s2 += x*x;
    }
#pragma unroll
    for (int o = 16; o > 0; o >>= 1) {
        s  += __shfl_down_sync(0xffffffffu, s,  o);
        s2 += __shfl_down_sync(0xffffffffu, s2, o);
    }
    __shared__ float ss[4], ss2[4];
    if ((tid & 31) == 0) { ss[tid >> 5] = s; ss2[tid >> 5] = s2; }
    __syncthreads();
    if (tid == 0) {
        float a  = ss[0]+ss[1]+ss[2]+ss[3];
        float a2 = ss2[0]+ss2[1]+ss2[2]+ss2[3];
        float mean = a * (1.f/DDIM);
        float var  = a2 * (1.f/DDIM) - mean*mean;
        ss[0] = mean;
        ss2[0] = rsqrtf(var + 1e-5f);
    }
    __syncthreads();
    float mean = ss[0], rstd = ss2[0];
#pragma unroll
    for (int j = 0; j < 3; j++) {
        int d = tid + j*128;
        if (d < DDIM)
            out[(size_t)rowo*DDIM + d] = (v[j]-mean)*rstd*gamma[d] + beta[d];
    }
}

// ---------------- bf16-split GEMM, cp.async 2-stage, register-lean ----------------
// C[M,N] = Ahi*Whi + Ahi*Wlo + Alo*Whi. BM=128,BN=128,BK=32. 8 warps (2x4), 64x32 tiles.
// A fragments loaded on demand (2 live) to fit 2 CTAs/SM.
#define SPAD 8
#define SROW (32+SPAD)
__global__ void __launch_bounds__(256, 2) gemm_bf16split(
    const bf16* __restrict__ Ahi, const bf16* __restrict__ Alo,
    const bf16* __restrict__ Whi, const bf16* __restrict__ Wlo,
    float* __restrict__ C, int M, int N, int Kpad)
{
    extern __shared__ bf16 sm[];
    int tid = threadIdx.x;
    int warp = tid >> 5;
    int wm = warp >> 2;          // 0..1
    int wn = warp & 3;           // 0..3
    int mb = blockIdx.y * 128;
    int nb = blockIdx.x * 128;

    int aIdx0 = tid*2, aIdx1 = tid*2 + 1;
    int r0 = aIdx0 >> 2, c0 = (aIdx0 & 3) * 8;
    int r1 = aIdx1 >> 2, c1 = (aIdx1 & 3) * 8;
    int wsz0 = ((nb + r0) < N) ? 16 : 0;
    int wsz1 = ((nb + r1) < N) ? 16 : 0;

    const bf16* pA0 = Ahi + (size_t)(mb + r0)*Kpad + c0;
    const bf16* pA1 = Ahi + (size_t)(mb + r1)*Kpad + c1;
    const bf16* pL0 = Alo + (size_t)(mb + r0)*Kpad + c0;
    const bf16* pL1 = Alo + (size_t)(mb + r1)*Kpad + c1;
    const bf16* pW0 = Whi + (size_t)(nb + r0)*Kpad + c0;
    const bf16* pW1 = Whi + (size_t)(nb + r1)*Kpad + c1;
    const bf16* pV0 = Wlo + (size_t)(nb + r0)*Kpad + c0;
    const bf16* pV1 = Wlo + (size_t)(nb + r1)*Kpad + c1;

    uint32_t sbase = (uint32_t)__cvta_generic_to_shared(sm);
    auto soff = [&](int stage, int arr, int row, int col) -> uint32_t {
        return (uint32_t)((((stage*4 + arr)*128) + row)*SROW + col);
    };
    uint32_t dA0 = soff(0,0,r0,c0), dA1 = soff(0,0,r1,c1);
    uint32_t dL0 = soff(0,1,r0,c0), dL1 = soff(0,1,r1,c1);
    uint32_t dW0 = soff(0,2,r0,c0), dW1 = soff(0,2,r1,c1);
    uint32_t dV0 = soff(0,3,r0,c0), dV1 = soff(0,3,r1,c1);
    const uint32_t STG = 4*128*SROW;

    wmma::fragment<wmma::accumulator,16,16,16,float> acc[4][2];
#pragma unroll
    for (int i = 0; i < 4; i++)
#pragma unroll
        for (int j = 0; j < 2; j++) wmma::fill_fragment(acc[i][j], 0.f);

    int ktiles = Kpad >> 5;

    // stage 0
    cp16(sbase + 2*dA0, pA0, 16); cp16(sbase + 2*dA1, pA1, 16);
    cp16(sbase + 2*dL0, pL0, 16); cp16(sbase + 2*dL1, pL1, 16);
    cp16(sbase + 2*dW0, pW0, wsz0); cp16(sbase + 2*dW1, pW1, wsz1);
    cp16(sbase + 2*dV0, pV0, wsz0); cp16(sbase + 2*dV1, pV1, wsz1);
    cp_commit();

    for (int kt = 0; kt < ktiles; kt++) {
        if (kt + 1 < ktiles) {
            int st = (kt+1) & 1;
            int go = (kt+1) * 32;
            uint32_t so = st * STG;
            cp16(sbase + 2*(dA0+so), pA0 + go, 16); cp16(sbase + 2*(dA1+so), pA1 + go, 16);
            cp16(sbase + 2*(dL0+so), pL0 + go, 16); cp16(sbase + 2*(dL1+so), pL1 + go, 16);
            cp16(sbase + 2*(dW0+so), pW0 + go, wsz0); cp16(sbase + 2*(dW1+so), pW1 + go, wsz1);
            cp16(sbase + 2*(dV0+so), pV0 + go, wsz0); cp16(sbase + 2*(dV1+so), pV1 + go, wsz1);
            cp_commit();
            cp_wait<1>();
        } else {
            cp_wait<0>();
        }
        __syncthreads();

        const bf16* bAhi = sm + (size_t)(kt&1)*STG + 0*128*SROW;
        const bf16* bAlo = sm + (size_t)(kt&1)*STG + 1*128*SROW;
        const bf16* bWhi = sm + (size_t)(kt&1)*STG + 2*128*SROW;
        const bf16* bWlo = sm + (size_t)(kt&1)*STG + 3*128*SROW;
#pragma unroll
        for (int ks = 0; ks < 32; ks += 16) {
            wmma::fragment<wmma::matrix_b,16,16,16,bf16,wmma::col_major> bhi[2], blo[2];
#pragma unroll
            for (int j = 0; j < 2; j++) {
                wmma::load_matrix_sync(bhi[j], bWhi + (wn*32 + j*16)*SROW + ks, SROW);
                wmma::load_matrix_sync(blo[j], bWlo + (wn*32 + j*16)*SROW + ks, SROW);
            }
#pragma unroll
            for (int i = 0; i < 4; i++) {
                wmma::fragment<wmma::matrix_a,16,16,16,bf16,wmma::row_major> ahi, alo;
                wmma::load_matrix_sync(ahi, bAhi + (wm*64 + i*16)*SROW + ks, SROW);
                wmma::load_matrix_sync(alo, bAlo + (wm*64 + i*16)*SROW + ks, SROW);
#pragma unroll
                for (int j = 0; j < 2; j++) {
                    wmma::mma_sync(acc[i][j], ahi, bhi[j], acc[i][j]);
                    wmma::mma_sync(acc[i][j], ahi, blo[j], acc[i][j]);
                    wmma::mma_sync(acc[i][j], alo, bhi[j], acc[i][j]);
                }
            }
        }
        __syncthreads();
    }
#pragma unroll
    for (int i = 0; i < 4; i++)
#pragma unroll
        for (int j = 0; j < 2; j++) {
            int n0 = nb + wn*32 + j*16;
            if (n0 < N)
                wmma::store_matrix_sync(C + (size_t)(mb + wm*64 + i*16)*N + n0,
                                        acc[i][j], N, wmma::mem_row_major);
        }
}
#define GEMM_SMEM (2*4*128*SROW*2)   // 81920 bytes

// ---------------- FFMA TN GEMM, BM=64 (x_proj, N=49) ----------------
__global__ void __launch_bounds__(256) gemm_tn64(
    const float* __restrict__ A, const float* __restrict__ W,
    float* __restrict__ C, int M, int N, int K)
{
    __shared__ float As[16][68];
    __shared__ float Ws[16][68];
    int tid = threadIdx.x;
    int mb = blockIdx.y * 64;
    int lr = tid >> 2;
    int lk = (tid & 3) << 2;
    int ty = tid >> 4;
    int tx = tid & 15;

    float acc[4][4];
#pragma unroll
    for (int i = 0; i < 4; i++)
#pragma unroll
        for (int j = 0; j < 4; j++) acc[i][j] = 0.f;

    const float* Arow = A + (size_t)(mb + lr) * K + lk;
    bool wvalid = lr < N;
    const float* Wrow = W + (size_t)lr * K + lk;

    int ktiles = K >> 4;
    for (int kt = 0; kt < ktiles; kt++) {
        float4 a0 = *(const float4*)(Arow + kt*16);
        float4 w0 = wvalid ? *(const float4*)(Wrow + kt*16)
                           : make_float4(0.f, 0.f, 0.f, 0.f);
        __syncthreads();
        As[lk+0][lr] = a0.x; As[lk+1][lr] = a0.y; As[lk+2][lr] = a0.z; As[lk+3][lr] = a0.w;
        Ws[lk+0][lr] = w0.x; Ws[lk+1][lr] = w0.y; Ws[lk+2][lr] = w0.z; Ws[lk+3][lr] = w0.w;
        __syncthreads();
#pragma unroll
        for (int kk = 0; kk < 16; kk++) {
            float ra[4], rw[4];
            *(float4*)&ra[0] = *(const float4*)&As[kk][ty*4];
            *(float4*)&rw[0] = *(const float4*)&Ws[kk][tx*4];
#pragma unroll
            for (int i = 0; i < 4; i++)
#pragma unroll
                for (int j = 0; j < 4; j++)
                    acc[i][j] = fmaf(ra[i], rw[j], acc[i][j]);
        }
    }
#pragma unroll
    for (int i = 0; i < 4; i++) {
        int m = mb + ty*4 + i;
#pragma unroll
        for (int j = 0; j < 4; j++) {
            int n = tx*4 + j;
            if (n < N) C[(size_t)m*N + n] = acc[i][j];
        }
    }
}

// ---------------- depthwise causal conv1d + bias + silu ----------------
__global__ void __launch_bounds__(DINNER) conv_kernel(
    const float* __restrict__ conv_w, const float* __restrict__ conv_b, int layer)
{
    int d = threadIdx.x;
    int t0 = blockIdx.x * CONVT;
    int b = blockIdx.y;
    const float* wp = conv_w + (size_t)(layer*DINNER + d)*DCONV;
    float w0 = wp[0], w1 = wp[1], w2 = wp[2], w3 = wp[3];
    float bias = conv_b[layer*DINNER + d];
    size_t base = (size_t)(b*TSEQ)*(2*DINNER) + d;
    float x0 = (t0-3 >= 0) ? g_xz[base + (size_t)(t0-3)*(2*DINNER)] : 0.f;
    float x1 = (t0-2 >= 0) ? g_xz[base + (size_t)(t0-2)*(2*DINNER)] : 0.f;
    float x2 = (t0-1 >= 0) ? g_xz[base + (size_t)(t0-1)*(2*DINNER)] : 0.f;
#pragma unroll
    for (int i = 0; i < CONVT; i++) {
        int t = t0 + i;
        float x3 = g_xz[base + (size_t)t*(2*DINNER)];
        float s = bias;
        s = fmaf(w0, x0, s);
        s = fmaf(w1, x1, s);
        s = fmaf(w2, x2, s);
        s = fmaf(w3, x3, s);
        float sl = s / (1.f + __expf(-s));
        g_xconv[(size_t)(b*TSEQ + t)*DINNER + d] = sl;
        x0 = x1; x1 = x2; x2 = x3;
    }
}

// ---------------- chunked selective scan (delta fused) ----------------
__global__ void __launch_bounds__(DINNER) scan1_kernel(
    const float* __restrict__ dt_w, const float* __restrict__ dt_b, int layer)
{
    int c = blockIdx.x, b = blockIdx.y;
    int d = threadIdx.x;
    __shared__ float sD[CHUNK][DTRANK+DSTATE+1];
    int m0 = b*TSEQ + c*CHUNK;
    for (int idx = d; idx < CHUNK*(DTRANK+DSTATE); idx += DINNER) {
        int i = idx / (DTRANK+DSTATE), j = idx - i*(DTRANK+DSTATE);
        sD[i][j] = g_dbl[(size_t)(m0+i)*NDBL + j];
    }
    float wreg[DTRANK];
#pragma unroll
    for (int r = 0; r < DTRANK; r++)
        wreg[r] = dt_w[(size_t)(layer*DINNER + d)*DTRANK + r];
    float dbias = dt_b[layer*DINNER + d];
    float A2[DSTATE];
#pragma unroll
    for (int n = 0; n < DSTATE; n++)
        A2[n] = g_A2[(size_t)(layer*DINNER + d)*DSTATE + n];
    float base = A2[0];
    bool fast = true;
#pragma unroll
    for (int n = 1; n < DSTATE; n++)
        fast = fast && (fabsf(A2[n] - (float)(n+1)*base)
                        <= 1e-4f*fabsf((float)(n+1)*base) + 1e-6f);

    float h[DSTATE];
#pragma unroll
    for (int n = 0; n < DSTATE; n++) h[n] = 0.f;
    float sumd = 0.f;
    __syncthreads();

    for (int i = 0; i < CHUNK; i++) {
        int m = m0 + i;
        float sdt = dbias;
#pragma unroll
        for (int r = 0; r < DTRANK; r++) sdt = fmaf(sD[i][r], wreg[r], sdt);
        float delta = fmaxf(sdt, 0.f) + log1pf(__expf(-fabsf(sdt)));
        float u = g_xconv[(size_t)m*DINNER + d];
        float du = delta * u;
        if (fast) {
            float e1 = ex2(delta * base);
            float p = e1;
#pragma unroll
            for (int n = 0; n < DSTATE; n++) {
                h[n] = fmaf(p, h[n], du * sD[i][DTRANK + n]);
                p *= e1;
            }
        } else {
#pragma unroll
            for (int n = 0; n < DSTATE; n++) {
                float a = ex2(delta * A2[n]);
                h[n] = fmaf(a, h[n], du * sD[i][DTRANK + n]);
            }
        }
        sumd += delta;
    }
    size_t o = ((size_t)(b*NCHUNK + c)*DINNER + d)*DSTATE;
#pragma unroll
    for (int n = 0; n < DSTATE; n++) {
        g_hend[o + n] = h[n];
        g_P[o + n] = ex2(A2[n] * sumd);
    }
}

__global__ void __launch_bounds__(256) scan2_kernel()
{
    int gw = (blockIdx.x*256 + threadIdx.x) >> 5;
    int lane = threadIdx.x & 31;
    if (gw >= BATCH*(DINNER/2)) return;
    int b = gw / (DINNER/2);
    int dp = gw - b*(DINNER/2);
    float H = 0.f;
    for (int c = 0; c < NCHUNK; c++) {
        size_t o = ((size_t)(b*NCHUNK + c)*DINNER + dp*2)*DSTATE + lane;
        float P = g_P[o];
        float E = g_hend[o];
        g_Hin[o] = H;
        H = fmaf(P, H, E);
    }
}

__global__ void __launch_bounds__(DINNER) scan3_kernel(
    const float* __restrict__ dt_w, const float* __restrict__ dt_b,
    const float* __restrict__ D_param, int layer)
{
    int c = blockIdx.x, b = blockIdx.y;
    int d = threadIdx.x;
    __shared__ float sD[CHUNK][NDBL+1];
    int m0 = b*TSEQ + c*CHUNK;
    for (int idx = d; idx < CHUNK*NDBL; idx += DINNER) {
        int i = idx / NDBL, j = idx - i*NDBL;
        sD[i][j] = g_dbl[(size_t)(m0+i)*NDBL + j];
    }
    float wreg[DTRANK];
#pragma unroll
    for (int r = 0; r < DTRANK; r++)
        wreg[r] = dt_w[(size_t)(layer*DINNER + d)*DTRANK + r];
    float dbias = dt_b[layer*DINNER + d];
    float A2[DSTATE];
#pragma unroll
    for (int n = 0; n < DSTATE; n++)
        A2[n] = g_A2[(size_t)(layer*DINNER + d)*DSTATE + n];
    float base = A2[0];
    bool fast = true;
#pragma unroll
    for (int n = 1; n < DSTATE; n++)
        fast = fast && (fabsf(A2[n] - (float)(n+1)*base)
                        <= 1e-4f*fabsf((float)(n+1)*base) + 1e-6f);

    float h[DSTATE];
    size_t oin = ((size_t)(b*NCHUNK + c)*DINNER + d)*DSTATE;
#pragma unroll
    for (int n = 0; n < DSTATE; n++) h[n] = g_Hin[oin + n];
    float Dp = D_param[layer*DINNER + d];
    __syncthreads();

    for (int i = 0; i < CHUNK; i++) {
        int m = m0 + i;
        float sdt = dbias;
#pragma unroll
        for (int r = 0; r < DTRANK; r++) sdt = fmaf(sD[i][r], wreg[r], sdt);
        float delta = fmaxf(sdt, 0.f) + log1pf(__expf(-fabsf(sdt)));
        float u = g_xconv[(size_t)m*DINNER + d];
        float z = g_xz[(size_t)m*(2*DINNER) + DINNER + d];
        float du = delta * u;
        float y = 0.f;
        if (fast) {
            float e1 = ex2(delta * base);
            float p = e1;
#pragma unroll
            for (int n = 0; n < DSTATE; n++) {
                h[n] = fmaf(p, h[n], du * sD[i][DTRANK + n]);
                y = fmaf(h[n], sD[i][DTRANK + DSTATE + n], y);
                p *= e1;
            }
        } else {
#pragma unroll
            for (int n = 0; n < DSTATE; n++) {
                float a = ex2(delta * A2[n]);
                h[n] = fmaf(a, h[n], du * sD[i][DTRANK + n]);
                y = fmaf(h[n], sD[i][DTRANK + DSTATE + n], y);
            }
        }
        float silz = z / (1.f + __expf(-z));
        float yg = fmaf(u, Dp, y) * silz;
        size_t om = (size_t)m*DINNER + d;
        split_bf16(yg, g_yg_hi[om], g_yg_lo[om]);
    }
}

// ---------------- host launcher ----------------
extern "C" void kernel_launch(void* const* d_in, const int* in_sizes, int n_in,
                              void* d_out, int out_size)
{
    (void)in_sizes; (void)n_in; (void)out_size;
    const int*   type_seq = (const int*)  d_in[0];
    const float* time_seq = (const float*)d_in[1];
    const float* temp_seq = (const float*)d_in[2];
    const float* emb      = (const float*)d_in[3];
    const float* norm_w   = (const float*)d_in[4];
    const float* norm_b   = (const float*)d_in[5];
    const float* in_w     = (const float*)d_in[6];
    const float* conv_w   = (const float*)d_in[7];
    const float* conv_b   = (const float*)d_in[8];
    const float* xproj_w  = (const float*)d_in[9];
    const float* dt_w     = (const float*)d_in[10];
    const float* dt_b     = (const float*)d_in[11];
    const float* A_log    = (const float*)d_in[12];
    const float* D_param  = (const float*)d_in[13];
    const float* out_w    = (const float*)d_in[14];
    const float* normf_w  = (const float*)d_in[15];
    const float* normf_b  = (const float*)d_in[16];
    float* out = (float*)d_out;

    float *p_xz, *p_xconv, *p_dbl, *p_h;
    cudaGetSymbolAddress((void**)&p_xz,    g_xz);
    cudaGetSymbolAddress((void**)&p_xconv, g_xconv);
    cudaGetSymbolAddress((void**)&p_dbl,   g_dbl);
    cudaGetSymbolAddress((void**)&p_h,     g_h);
    bf16 *p_hnh, *p_hnl, *p_ygh, *p_ygl, *p_w1h, *p_w1l, *p_w2h, *p_w2l;
    cudaGetSymbolAddress((void**)&p_hnh, g_hn_hi);
    cudaGetSymbolAddress((void**)&p_hnl, g_hn_lo);
    cudaGetSymbolAddress((void**)&p_ygh, g_yg_hi);
    cudaGetSymbolAddress((void**)&p_ygl, g_yg_lo);
    cudaGetSymbolAddress((void**)&p_w1h, g_w1_hi);
    cudaGetSymbolAddress((void**)&p_w1l, g_w1_lo);
    cudaGetSymbolAddress((void**)&p_w2h, g_w2_hi);
    cudaGetSymbolAddress((void**)&p_w2l, g_w2_lo);

    cudaFuncSetAttribute(gemm_bf16split,
                         cudaFuncAttributeMaxDynamicSharedMemorySize, GEMM_SMEM);

    embed_kernel<<<MROWS, DDIM>>>(type_seq, time_seq, temp_seq, emb);
    prep_all<<<(W1TOT + W2TOT + A2TOT + 255)/256, 256>>>(in_w, out_w, A_log);

    for (int l = 0; l < NLAYER; l++) {
        addnorm_kernel<<<MROWS, 128>>>(norm_w + l*DDIM, norm_b + l*DDIM, l > 0);

        // xz = hn @ in_w^T : (8192,288)x(1088,288)^T
        gemm_bf16split<<<dim3((2*DINNER + 127)/128, MROWS/128), 256, GEMM_SMEM>>>(
            p_hnh, p_hnl,
            p_w1h + (size_t)l*2*DINNER*KPAD1, p_w1l + (size_t)l*2*DINNER*KPAD1,
            p_xz, MROWS, 2*DINNER, KPAD1);

        conv_kernel<<<dim3(TSEQ/CONVT, BATCH), DINNER>>>(conv_w, conv_b, l);

        // dbl = xconv @ xproj_w^T : (8192,544)x(49,544)^T
        gemm_tn64<<<dim3(1, MROWS/64), 256>>>(
            p_xconv, xproj_w + (size_t)l*NDBL*DINNER, p_dbl, MROWS, NDBL, DINNER);

        scan1_kernel<<<dim3(NCHUNK, BATCH), DINNER>>>(dt_w, dt_b, l);
        scan2_kernel<<<(BATCH*(DINNER/2)*32 + 255)/256, 256>>>();
        scan3_kernel<<<dim3(NCHUNK, BATCH), DINNER>>>(dt_w, dt_b, D_param, l);

        // h = yg @ out_w^T : (8192,544)x(272,544)^T
        gemm_bf16split<<<dim3((DDIM + 127)/128, MROWS/128), 256, GEMM_SMEM>>>(
            p_ygh, p_ygl,
            p_w2h + (size_t)l*DDIM*DINNER, p_w2l + (size_t)l*DDIM*DINNER,
            p_h, MROWS, DDIM, DINNER);
    }

    final_kernel<<<BATCH*LQ, 128>>>(normf_w, normf_b, out);
}

// round 8
// speedup vs baseline: 2.5827x; 1.1594x over previous
#include <cuda_runtime.h>
#include <cuda_fp16.h>
#include <math.h>
#include <stdint.h>
#include <mma.h>

using namespace nvcuda;

#define BATCH   4
#define LQ      1024
#define TSEQ    2048
#define DMODEL  256
#define DTIME   16
#define DDIM    272
#define KPAD1   288
#define NLAYER  4
#define DINNER  544
#define DSTATE  16
#define DCONV   4
#define DTRANK  17
#define NDBL    (DTRANK + 2*DSTATE)   // 49
#define MROWS   (BATCH*TSEQ)          // 8192
#define NCHUNK  32
#define CHUNK   (TSEQ/NCHUNK)         // 64
#define CONVT   16

typedef __half h16;

// ---------------- scratch ----------------
__device__ float g_h   [MROWS*DDIM];
__device__ float g_res [MROWS*DDIM];
__device__ float g_xz  [MROWS*2*DINNER];
__device__ float g_xconv[MROWS*DINNER];
__device__ float g_dbl [MROWS*NDBL];
__device__ float g_hend[BATCH*NCHUNK*DINNER*DSTATE];
__device__ float g_P   [BATCH*NCHUNK*DINNER*DSTATE];
__device__ float g_Hin [BATCH*NCHUNK*DINNER*DSTATE];
__device__ float g_A2  [NLAYER*DINNER*DSTATE];
// fp16 activations (single precision-rounded copy)
__device__ h16 g_hn [MROWS*KPAD1];
__device__ h16 g_yg [MROWS*DINNER];
// fp16 split weights (hi + lo), all layers
__device__ h16 g_w1_hi[NLAYER*2*DINNER*KPAD1];
__device__ h16 g_w1_lo[NLAYER*2*DINNER*KPAD1];
__device__ h16 g_w2_hi[NLAYER*DDIM*DINNER];
__device__ h16 g_w2_lo[NLAYER*DDIM*DINNER];

__device__ __forceinline__ float ex2(float x) {
    float y; asm("ex2.approx.ftz.f32 %0, %1;" : "=f"(y) : "f"(x)); return y;
}
__device__ __forceinline__ void split_h16(float v, h16& hi, h16& lo) {
    hi = __float2half_rn(v);
    lo = __float2half_rn(v - __half2float(hi));
}
__device__ __forceinline__ void cp16(uint32_t saddr, const void* g, int srcsz) {
    asm volatile("cp.async.ca.shared.global [%0], [%1], 16, %2;\n"
                 :: "r"(saddr), "l"(g), "r"(srcsz));
}
__device__ __forceinline__ void cp_commit() { asm volatile("cp.async.commit_group;\n"); }
template<int NN> __device__ __forceinline__ void cp_wait() {
    asm volatile("cp.async.wait_group %0;\n" :: "n"(NN));
}

// ---------------- embedding ----------------
__global__ void __launch_bounds__(DDIM) embed_kernel(
    const int* __restrict__ type_seq, const float* __restrict__ time_seq,
    const float* __restrict__ temp_seq, const float* __restrict__ emb)
{
    int row = blockIdx.x;
    int d = threadIdx.x;
    int b = row / TSEQ, t = row % TSEQ;
    float v;
    if (t < LQ) {
        if (d < DMODEL) {
            v = tanhf(emb[(size_t)type_seq[b*LQ + t]*DMODEL + d]);
        } else {
            int j = d - DMODEL;
            int i = j >> 1;
            float div = expf(-0.57564627324851142f * (float)(2*i));
            float arg = time_seq[b*LQ + t] * div;
            v = (j & 1) ? cosf(arg) : sinf(arg);
        }
    } else {
        v = (d < DMODEL) ? 0.f
                         : temp_seq[(size_t)(b*LQ + (t - LQ))*DTIME + (d - DMODEL)];
    }
    g_h[(size_t)row*DDIM + d] = v;
}

// ---------------- one-time prep: fp16 weight splits + A2 ----------------
#define W1TOT (NLAYER*2*DINNER*KPAD1)
#define W2TOT (NLAYER*DDIM*DINNER)
#define A2TOT (NLAYER*DINNER*DSTATE)
__global__ void __launch_bounds__(256) prep_all(
    const float* __restrict__ in_w, const float* __restrict__ out_w,
    const float* __restrict__ A_log)
{
    int idx = blockIdx.x*256 + threadIdx.x;
    if (idx < W1TOT) {
        const int per = 2*DINNER*KPAD1;
        int l = idx / per, rem = idx - l*per;
        int r = rem / KPAD1, c = rem - r*KPAD1;
        float v = (c < DDIM) ? in_w[((size_t)l*2*DINNER + r)*DDIM + c] : 0.f;
        split_h16(v, g_w1_hi[idx], g_w1_lo[idx]);
    } else if (idx < W1TOT + W2TOT) {
        int j = idx - W1TOT;
        split_h16(out_w[j], g_w2_hi[j], g_w2_lo[j]);
    } else if (idx < W1TOT + W2TOT + A2TOT) {
        int j = idx - W1TOT - W2TOT;
        g_A2[j] = -__expf(A_log[j]) * 1.4426950408889634f;
    }
}

// ---------------- residual add + layernorm -> fp16 hn ----------------
__global__ void __launch_bounds__(128) addnorm_kernel(
    const float* __restrict__ gamma, const float* __restrict__ beta, int addflag)
{
    int row = blockIdx.x;
    int tid = threadIdx.x;
    float v[3];
    float s = 0.f, s2 = 0.f;
#pragma unroll
    for (int j = 0; j < 3; j++) {
        int d = tid + j*128;
        float x = 0.f;
        if (d < DDIM) {
            x = g_h[(size_t)row*DDIM + d];
            if (addflag) x += g_res[(size_t)row*DDIM + d];
        }
        v[j] = x; s += x; s2 += x*x;
    }
#pragma unroll
    for (int o = 16; o > 0; o >>= 1) {
        s  += __shfl_down_sync(0xffffffffu, s,  o);
        s2 += __shfl_down_sync(0xffffffffu, s2, o);
    }
    __shared__ float ss[4], ss2[4];
    if ((tid & 31) == 0) { ss[tid >> 5] = s; ss2[tid >> 5] = s2; }
    __syncthreads();
    if (tid == 0) {
        float a  = ss[0]+ss[1]+ss[2]+ss[3];
        float a2 = ss2[0]+ss2[1]+ss2[2]+ss2[3];
        float mean = a * (1.f/DDIM);
        float var  = a2 * (1.f/DDIM) - mean*mean;
        ss[0] = mean;
        ss2[0] = rsqrtf(var + 1e-5f);
    }
    __syncthreads();
    float mean = ss[0], rstd = ss2[0];
#pragma unroll
    for (int j = 0; j < 3; j++) {
        int d = tid + j*128;
        if (d < DDIM) {
            g_res[(size_t)row*DDIM + d] = v[j];
            float hn = (v[j]-mean)*rstd*gamma[d] + beta[d];
            g_hn[(size_t)row*KPAD1 + d] = __float2half_rn(hn);
        } else if (d < KPAD1) {
            g_hn[(size_t)row*KPAD1 + d] = __float2half(0.f);
        }
    }
}

// ---------------- final add + layernorm ----------------
__global__ void __launch_bounds__(128) final_kernel(
    const float* __restrict__ gamma, const float* __restrict__ beta,
    float* __restrict__ out)
{
    int rowo = blockIdx.x;
    int tid = threadIdx.x;
    int b = rowo / LQ, t = rowo % LQ;
    int m = b*TSEQ + t;
    float v[3];
    float s = 0.f, s2 = 0.f;
#pragma unroll
    for (int j = 0; j < 3; j++) {
        int d = tid + j*128;
        float x = 0.f;
        if (d < DDIM) x = g_h[(size_t)m*DDIM + d] + g_res[(size_t)m*DDIM + d];
        v[j] = x; s += x; s2 += x*x;
    }
#pragma unroll
    for (int o = 16; o > 0; o >>= 1) {
        s  += __shfl_down_sync(0xffffffffu, s,  o);
        s2 += __shfl_down_sync(0xffffffffu, s2, o);
    }
    __shared__ float ss[4], ss2[4];
    if ((tid & 31) == 0) { ss[tid >> 5] = s; ss2[tid >> 5] = s2; }
    __syncthreads();
    if (tid == 0) {
        float a  = ss[0]+ss[1]+ss[2]+ss[3];
        float a2 = ss2[0]+ss2[1]+ss2[2]+ss2[3];
        float mean = a * (1.f/DDIM);
        float var  = a2 * (1.f/DDIM) - mean*mean;
        ss[0] = mean;
        ss2[0] = rsqrtf(var + 1e-5f);
    }
    __syncthreads();
    float mean = ss[0], rstd = ss2[0];
#pragma unroll
    for (int j = 0; j < 3; j++) {
        int d = tid + j*128;
        if (d < DDIM)
            out[(size_t)rowo*DDIM + d] = (v[j]-mean)*rstd*gamma[d] + beta[d];
    }
}

// ---------------- fp16 2-term GEMM, cp.async 2-stage ----------------
// C[M,N] = A*(Whi + Wlo).  BM=128,BN=128,BK=32. 8 warps (2x4), 64x32 tiles.
#define SPAD 8
#define SROW (32+SPAD)
__global__ void __launch_bounds__(256, 2) gemm_h16(
    const h16* __restrict__ A,
    const h16* __restrict__ Whi, const h16* __restrict__ Wlo,
    float* __restrict__ C, int M, int N, int Kpad)
{
    extern __shared__ h16 sm[];
    int tid = threadIdx.x;
    int warp = tid >> 5;
    int wm = warp >> 2;          // 0..1
    int wn = warp & 3;           // 0..3
    int mb = blockIdx.y * 128;
    int nb = blockIdx.x * 128;

    int aIdx0 = tid*2, aIdx1 = tid*2 + 1;
    int r0 = aIdx0 >> 2, c0 = (aIdx0 & 3) * 8;
    int r1 = aIdx1 >> 2, c1 = (aIdx1 & 3) * 8;
    int wsz0 = ((nb + r0) < N) ? 16 : 0;
    int wsz1 = ((nb + r1) < N) ? 16 : 0;

    const h16* pA0 = A   + (size_t)(mb + r0)*Kpad + c0;
    const h16* pA1 = A   + (size_t)(mb + r1)*Kpad + c1;
    const h16* pW0 = Whi + (size_t)(nb + r0)*Kpad + c0;
    const h16* pW1 = Whi + (size_t)(nb + r1)*Kpad + c1;
    const h16* pV0 = Wlo + (size_t)(nb + r0)*Kpad + c0;
    const h16* pV1 = Wlo + (size_t)(nb + r1)*Kpad + c1;

    uint32_t sbase = (uint32_t)__cvta_generic_to_shared(sm);
    auto soff = [&](int stage, int arr, int row, int col) -> uint32_t {
        return (uint32_t)((((stage*3 + arr)*128) + row)*SROW + col);
    };
    uint32_t dA0 = soff(0,0,r0,c0), dA1 = soff(0,0,r1,c1);
    uint32_t dW0 = soff(0,1,r0,c0), dW1 = soff(0,1,r1,c1);
    uint32_t dV0 = soff(0,2,r0,c0), dV1 = soff(0,2,r1,c1);
    const uint32_t STG = 3*128*SROW;

    wmma::fragment<wmma::accumulator,16,16,16,float> acc[4][2];
#pragma unroll
    for (int i = 0; i < 4; i++)
#pragma unroll
        for (int j = 0; j < 2; j++) wmma::fill_fragment(acc[i][j], 0.f);

    int ktiles = Kpad >> 5;

    // stage 0
    cp16(sbase + 2*dA0, pA0, 16); cp16(sbase + 2*dA1, pA1, 16);
    cp16(sbase + 2*dW0, pW0, wsz0); cp16(sbase + 2*dW1, pW1, wsz1);
    cp16(sbase + 2*dV0, pV0, wsz0); cp16(sbase + 2*dV1, pV1, wsz1);
    cp_commit();

    for (int kt = 0; kt < ktiles; kt++) {
        if (kt + 1 < ktiles) {
            int st = (kt+1) & 1;
            int go = (kt+1) * 32;
            uint32_t so = st * STG;
            cp16(sbase + 2*(dA0+so), pA0 + go, 16); cp16(sbase + 2*(dA1+so), pA1 + go, 16);
            cp16(sbase + 2*(dW0+so), pW0 + go, wsz0); cp16(sbase + 2*(dW1+so), pW1 + go, wsz1);
            cp16(sbase + 2*(dV0+so), pV0 + go, wsz0); cp16(sbase + 2*(dV1+so), pV1 + go, wsz1);
            cp_commit();
            cp_wait<1>();
        } else {
            cp_wait<0>();
        }
        __syncthreads();

        const h16* bA   = sm + (size_t)(kt&1)*STG + 0*128*SROW;
        const h16* bWhi = sm + (size_t)(kt&1)*STG + 1*128*SROW;
        const h16* bWlo = sm + (size_t)(kt&1)*STG + 2*128*SROW;
#pragma unroll
        for (int ks = 0; ks < 32; ks += 16) {
            wmma::fragment<wmma::matrix_b,16,16,16,h16,wmma::col_major> bhi[2], blo[2];
#pragma unroll
            for (int j = 0; j < 2; j++) {
                wmma::load_matrix_sync(bhi[j], bWhi + (wn*32 + j*16)*SROW + ks, SROW);
                wmma::load_matrix_sync(blo[j], bWlo + (wn*32 + j*16)*SROW + ks, SROW);
            }
#pragma unroll
            for (int i = 0; i < 4; i++) {
                wmma::fragment<wmma::matrix_a,16,16,16,h16,wmma::row_major> af;
                wmma::load_matrix_sync(af, bA + (wm*64 + i*16)*SROW + ks, SROW);
#pragma unroll
                for (int j = 0; j < 2; j++) {
                    wmma::mma_sync(acc[i][j], af, bhi[j], acc[i][j]);
                    wmma::mma_sync(acc[i][j], af, blo[j], acc[i][j]);
                }
            }
        }
        __syncthreads();
    }
#pragma unroll
    for (int i = 0; i < 4; i++)
#pragma unroll
        for (int j = 0; j < 2; j++) {
            int n0 = nb + wn*32 + j*16;
            if (n0 < N)
                wmma::store_matrix_sync(C + (size_t)(mb + wm*64 + i*16)*N + n0,
                                        acc[i][j], N, wmma::mem_row_major);
        }
}
#define GEMM_SMEM (2*3*128*SROW*2)   // 61440 bytes

// ---------------- FFMA TN GEMM, BM=64 (x_proj, N=49) ----------------
__global__ void __launch_bounds__(256) gemm_tn64(
    const float* __restrict__ A, const float* __restrict__ W,
    float* __restrict__ C, int M, int N, int K)
{
    __shared__ float As[16][68];
    __shared__ float Ws[16][68];
    int tid = threadIdx.x;
    int mb = blockIdx.y * 64;
    int lr = tid >> 2;
    int lk = (tid & 3) << 2;
    int ty = tid >> 4;
    int tx = tid & 15;

    float acc[4][4];
#pragma unroll
    for (int i = 0; i < 4; i++)
#pragma unroll
        for (int j = 0; j < 4; j++) acc[i][j] = 0.f;

    const float* Arow = A + (size_t)(mb + lr) * K + lk;
    bool wvalid = lr < N;
    const float* Wrow = W + (size_t)lr * K + lk;

    int ktiles = K >> 4;
    for (int kt = 0; kt < ktiles; kt++) {
        float4 a0 = *(const float4*)(Arow + kt*16);
        float4 w0 = wvalid ? *(const float4*)(Wrow + kt*16)
                           : make_float4(0.f, 0.f, 0.f, 0.f);
        __syncthreads();
        As[lk+0][lr] = a0.x; As[lk+1][lr] = a0.y; As[lk+2][lr] = a0.z; As[lk+3][lr] = a0.w;
        Ws[lk+0][lr] = w0.x; Ws[lk+1][lr] = w0.y; Ws[lk+2][lr] = w0.z; Ws[lk+3][lr] = w0.w;
        __syncthreads();
#pragma unroll
        for (int kk = 0; kk < 16; kk++) {
            float ra[4], rw[4];
            *(float4*)&ra[0] = *(const float4*)&As[kk][ty*4];
            *(float4*)&rw[0] = *(const float4*)&Ws[kk][tx*4];
#pragma unroll
            for (int i = 0; i < 4; i++)
#pragma unroll
                for (int j = 0; j < 4; j++)
                    acc[i][j] = fmaf(ra[i], rw[j], acc[i][j]);
        }
    }
#pragma unroll
    for (int i = 0; i < 4; i++) {
        int m = mb + ty*4 + i;
#pragma unroll
        for (int j = 0; j < 4; j++) {
            int n = tx*4 + j;
            if (n < N) C[(size_t)m*N + n] = acc[i][j];
        }
    }
}

// ---------------- depthwise causal conv1d + bias + silu ----------------
__global__ void __launch_bounds__(DINNER) conv_kernel(
    const float* __restrict__ conv_w, const float* __restrict__ conv_b, int layer)
{
    int d = threadIdx.x;
    int t0 = blockIdx.x * CONVT;
    int b = blockIdx.y;
    const float* wp = conv_w + (size_t)(layer*DINNER + d)*DCONV;
    float w0 = wp[0], w1 = wp[1], w2 = wp[2], w3 = wp[3];
    float bias = conv_b[layer*DINNER + d];
    size_t base = (size_t)(b*TSEQ)*(2*DINNER) + d;
    float x0 = (t0-3 >= 0) ? g_xz[base + (size_t)(t0-3)*(2*DINNER)] : 0.f;
    float x1 = (t0-2 >= 0) ? g_xz[base + (size_t)(t0-2)*(2*DINNER)] : 0.f;
    float x2 = (t0-1 >= 0) ? g_xz[base + (size_t)(t0-1)*(2*DINNER)] : 0.f;
#pragma unroll
    for (int i = 0; i < CONVT; i++) {
        int t = t0 + i;
        float x3 = g_xz[base + (size_t)t*(2*DINNER)];
        float s = bias;
        s = fmaf(w0, x0, s);
        s = fmaf(w1, x1, s);
        s = fmaf(w2, x2, s);
        s = fmaf(w3, x3, s);
        float sl = s / (1.f + __expf(-s));
        g_xconv[(size_t)(b*TSEQ + t)*DINNER + d] = sl;
        x0 = x1; x1 = x2; x2 = x3;
    }
}

// ---------------- chunked selective scan (delta fused) ----------------
__global__ void __launch_bounds__(DINNER) scan1_kernel(
    const float* __restrict__ dt_w, const float* __restrict__ dt_b, int layer)
{
    int c = blockIdx.x, b = blockIdx.y;
    int d = threadIdx.x;
    __shared__ float sD[CHUNK][DTRANK+DSTATE+1];
    int m0 = b*TSEQ + c*CHUNK;
    for (int idx = d; idx < CHUNK*(DTRANK+DSTATE); idx += DINNER) {
        int i = idx / (DTRANK+DSTATE), j = idx - i*(DTRANK+DSTATE);
        sD[i][j] = g_dbl[(size_t)(m0+i)*NDBL + j];
    }
    float wreg[DTRANK];
#pragma unroll
    for (int r = 0; r < DTRANK; r++)
        wreg[r] = dt_w[(size_t)(layer*DINNER + d)*DTRANK + r];
    float dbias = dt_b[layer*DINNER + d];
    float A2[DSTATE];
#pragma unroll
    for (int n = 0; n < DSTATE; n++)
        A2[n] = g_A2[(size_t)(layer*DINNER + d)*DSTATE + n];
    float base = A2[0];
    bool fast = true;
#pragma unroll
    for (int n = 1; n < DSTATE; n++)
        fast = fast && (fabsf(A2[n] - (float)(n+1)*base)
                        <= 1e-4f*fabsf((float)(n+1)*base) + 1e-6f);

    float h[DSTATE];
#pragma unroll
    for (int n = 0; n < DSTATE; n++) h[n] = 0.f;
    float sumd = 0.f;
    __syncthreads();

    for (int i = 0; i < CHUNK; i++) {
        int m = m0 + i;
        float sdt = dbias;
#pragma unroll
        for (int r = 0; r < DTRANK; r++) sdt = fmaf(sD[i][r], wreg[r], sdt);
        float delta = fmaxf(sdt, 0.f) + log1pf(__expf(-fabsf(sdt)));
        float u = g_xconv[(size_t)m*DINNER + d];
        float du = delta * u;
        if (fast) {
            float e1 = ex2(delta * base);
            float p = e1;
#pragma unroll
            for (int n = 0; n < DSTATE; n++) {
                h[n] = fmaf(p, h[n], du * sD[i][DTRANK + n]);
                p *= e1;
            }
        } else {
#pragma unroll
            for (int n = 0; n < DSTATE; n++) {
                float a = ex2(delta * A2[n]);
                h[n] = fmaf(a, h[n], du * sD[i][DTRANK + n]);
            }
        }
        sumd += delta;
    }
    size_t o = ((size_t)(b*NCHUNK + c)*DINNER + d)*DSTATE;
#pragma unroll
    for (int n = 0; n < DSTATE; n++) {
        g_hend[o + n] = h[n];
        g_P[o + n] = ex2(A2[n] * sumd);
    }
}

__global__ void __launch_bounds__(256) scan2_kernel()
{
    int gw = (blockIdx.x*256 + threadIdx.x) >> 5;
    int lane = threadIdx.x & 31;
    if (gw >= BATCH*(DINNER/2)) return;
    int b = gw / (DINNER/2);
    int dp = gw - b*(DINNER/2);
    float H = 0.f;
    for (int c = 0; c < NCHUNK; c++) {
        size_t o = ((size_t)(b*NCHUNK + c)*DINNER + dp*2)*DSTATE + lane;
        float P = g_P[o];
        float E = g_hend[o];
        g_Hin[o] = H;
        H = fmaf(P, H, E);
    }
}

__global__ void __launch_bounds__(DINNER) scan3_kernel(
    const float* __restrict__ dt_w, const float* __restrict__ dt_b,
    const float* __restrict__ D_param, int layer)
{
    int c = blockIdx.x, b = blockIdx.y;
    int d = threadIdx.x;
    __shared__ float sD[CHUNK][NDBL+1];
    int m0 = b*TSEQ + c*CHUNK;
    for (int idx = d; idx < CHUNK*NDBL; idx += DINNER) {
        int i = idx / NDBL, j = idx - i*NDBL;
        sD[i][j] = g_dbl[(size_t)(m0+i)*NDBL + j];
    }
    float wreg[DTRANK];
#pragma unroll
    for (int r = 0; r < DTRANK; r++)
        wreg[r] = dt_w[(size_t)(layer*DINNER + d)*DTRANK + r];
    float dbias = dt_b[layer*DINNER + d];
    float A2[DSTATE];
#pragma unroll
    for (int n = 0; n < DSTATE; n++)
        A2[n] = g_A2[(size_t)(layer*DINNER + d)*DSTATE + n];
    float base = A2[0];
    bool fast = true;
#pragma unroll
    for (int n = 1; n < DSTATE; n++)
        fast = fast && (fabsf(A2[n] - (float)(n+1)*base)
                        <= 1e-4f*fabsf((float)(n+1)*base) + 1e-6f);

    float h[DSTATE];
    size_t oin = ((size_t)(b*NCHUNK + c)*DINNER + d)*DSTATE;
#pragma unroll
    for (int n = 0; n < DSTATE; n++) h[n] = g_Hin[oin + n];
    float Dp = D_param[layer*DINNER + d];
    __syncthreads();

    for (int i = 0; i < CHUNK; i++) {
        int m = m0 + i;
        float sdt = dbias;
#pragma unroll
        for (int r = 0; r < DTRANK; r++) sdt = fmaf(sD[i][r], wreg[r], sdt);
        float delta = fmaxf(sdt, 0.f) + log1pf(__expf(-fabsf(sdt)));
        float u = g_xconv[(size_t)m*DINNER + d];
        float z = g_xz[(size_t)m*(2*DINNER) + DINNER + d];
        float du = delta * u;
        float y = 0.f;
        if (fast) {
            float e1 = ex2(delta * base);
            float p = e1;
#pragma unroll
            for (int n = 0; n < DSTATE; n++) {
                h[n] = fmaf(p, h[n], du * sD[i][DTRANK + n]);
                y = fmaf(h[n], sD[i][DTRANK + DSTATE + n], y);
                p *= e1;
            }
        } else {
#pragma unroll
            for (int n = 0; n < DSTATE; n++) {
                float a = ex2(delta * A2[n]);
                h[n] = fmaf(a, h[n], du * sD[i][DTRANK + n]);
                y = fmaf(h[n], sD[i][DTRANK + DSTATE + n], y);
            }
        }
        float silz = z / (1.f + __expf(-z));
        float yg = fmaf(u, Dp, y) * silz;
        g_yg[(size_t)m*DINNER + d] = __float2half_rn(yg);
    }
}

// ---------------- host launcher ----------------
extern "C" void kernel_launch(void* const* d_in, const int* in_sizes, int n_in,
                              void* d_out, int out_size)
{
    (void)in_sizes; (void)n_in; (void)out_size;
    const int*   type_seq = (const int*)  d_in[0];
    const float* time_seq = (const float*)d_in[1];
    const float* temp_seq = (const float*)d_in[2];
    const float* emb      = (const float*)d_in[3];
    const float* norm_w   = (const float*)d_in[4];
    const float* norm_b   = (const float*)d_in[5];
    const float* in_w     = (const float*)d_in[6];
    const float* conv_w   = (const float*)d_in[7];
    const float* conv_b   = (const float*)d_in[8];
    const float* xproj_w  = (const float*)d_in[9];
    const float* dt_w     = (const float*)d_in[10];
    const float* dt_b     = (const float*)d_in[11];
    const float* A_log    = (const float*)d_in[12];
    const float* D_param  = (const float*)d_in[13];
    const float* out_w    = (const float*)d_in[14];
    const float* normf_w  = (const float*)d_in[15];
    const float* normf_b  = (const float*)d_in[16];
    float* out = (float*)d_out;

    float *p_xz, *p_xconv, *p_dbl, *p_h;
    cudaGetSymbolAddress((void**)&p_xz,    g_xz);
    cudaGetSymbolAddress((void**)&p_xconv, g_xconv);
    cudaGetSymbolAddress((void**)&p_dbl,   g_dbl);
    cudaGetSymbolAddress((void**)&p_h,     g_h);
    h16 *p_hn, *p_yg, *p_w1h, *p_w1l, *p_w2h, *p_w2l;
    cudaGetSymbolAddress((void**)&p_hn,  g_hn);
    cudaGetSymbolAddress((void**)&p_yg,  g_yg);
    cudaGetSymbolAddress((void**)&p_w1h, g_w1_hi);
    cudaGetSymbolAddress((void**)&p_w1l, g_w1_lo);
    cudaGetSymbolAddress((void**)&p_w2h, g_w2_hi);
    cudaGetSymbolAddress((void**)&p_w2l, g_w2_lo);

    cudaFuncSetAttribute(gemm_h16,
                         cudaFuncAttributeMaxDynamicSharedMemorySize, GEMM_SMEM);

    embed_kernel<<<MROWS, DDIM>>>(type_seq, time_seq, temp_seq, emb);
    prep_all<<<(W1TOT + W2TOT + A2TOT + 255)/256, 256>>>(in_w, out_w, A_log);

    for (int l = 0; l < NLAYER; l++) {
        addnorm_kernel<<<MROWS, 128>>>(norm_w + l*DDIM, norm_b + l*DDIM, l > 0);

        // xz = hn @ in_w^T : (8192,288)x(1088,288)^T
        gemm_h16<<<dim3((2*DINNER + 127)/128, MROWS/128), 256, GEMM_SMEM>>>(
            p_hn,
            p_w1h + (size_t)l*2*DINNER*KPAD1, p_w1l + (size_t)l*2*DINNER*KPAD1,
            p_xz, MROWS, 2*DINNER, KPAD1);

        conv_kernel<<<dim3(TSEQ/CONVT, BATCH), DINNER>>>(conv_w, conv_b, l);

        // dbl = xconv @ xproj_w^T : (8192,544)x(49,544)^T
        gemm_tn64<<<dim3(1, MROWS/64), 256>>>(
            p_xconv, xproj_w + (size_t)l*NDBL*DINNER, p_dbl, MROWS, NDBL, DINNER);

        scan1_kernel<<<dim3(NCHUNK, BATCH), DINNER>>>(dt_w, dt_b, l);
        scan2_kernel<<<(BATCH*(DINNER/2)*32 + 255)/256, 256>>>();
        scan3_kernel<<<dim3(NCHUNK, BATCH), DINNER>>>(dt_w, dt_b, D_param, l);

        // h = yg @ out_w^T : (8192,544)x(272,544)^T
        gemm_h16<<<dim3((DDIM + 127)/128, MROWS/128), 256, GEMM_SMEM>>>(
            p_yg,
            p_w2h + (size_t)l*DDIM*DINNER, p_w2l + (size_t)l*DDIM*DINNER,
            p_h, MROWS, DDIM, DINNER);
    }

    final_kernel<<<BATCH*LQ, 128>>>(normf_w, normf_b, out);
}

// round 9
// speedup vs baseline: 2.8731x; 1.1124x over previous
#include <cuda_runtime.h>
#include <cuda_fp16.h>
#include <math.h>
#include <stdint.h>
#include <mma.h>

using namespace nvcuda;

#define BATCH   4
#define LQ      1024
#define TSEQ    2048
#define DMODEL  256
#define DTIME   16
#define DDIM    272
#define KPAD1   288
#define NLAYER  4
#define DINNER  544
#define DSTATE  16
#define DCONV   4
#define DTRANK  17
#define NDBL    (DTRANK + 2*DSTATE)   // 49
#define MROWS   (BATCH*TSEQ)          // 8192
#define NCHUNK  32
#define CHUNK   (TSEQ/NCHUNK)         // 64
#define XK      576
#define XKS     (XK+8)
#define NX      64

typedef __half h16;

__device__ float g_h   [MROWS*DDIM];
__device__ float g_res [MROWS*DDIM];
__device__ float g_xz  [MROWS*2*DINNER];
__device__ float g_dbl2[MROWS*NX];
__device__ float g_hend[BATCH*NCHUNK*DINNER*DSTATE];
__device__ float g_P   [BATCH*NCHUNK*DINNER*DSTATE];
__device__ float g_Hin [BATCH*NCHUNK*DINNER*DSTATE];
__device__ float g_A2  [NLAYER*DINNER*DSTATE];
__device__ h16 g_hn [MROWS*KPAD1];
__device__ h16 g_yg [MROWS*DINNER];
__device__ h16 g_w1_hi[NLAYER*2*DINNER*KPAD1];
__device__ h16 g_w1_lo[NLAYER*2*DINNER*KPAD1];
__device__ h16 g_w2_hi[NLAYER*DDIM*DINNER];
__device__ h16 g_w2_lo[NLAYER*DDIM*DINNER];
__device__ h16 g_wx_hi[NLAYER*64*XK];
__device__ h16 g_wx_lo[NLAYER*64*XK];

__device__ __forceinline__ float ex2(float x) {
    float y; asm("ex2.approx.ftz.f32 %0, %1;" : "=f"(y) : "f"(x)); return y;
}
__device__ __forceinline__ void split_h16(float v, h16& hi, h16& lo) {
    hi = __float2half_rn(v);
    lo = __float2half_rn(v - __half2float(hi));
}
__device__ __forceinline__ void cp16(uint32_t saddr, const void* g, int srcsz) {
    asm volatile("cp.async.ca.shared.global [%0], [%1], 16, %2;\n"
                 :: "r"(saddr), "l"(g), "r"(srcsz));
}
__device__ __forceinline__ void cp_commit() { asm volatile("cp.async.commit_group;\n"); }
template<int NN> __device__ __forceinline__ void cp_wait() {
    asm volatile("cp.async.wait_group %0;\n" :: "n"(NN));
}

// ---------------- embedding ----------------
__global__ void __launch_bounds__(DDIM) embed_kernel(
    const int* __restrict__ type_seq, const float* __restrict__ time_seq,
    const float* __restrict__ temp_seq, const float* __restrict__ emb)
{
    int row = blockIdx.x;
    int d = threadIdx.x;
    int b = row / TSEQ, t = row % TSEQ;
    float v;
    if (t < LQ) {
        if (d < DMODEL) {
            v = tanhf(emb[(size_t)type_seq[b*LQ + t]*DMODEL + d]);
        } else {
            int j = d - DMODEL;
            int i = j >> 1;
            float div = expf(-0.57564627324851142f * (float)(2*i));
            float arg = time_seq[b*LQ + t] * div;
            v = (j & 1) ? cosf(arg) : sinf(arg);
        }
    } else {
        v = (d < DMODEL) ? 0.f
                         : temp_seq[(size_t)(b*LQ + (t - LQ))*DTIME + (d - DMODEL)];
    }
    g_h[(size_t)row*DDIM + d] = v;
}

// ---------------- one-time prep ----------------
#define W1TOT (NLAYER*2*DINNER*KPAD1)
#define W2TOT (NLAYER*DDIM*DINNER)
#define WXTOT (NLAYER*64*XK)
#define A2TOT (NLAYER*DINNER*DSTATE)
__global__ void __launch_bounds__(256) prep_all(
    const float* __restrict__ in_w, const float* __restrict__ out_w,
    const float* __restrict__ xproj_w, const float* __restrict__ A_log)
{
    int idx = blockIdx.x*256 + threadIdx.x;
    if (idx < W1TOT) {
        const int per = 2*DINNER*KPAD1;
        int l = idx / per, rem = idx - l*per;
        int r = rem / KPAD1, c = rem - r*KPAD1;
        float v = (c < DDIM) ? in_w[((size_t)l*2*DINNER + r)*DDIM + c] : 0.f;
        split_h16(v, g_w1_hi[idx], g_w1_lo[idx]);
    } else if (idx < W1TOT + W2TOT) {
        int j = idx - W1TOT;
        split_h16(out_w[j], g_w2_hi[j], g_w2_lo[j]);
    } else if (idx < W1TOT + W2TOT + WXTOT) {
        int j = idx - W1TOT - W2TOT;
        const int per = 64*XK;
        int l = j / per, rem = j - l*per;
        int r = rem / XK, cc = rem - r*XK;
        float v = (r < NDBL && cc < DINNER)
                ? xproj_w[((size_t)l*NDBL + r)*DINNER + cc] : 0.f;
        split_h16(v, g_wx_hi[j], g_wx_lo[j]);
    } else if (idx < W1TOT + W2TOT + WXTOT + A2TOT) {
        int j = idx - W1TOT - W2TOT - WXTOT;
        g_A2[j] = -__expf(A_log[j]) * 1.4426950408889634f;
    }
}

// ---------------- residual add + layernorm -> fp16 hn ----------------
__global__ void __launch_bounds__(128) addnorm_kernel(
    const float* __restrict__ gamma, const float* __restrict__ beta, int addflag)
{
    int row = blockIdx.x;
    int tid = threadIdx.x;
    float v[3];
    float s = 0.f, s2 = 0.f;
#pragma unroll
    for (int j = 0; j < 3; j++) {
        int d = tid + j*128;
        float x = 0.f;
        if (d < DDIM) {
            x = g_h[(size_t)row*DDIM + d];
            if (addflag) x += g_res[(size_t)row*DDIM + d];
        }
        v[j] = x; s += x; s2 += x*x;
    }
#pragma unroll
    for (int o = 16; o > 0; o >>= 1) {
        s  += __shfl_down_sync(0xffffffffu, s,  o);
        s2 += __shfl_down_sync(0xffffffffu, s2, o);
    }
    __shared__ float ss[4], ss2[4];
    if ((tid & 31) == 0) { ss[tid >> 5] = s; ss2[tid >> 5] = s2; }
    __syncthreads();
    if (tid == 0) {
        float a  = ss[0]+ss[1]+ss[2]+ss[3];
        float a2 = ss2[0]+ss2[1]+ss2[2]+ss2[3];
        float mean = a * (1.f/DDIM);
        float var  = a2 * (1.f/DDIM) - mean*mean;
        ss[0] = mean;
        ss2[0] = rsqrtf(var + 1e-5f);
    }
    __syncthreads();
    float mean = ss[0], rstd = ss2[0];
#pragma unroll
    for (int j = 0; j < 3; j++) {
        int d = tid + j*128;
        if (d < DDIM) {
            g_res[(size_t)row*DDIM + d] = v[j];
            float hn = (v[j]-mean)*rstd*gamma[d] + beta[d];
            g_hn[(size_t)row*KPAD1 + d] = __float2half_rn(hn);
        } else if (d < KPAD1) {
            g_hn[(size_t)row*KPAD1 + d] = __float2half(0.f);
        }
    }
}

// ---------------- final add + layernorm ----------------
__global__ void __launch_bounds__(128) final_kernel(
    const float* __restrict__ gamma, const float* __restrict__ beta,
    float* __restrict__ out)
{
    int rowo = blockIdx.x;
    int tid = threadIdx.x;
    int b = rowo / LQ, t = rowo % LQ;
    int m = b*TSEQ + t;
    float v[3];
    float s = 0.f, s2 = 0.f;
#pragma unroll
    for (int j = 0; j < 3; j++) {
        int d = tid + j*128;
        float x = 0.f;
        if (d < DDIM) x = g_h[(size_t)m*DDIM + d] + g_res[(size_t)m*DDIM + d];
        v[j] = x; s += x; s2 += x*x;
    }
#pragma unroll
    for (int o = 16; o > 0; o >>= 1) {
        s  += __shfl_down_sync(0xffffffffu, s,  o);
        s2 += __shfl_down_sync(0xffffffffu, s2, o);
    }
    __shared__ float ss[4], ss2[4];
    if ((tid & 31) == 0) { ss[tid >> 5] = s; ss2[tid >> 5] = s2; }
    __syncthreads();
    if (tid == 0) {
        float a  = ss[0]+ss[1]+ss[2]+ss[3];
        float a2 = ss2[0]+ss2[1]+ss2[2]+ss2[3];
        float mean = a * (1.f/DDIM);
        float var  = a2 * (1.f/DDIM) - mean*mean;
        ss[0] = mean;
        ss2[0] = rsqrtf(var + 1e-5f);
    }
    __syncthreads();
    float mean = ss[0], rstd = ss2[0];
#pragma unroll
    for (int j = 0; j < 3; j++) {
        int d = tid + j*128;
        if (d < DDIM)
            out[(size_t)rowo*DDIM + d] = (v[j]-mean)*rstd*gamma[d] + beta[d];
    }
}

// ---------------- fp16 2-term GEMM, cp.async 2-stage ----------------
#define SPAD 8
#define SROW (32+SPAD)
__global__ void __launch_bounds__(256, 2) gemm_h16(
    const h16* __restrict__ A,
    const h16* __restrict__ Whi, const h16* __restrict__ Wlo,
    float* __restrict__ C, int M, int N, int Kpad)
{
    extern __shared__ h16 sm[];
    int tid = threadIdx.x;
    int warp = tid >> 5;
    int wm = warp >> 2;
    int wn = warp & 3;
    int mb = blockIdx.y * 128;
    int nb = blockIdx.x * 128;

    int aIdx0 = tid*2, aIdx1 = tid*2 + 1;
    int r0 = aIdx0 >> 2, c0 = (aIdx0 & 3) * 8;
    int r1 = aIdx1 >> 2, c1 = (aIdx1 & 3) * 8;
    int wsz0 = ((nb + r0) < N) ? 16 : 0;
    int wsz1 = ((nb + r1) < N) ? 16 : 0;

    const h16* pA0 = A   + (size_t)(mb + r0)*Kpad + c0;
    const h16* pA1 = A   + (size_t)(mb + r1)*Kpad + c1;
    const h16* pW0 = Whi + (size_t)(nb + r0)*Kpad + c0;
    const h16* pW1 = Whi + (size_t)(nb + r1)*Kpad + c1;
    const h16* pV0 = Wlo + (size_t)(nb + r0)*Kpad + c0;
    const h16* pV1 = Wlo + (size_t)(nb + r1)*Kpad + c1;

    uint32_t sbase = (uint32_t)__cvta_generic_to_shared(sm);
    auto soff = [&](int stage, int arr, int row, int col) -> uint32_t {
        return (uint32_t)((((stage*3 + arr)*128) + row)*SROW + col);
    };
    uint32_t dA0 = soff(0,0,r0,c0), dA1 = soff(0,0,r1,c1);
    uint32_t dW0 = soff(0,1,r0,c0), dW1 = soff(0,1,r1,c1);
    uint32_t dV0 = soff(0,2,r0,c0), dV1 = soff(0,2,r1,c1);
    const uint32_t STG = 3*128*SROW;

    wmma::fragment<wmma::accumulator,16,16,16,float> acc[4][2];
#pragma unroll
    for (int i = 0; i < 4; i++)
#pragma unroll
        for (int j = 0; j < 2; j++) wmma::fill_fragment(acc[i][j], 0.f);

    int ktiles = Kpad >> 5;

    cp16(sbase + 2*dA0, pA0, 16); cp16(sbase + 2*dA1, pA1, 16);
    cp16(sbase + 2*dW0, pW0, wsz0); cp16(sbase + 2*dW1, pW1, wsz1);
    cp16(sbase + 2*dV0, pV0, wsz0); cp16(sbase + 2*dV1, pV1, wsz1);
    cp_commit();

    for (int kt = 0; kt < ktiles; kt++) {
        if (kt + 1 < ktiles) {
            int st = (kt+1) & 1;
            int go = (kt+1) * 32;
            uint32_t so = st * STG;
            cp16(sbase + 2*(dA0+so), pA0 + go, 16); cp16(sbase + 2*(dA1+so), pA1 + go, 16);
            cp16(sbase + 2*(dW0+so), pW0 + go, wsz0); cp16(sbase + 2*(dW1+so), pW1 + go, wsz1);
            cp16(sbase + 2*(dV0+so), pV0 + go, wsz0); cp16(sbase + 2*(dV1+so), pV1 + go, wsz1);
            cp_commit();
            cp_wait<1>();
        } else {
            cp_wait<0>();
        }
        __syncthreads();

        const h16* bA   = sm + (size_t)(kt&1)*STG + 0*128*SROW;
        const h16* bWhi = sm + (size_t)(kt&1)*STG + 1*128*SROW;
        const h16* bWlo = sm + (size_t)(kt&1)*STG + 2*128*SROW;
#pragma unroll
        for (int ks = 0; ks < 32; ks += 16) {
            wmma::fragment<wmma::matrix_b,16,16,16,h16,wmma::col_major> bhi[2], blo[2];
#pragma unroll
            for (int j = 0; j < 2; j++) {
                wmma::load_matrix_sync(bhi[j], bWhi + (wn*32 + j*16)*SROW + ks, SROW);
                wmma::load_matrix_sync(blo[j], bWlo + (wn*32 + j*16)*SROW + ks, SROW);
            }
#pragma unroll
            for (int i = 0; i < 4; i++) {
                wmma::fragment<wmma::matrix_a,16,16,16,h16,wmma::row_major> af;
                wmma::load_matrix_sync(af, bA + (wm*64 + i*16)*SROW + ks, SROW);
#pragma unroll
                for (int j = 0; j < 2; j++) {
                    wmma::mma_sync(acc[i][j], af, bhi[j], acc[i][j]);
                    wmma::mma_sync(acc[i][j], af, blo[j], acc[i][j]);
                }
            }
        }
        __syncthreads();
    }
#pragma unroll
    for (int i = 0; i < 4; i++)
#pragma unroll
        for (int j = 0; j < 2; j++) {
            int n0 = nb + wn*32 + j*16;
            if (n0 < N)
                wmma::store_matrix_sync(C + (size_t)(mb + wm*64 + i*16)*N + n0,
                                        acc[i][j], N, wmma::mem_row_major);
        }
}
#define GEMM_SMEM (2*3*128*SROW*2)

// ---------------- mega1: conv + x_proj (3-term fp16 tensor) + scan1 ----------------
#define MG_AHI  0
#define MG_ALO  (64*XKS*2)
#define MG_WH   (2*64*XKS*2)
#define MG_WL   (MG_WH + 64*72*2)
#define MG_DBL  (MG_WL + 64*72*2)
#define MG_SMEM (MG_DBL + 64*68*4)
__global__ void __launch_bounds__(DINNER) mega1(
    const float* __restrict__ conv_w, const float* __restrict__ conv_b,
    const float* __restrict__ dt_w, const float* __restrict__ dt_b,
    int layer)
{
    extern __shared__ __align__(16) char smx[];
    h16*  Ahi  = (h16*)(smx + MG_AHI);
    h16*  Alo  = (h16*)(smx + MG_ALO);
    h16*  Wh   = (h16*)(smx + MG_WH);
    h16*  Wl   = (h16*)(smx + MG_WL);
    float* sdbl = (float*)(smx + MG_DBL);

    int c = blockIdx.x, b = blockIdx.y;
    int tid = threadIdx.x;
    int d = tid;
    int warp = tid >> 5;
    int t0 = c*CHUNK;
    int m0 = b*TSEQ + t0;

    // ---- conv phase ----
    {
        const float* wp = conv_w + (size_t)(layer*DINNER + d)*DCONV;
        float w0 = wp[0], w1 = wp[1], w2 = wp[2], w3 = wp[3];
        float bias = conv_b[layer*DINNER + d];
        size_t base = (size_t)(b*TSEQ)*(2*DINNER) + d;
        float x0 = (t0-3 >= 0) ? g_xz[base + (size_t)(t0-3)*(2*DINNER)] : 0.f;
        float x1 = (t0-2 >= 0) ? g_xz[base + (size_t)(t0-2)*(2*DINNER)] : 0.f;
        float x2 = (t0-1 >= 0) ? g_xz[base + (size_t)(t0-1)*(2*DINNER)] : 0.f;
        for (int i = 0; i < CHUNK; i++) {
            float x3 = g_xz[base + (size_t)(t0+i)*(2*DINNER)];
            float s = bias;
            s = fmaf(w0, x0, s); s = fmaf(w1, x1, s);
            s = fmaf(w2, x2, s); s = fmaf(w3, x3, s);
            float sl = s / (1.f + __expf(-s));
            h16 hi, lo; split_h16(sl, hi, lo);
            Ahi[i*XKS + d] = hi;
            Alo[i*XKS + d] = lo;
            x0 = x1; x1 = x2; x2 = x3;
        }
        if (d < XK - DINNER) {
            h16 z0 = __float2half(0.f);
            for (int i = 0; i < CHUNK; i++) {
                Ahi[i*XKS + DINNER + d] = z0;
                Alo[i*XKS + DINNER + d] = z0;
            }
        }
    }
    __syncthreads();

    // ---- x_proj GEMM: sdbl[64][64] = A[64][576] @ Wx[64][576]^T (3-term) ----
    {
        wmma::fragment<wmma::accumulator,16,16,16,float> accf;
        if (warp < 16) wmma::fill_fragment(accf, 0.f);
        int ti = warp >> 2, tj = warp & 3;
        const h16* gwh = g_wx_hi + (size_t)layer*64*XK;
        const h16* gwl = g_wx_lo + (size_t)layer*64*XK;
        for (int kc = 0; kc < XK/64; kc++) {
            __syncthreads();
            for (int idx = tid; idx < 512; idx += DINNER) {
                int r = idx >> 3, q = (idx & 7)*8;
                *(uint4*)&Wh[r*72 + q] = *(const uint4*)&gwh[(size_t)r*XK + kc*64 + q];
                *(uint4*)&Wl[r*72 + q] = *(const uint4*)&gwl[(size_t)r*XK + kc*64 + q];
            }
            __syncthreads();
            if (warp < 16) {
#pragma unroll
                for (int ks = 0; ks < 64; ks += 16) {
                    wmma::fragment<wmma::matrix_a,16,16,16,h16,wmma::row_major> ah, al;
                    wmma::fragment<wmma::matrix_b,16,16,16,h16,wmma::col_major> bh, bl;
                    wmma::load_matrix_sync(ah, Ahi + ti*16*XKS + kc*64 + ks, XKS);
                    wmma::load_matrix_sync(al, Alo + ti*16*XKS + kc*64 + ks, XKS);
                    wmma::load_matrix_sync(bh, Wh + tj*16*72 + ks, 72);
                    wmma::load_matrix_sync(bl, Wl + tj*16*72 + ks, 72);
                    wmma::mma_sync(accf, ah, bh, accf);
                    wmma::mma_sync(accf, ah, bl, accf);
                    wmma::mma_sync(accf, al, bh, accf);
                }
            }
        }
        __syncthreads();
        if (warp < 16)
            wmma::store_matrix_sync(sdbl + ti*16*68 + tj*16, accf, 68, wmma::mem_row_major);
    }
    __syncthreads();

    // dbl -> global for scan3
    for (int idx = tid; idx < 64*64; idx += DINNER) {
        int i = idx >> 6, j = idx & 63;
        g_dbl2[(size_t)(m0+i)*NX + j] = sdbl[i*68 + j];
    }

    // ---- scan1 phase ----
    {
        float wreg[DTRANK];
#pragma unroll
        for (int r = 0; r < DTRANK; r++)
            wreg[r] = dt_w[(size_t)(layer*DINNER + d)*DTRANK + r];
        float dbias = dt_b[layer*DINNER + d];
        float A2[DSTATE];
#pragma unroll
        for (int n = 0; n < DSTATE; n++)
            A2[n] = g_A2[(size_t)(layer*DINNER + d)*DSTATE + n];
        float ab = A2[0];
        bool fast = true;
#pragma unroll
        for (int n = 1; n < DSTATE; n++)
            fast = fast && (fabsf(A2[n] - (float)(n+1)*ab)
                            <= 1e-4f*fabsf((float)(n+1)*ab) + 1e-6f);

        float h[DSTATE];
#pragma unroll
        for (int n = 0; n < DSTATE; n++) h[n] = 0.f;
        float sumd = 0.f;

        for (int i = 0; i < CHUNK; i++) {
            float sdt = dbias;
#pragma unroll
            for (int r = 0; r < DTRANK; r++) sdt = fmaf(sdbl[i*68 + r], wreg[r], sdt);
            float delta = fmaxf(sdt, 0.f) + log1pf(__expf(-fabsf(sdt)));
            float u = __half2float(Ahi[i*XKS + d]) + __half2float(Alo[i*XKS + d]);
            float du = delta * u;
            if (fast) {
                float e1 = ex2(delta * ab);
                float p = e1;
#pragma unroll
                for (int n = 0; n < DSTATE; n++) {
                    h[n] = fmaf(p, h[n], du * sdbl[i*68 + DTRANK + n]);
                    p *= e1;
                }
            } else {
#pragma unroll
                for (int n = 0; n < DSTATE; n++) {
                    float a = ex2(delta * A2[n]);
                    h[n] = fmaf(a, h[n], du * sdbl[i*68 + DTRANK + n]);
                }
            }
            sumd += delta;
        }
        size_t o = ((size_t)(b*NCHUNK + c)*DINNER + d)*DSTATE;
#pragma unroll
        for (int n = 0; n < DSTATE; n++) {
            g_hend[o + n] = h[n];
            g_P[o + n] = ex2(A2[n] * sumd);
        }
    }
}

__global__ void __launch_bounds__(256) scan2_kernel()
{
    int gw = (blockIdx.x*256 + threadIdx.x) >> 5;
    int lane = threadIdx.x & 31;
    if (gw >= BATCH*(DINNER/2)) return;
    int b = gw / (DINNER/2);
    int dp = gw - b*(DINNER/2);
    float H = 0.f;
    for (int c = 0; c < NCHUNK; c++) {
        size_t o = ((size_t)(b*NCHUNK + c)*DINNER + dp*2)*DSTATE + lane;
        float P = g_P[o];
        float E = g_hend[o];
        g_Hin[o] = H;
        H = fmaf(P, H, E);
    }
}

// ---------------- scan3: inline conv + scan + gate -> yg fp16 ----------------
__global__ void __launch_bounds__(DINNER) scan3_kernel(
    const float* __restrict__ conv_w, const float* __restrict__ conv_b,
    const float* __restrict__ dt_w, const float* __restrict__ dt_b,
    const float* __restrict__ D_param, int layer)
{
    int c = blockIdx.x, b = blockIdx.y;
    int d = threadIdx.x;
    __shared__ float sD[CHUNK][NDBL+1];
    int t0 = c*CHUNK;
    int m0 = b*TSEQ + t0;
    for (int idx = d; idx < CHUNK*NDBL; idx += DINNER) {
        int i = idx / NDBL, j = idx - i*NDBL;
        sD[i][j] = g_dbl2[(size_t)(m0+i)*NX + j];
    }
    float wreg[DTRANK];
#pragma unroll
    for (int r = 0; r < DTRANK; r++)
        wreg[r] = dt_w[(size_t)(layer*DINNER + d)*DTRANK + r];
    float dbias = dt_b[layer*DINNER + d];
    float A2[DSTATE];
#pragma unroll
    for (int n = 0; n < DSTATE; n++)
        A2[n] = g_A2[(size_t)(layer*DINNER + d)*DSTATE + n];
    float ab = A2[0];
    bool fast = true;
#pragma unroll
    for (int n = 1; n < DSTATE; n++)
        fast = fast && (fabsf(A2[n] - (float)(n+1)*ab)
                        <= 1e-4f*fabsf((float)(n+1)*ab) + 1e-6f);

    const float* wp = conv_w + (size_t)(layer*DINNER + d)*DCONV;
    float w0 = wp[0], w1 = wp[1], w2 = wp[2], w3 = wp[3];
    float cbias = conv_b[layer*DINNER + d];
    size_t base = (size_t)(b*TSEQ)*(2*DINNER) + d;
    float x0 = (t0-3 >= 0) ? g_xz[base + (size_t)(t0-3)*(2*DINNER)] : 0.f;
    float x1 = (t0-2 >= 0) ? g_xz[base + (size_t)(t0-2)*(2*DINNER)] : 0.f;
    float x2 = (t0-1 >= 0) ? g_xz[base + (size_t)(t0-1)*(2*DINNER)] : 0.f;

    float h[DSTATE];
    size_t oin = ((size_t)(b*NCHUNK + c)*DINNER + d)*DSTATE;
#pragma unroll
    for (int n = 0; n < DSTATE; n++) h[n] = g_Hin[oin + n];
    float Dp = D_param[layer*DINNER + d];
    __syncthreads();

    for (int i = 0; i < CHUNK; i++) {
        int m = m0 + i;
        float x3 = g_xz[base + (size_t)(t0+i)*(2*DINNER)];
        float cs = cbias;
        cs = fmaf(w0, x0, cs); cs = fmaf(w1, x1, cs);
        cs = fmaf(w2, x2, cs); cs = fmaf(w3, x3, cs);
        float u = cs / (1.f + __expf(-cs));
        x0 = x1; x1 = x2; x2 = x3;

        float sdt = dbias;
#pragma unroll
        for (int r = 0; r < DTRANK; r++) sdt = fmaf(sD[i][r], wreg[r], sdt);
        float delta = fmaxf(sdt, 0.f) + log1pf(__expf(-fabsf(sdt)));
        float z = g_xz[base + (size_t)(t0+i)*(2*DINNER) + DINNER];
        float du = delta * u;
        float y = 0.f;
        if (fast) {
            float e1 = ex2(delta * ab);
            float p = e1;
#pragma unroll
            for (int n = 0; n < DSTATE; n++) {
                h[n] = fmaf(p, h[n], du * sD[i][DTRANK + n]);
                y = fmaf(h[n], sD[i][DTRANK + DSTATE + n], y);
                p *= e1;
            }
        } else {
#pragma unroll
            for (int n = 0; n < DSTATE; n++) {
                float a = ex2(delta * A2[n]);
                h[n] = fmaf(a, h[n], du * sD[i][DTRANK + n]);
                y = fmaf(h[n], sD[i][DTRANK + DSTATE + n], y);
            }
        }
        float silz = z / (1.f + __expf(-z));
        float yg = fmaf(u, Dp, y) * silz;
        g_yg[(size_t)m*DINNER + d] = __float2half_rn(yg);
    }
}

// ---------------- host launcher ----------------
extern "C" void kernel_launch(void* const* d_in, const int* in_sizes, int n_in,
                              void* d_out, int out_size)
{
    (void)in_sizes; (void)n_in; (void)out_size;
    const int*   type_seq = (const int*)  d_in[0];
    const float* time_seq = (const float*)d_in[1];
    const float* temp_seq = (const float*)d_in[2];
    const float* emb      = (const float*)d_in[3];
    const float* norm_w   = (const float*)d_in[4];
    const float* norm_b   = (const float*)d_in[5];
    const float* in_w     = (const float*)d_in[6];
    const float* conv_w   = (const float*)d_in[7];
    const float* conv_b   = (const float*)d_in[8];
    const float* xproj_w  = (const float*)d_in[9];
    const float* dt_w     = (const float*)d_in[10];
    const float* dt_b     = (const float*)d_in[11];
    const float* A_log    = (const float*)d_in[12];
    const float* D_param  = (const float*)d_in[13];
    const float* out_w    = (const float*)d_in[14];
    const float* normf_w  = (const float*)d_in[15];
    const float* normf_b  = (const float*)d_in[16];
    float* out = (float*)d_out;

    float *p_xz, *p_h;
    cudaGetSymbolAddress((void**)&p_xz, g_xz);
    cudaGetSymbolAddress((void**)&p_h,  g_h);
    h16 *p_hn, *p_yg, *p_w1h, *p_w1l, *p_w2h, *p_w2l;
    cudaGetSymbolAddress((void**)&p_hn,  g_hn);
    cudaGetSymbolAddress((void**)&p_yg,  g_yg);
    cudaGetSymbolAddress((void**)&p_w1h, g_w1_hi);
    cudaGetSymbolAddress((void**)&p_w1l, g_w1_lo);
    cudaGetSymbolAddress((void**)&p_w2h, g_w2_hi);
    cudaGetSymbolAddress((void**)&p_w2l, g_w2_lo);

    cudaFuncSetAttribute(gemm_h16,
                         cudaFuncAttributeMaxDynamicSharedMemorySize, GEMM_SMEM);
    cudaFuncSetAttribute(mega1,
                         cudaFuncAttributeMaxDynamicSharedMemorySize, MG_SMEM);

    embed_kernel<<<MROWS, DDIM>>>(type_seq, time_seq, temp_seq, emb);
    prep_all<<<(W1TOT + W2TOT + WXTOT + A2TOT + 255)/256, 256>>>(
        in_w, out_w, xproj_w, A_log);

    for (int l = 0; l < NLAYER; l++) {
        addnorm_kernel<<<MROWS, 128>>>(norm_w + l*DDIM, norm_b + l*DDIM, l > 0);

        gemm_h16<<<dim3((2*DINNER + 127)/128, MROWS/128), 256, GEMM_SMEM>>>(
            p_hn,
            p_w1h + (size_t)l*2*DINNER*KPAD1, p_w1l + (size_t)l*2*DINNER*KPAD1,
            p_xz, MROWS, 2*DINNER, KPAD1);

        mega1<<<dim3(NCHUNK, BATCH), DINNER, MG_SMEM>>>(
            conv_w, conv_b, dt_w, dt_b, l);

        scan2_kernel<<<(BATCH*(DINNER/2)*32 + 255)/256, 256>>>();

        scan3_kernel<<<dim3(NCHUNK, BATCH), DINNER>>>(
            conv_w, conv_b, dt_w, dt_b, D_param, l);

        gemm_h16<<<dim3((DDIM + 127)/128, MROWS/128), 256, GEMM_SMEM>>>(
            p_yg,
            p_w2h + (size_t)l*DDIM*DINNER, p_w2l + (size_t)l*DDIM*DINNER,
            p_h, MROWS, DDIM, DINNER);
    }

    final_kernel<<<BATCH*LQ, 128>>>(normf_w, normf_b, out);
}

// round 11
// speedup vs baseline: 3.0626x; 1.0660x over previous
#include <cuda_runtime.h>
#include <cuda_fp16.h>
#include <math.h>
#include <stdint.h>
#include <mma.h>

using namespace nvcuda;

#define BATCH   4
#define LQ      1024
#define TSEQ    2048
#define DMODEL  256
#define DTIME   16
#define DDIM    272
#define KPAD1   288
#define NLAYER  4
#define DINNER  544
#define DSTATE  16
#define DCONV   4
#define DTRANK  17
#define NDBL    (DTRANK + 2*DSTATE)   // 49
#define MROWS   (BATCH*TSEQ)          // 8192
#define NCHUNK  32
#define CHUNK   (TSEQ/NCHUNK)         // 64
#define XK      576
#define XKS     (XK+8)
#define NX      64

typedef __half h16;

__device__ float g_h   [MROWS*DDIM];
__device__ float g_res [MROWS*DDIM];
__device__ float g_xz  [MROWS*2*DINNER];
__device__ float g_dbl2[MROWS*NX];
__device__ float g_hend[BATCH*NCHUNK*DINNER*DSTATE];
__device__ float g_P   [BATCH*NCHUNK*DINNER*DSTATE];
__device__ float g_Hin [BATCH*NCHUNK*DINNER*DSTATE];
__device__ float g_A2  [NLAYER*DINNER*DSTATE];
__device__ h16 g_hn [MROWS*KPAD1];
__device__ h16 g_yg [MROWS*DINNER];
__device__ h16 g_w1_hi[NLAYER*2*DINNER*KPAD1];
__device__ h16 g_w1_lo[NLAYER*2*DINNER*KPAD1];
__device__ h16 g_w2_hi[NLAYER*DDIM*DINNER];
__device__ h16 g_w2_lo[NLAYER*DDIM*DINNER];
__device__ h16 g_wx_hi[NLAYER*64*XK];
__device__ h16 g_wx_lo[NLAYER*64*XK];

__device__ __forceinline__ float ex2(float x) {
    float y; asm("ex2.approx.ftz.f32 %0, %1;" : "=f"(y) : "f"(x)); return y;
}
__device__ __forceinline__ void split_h16(float v, h16& hi, h16& lo) {
    hi = __float2half_rn(v);
    lo = __float2half_rn(v - __half2float(hi));
}
__device__ __forceinline__ void cp16(uint32_t saddr, const void* g, int srcsz) {
    asm volatile("cp.async.ca.shared.global [%0], [%1], 16, %2;\n"
                 :: "r"(saddr), "l"(g), "r"(srcsz));
}
__device__ __forceinline__ void cp_commit() { asm volatile("cp.async.commit_group;\n"); }
template<int NN> __device__ __forceinline__ void cp_wait() {
    asm volatile("cp.async.wait_group %0;\n" :: "n"(NN));
}

// ---------------- embedding ----------------
__global__ void __launch_bounds__(DDIM) embed_kernel(
    const int* __restrict__ type_seq, const float* __restrict__ time_seq,
    const float* __restrict__ temp_seq, const float* __restrict__ emb)
{
    int row = blockIdx.x;
    int d = threadIdx.x;
    int b = row / TSEQ, t = row % TSEQ;
    float v;
    if (t < LQ) {
        if (d < DMODEL) {
            v = tanhf(emb[(size_t)type_seq[b*LQ + t]*DMODEL + d]);
        } else {
            int j = d - DMODEL;
            int i = j >> 1;
            float div = expf(-0.57564627324851142f * (float)(2*i));
            float arg = time_seq[b*LQ + t] * div;
            v = (j & 1) ? cosf(arg) : sinf(arg);
        }
    } else {
        v = (d < DMODEL) ? 0.f
                         : temp_seq[(size_t)(b*LQ + (t - LQ))*DTIME + (d - DMODEL)];
    }
    g_h[(size_t)row*DDIM + d] = v;
}

// ---------------- one-time prep ----------------
#define W1TOT (NLAYER*2*DINNER*KPAD1)
#define W2TOT (NLAYER*DDIM*DINNER)
#define WXTOT (NLAYER*64*XK)
#define A2TOT (NLAYER*DINNER*DSTATE)
__global__ void __launch_bounds__(256) prep_all(
    const float* __restrict__ in_w, const float* __restrict__ out_w,
    const float* __restrict__ xproj_w, const float* __restrict__ A_log)
{
    int idx = blockIdx.x*256 + threadIdx.x;
    if (idx < W1TOT) {
        const int per = 2*DINNER*KPAD1;
        int l = idx / per, rem = idx - l*per;
        int r = rem / KPAD1, c = rem - r*KPAD1;
        float v = (c < DDIM) ? in_w[((size_t)l*2*DINNER + r)*DDIM + c] : 0.f;
        split_h16(v, g_w1_hi[idx], g_w1_lo[idx]);
    } else if (idx < W1TOT + W2TOT) {
        int j = idx - W1TOT;
        split_h16(out_w[j], g_w2_hi[j], g_w2_lo[j]);
    } else if (idx < W1TOT + W2TOT + WXTOT) {
        int j = idx - W1TOT - W2TOT;
        const int per = 64*XK;
        int l = j / per, rem = j - l*per;
        int r = rem / XK, cc = rem - r*XK;
        float v = (r < NDBL && cc < DINNER)
                ? xproj_w[((size_t)l*NDBL + r)*DINNER + cc] : 0.f;
        split_h16(v, g_wx_hi[j], g_wx_lo[j]);
    } else if (idx < W1TOT + W2TOT + WXTOT + A2TOT) {
        int j = idx - W1TOT - W2TOT - WXTOT;
        g_A2[j] = -__expf(A_log[j]) * 1.4426950408889634f;
    }
}

// ---------------- residual add + layernorm -> fp16 hn ----------------
__global__ void __launch_bounds__(128) addnorm_kernel(
    const float* __restrict__ gamma, const float* __restrict__ beta, int addflag)
{
    int row = blockIdx.x;
    int tid = threadIdx.x;
    float v[3];
    float s = 0.f, s2 = 0.f;
#pragma unroll
    for (int j = 0; j < 3; j++) {
        int d = tid + j*128;
        float x = 0.f;
        if (d < DDIM) {
            x = g_h[(size_t)row*DDIM + d];
            if (addflag) x += g_res[(size_t)row*DDIM + d];
        }
        v[j] = x; s += x; s2 += x*x;
    }
#pragma unroll
    for (int o = 16; o > 0; o >>= 1) {
        s  += __shfl_down_sync(0xffffffffu, s,  o);
        s2 += __shfl_down_sync(0xffffffffu, s2, o);
    }
    __shared__ float ss[4], ss2[4];
    if ((tid & 31) == 0) { ss[tid >> 5] = s; ss2[tid >> 5] = s2; }
    __syncthreads();
    if (tid == 0) {
        float a  = ss[0]+ss[1]+ss[2]+ss[3];
        float a2 = ss2[0]+ss2[1]+ss2[2]+ss2[3];
        float mean = a * (1.f/DDIM);
        float var  = a2 * (1.f/DDIM) - mean*mean;
        ss[0] = mean;
        ss2[0] = rsqrtf(var + 1e-5f);
    }
    __syncthreads();
    float mean = ss[0], rstd = ss2[0];
#pragma unroll
    for (int j = 0; j < 3; j++) {
        int d = tid + j*128;
        if (d < DDIM) {
            g_res[(size_t)row*DDIM + d] = v[j];
            float hn = (v[j]-mean)*rstd*gamma[d] + beta[d];
            g_hn[(size_t)row*KPAD1 + d] = __float2half_rn(hn);
        } else if (d < KPAD1) {
            g_hn[(size_t)row*KPAD1 + d] = __float2half(0.f);
        }
    }
}

// ---------------- final add + layernorm ----------------
__global__ void __launch_bounds__(128) final_kernel(
    const float* __restrict__ gamma, const float* __restrict__ beta,
    float* __restrict__ out)
{
    int rowo = blockIdx.x;
    int tid = threadIdx.x;
    int b = rowo / LQ, t = rowo % LQ;
    int m = b*TSEQ + t;
    float v[3];
    float s = 0.f, s2 = 0.f;
#pragma unroll
    for (int j = 0; j < 3; j++) {
        int d = tid + j*128;
        float x = 0.f;
        if (d < DDIM) x = g_h[(size_t)m*DDIM + d] + g_res[(size_t)m*DDIM + d];
        v[j] = x; s += x; s2 += x*x;
    }
#pragma unroll
    for (int o = 16; o > 0; o >>= 1) {
        s  += __shfl_down_sync(0xffffffffu, s,  o);
        s2 += __shfl_down_sync(0xffffffffu, s2, o);
    }
    __shared__ float ss[4], ss2[4];
    if ((tid & 31) == 0) { ss[tid >> 5] = s; ss2[tid >> 5] = s2; }
    __syncthreads();
    if (tid == 0) {
        float a  = ss[0]+ss[1]+ss[2]+ss[3];
        float a2 = ss2[0]+ss2[1]+ss2[2]+ss2[3];
        float mean = a * (1.f/DDIM);
        float var  = a2 * (1.f/DDIM) - mean*mean;
        ss[0] = mean;
        ss2[0] = rsqrtf(var + 1e-5f);
    }
    __syncthreads();
    float mean = ss[0], rstd = ss2[0];
#pragma unroll
    for (int j = 0; j < 3; j++) {
        int d = tid + j*128;
        if (d < DDIM)
            out[(size_t)rowo*DDIM + d] = (v[j]-mean)*rstd*gamma[d] + beta[d];
    }
}

// ---------------- fp16 2-term GEMM, cp.async 3-stage, 1 sync/tile ----------------
#define SPAD 8
#define SROW (32+SPAD)
__global__ void __launch_bounds__(256, 2) gemm_h16(
    const h16* __restrict__ A,
    const h16* __restrict__ Whi, const h16* __restrict__ Wlo,
    float* __restrict__ C, int M, int N, int Kpad)
{
    extern __shared__ h16 sm[];
    int tid = threadIdx.x;
    int warp = tid >> 5;
    int wm = warp >> 2;
    int wn = warp & 3;
    int mb = blockIdx.y * 128;
    int nb = blockIdx.x * 128;
    bool wnvalid = (nb + wn*32) < N;     // whole 32-col slab OOB -> skip compute

    int aIdx0 = tid*2, aIdx1 = tid*2 + 1;
    int r0 = aIdx0 >> 2, c0 = (aIdx0 & 3) * 8;
    int r1 = aIdx1 >> 2, c1 = (aIdx1 & 3) * 8;
    int wsz0 = ((nb + r0) < N) ? 16 : 0;
    int wsz1 = ((nb + r1) < N) ? 16 : 0;

    const h16* pA0 = A   + (size_t)(mb + r0)*Kpad + c0;
    const h16* pA1 = A   + (size_t)(mb + r1)*Kpad + c1;
    const h16* pW0 = Whi + (size_t)(nb + r0)*Kpad + c0;
    const h16* pW1 = Whi + (size_t)(nb + r1)*Kpad + c1;
    const h16* pV0 = Wlo + (size_t)(nb + r0)*Kpad + c0;
    const h16* pV1 = Wlo + (size_t)(nb + r1)*Kpad + c1;

    uint32_t sbase = (uint32_t)__cvta_generic_to_shared(sm);
    auto soff = [&](int stage, int arr, int row, int col) -> uint32_t {
        return (uint32_t)((((stage*3 + arr)*128) + row)*SROW + col);
    };
    uint32_t dA0 = soff(0,0,r0,c0), dA1 = soff(0,0,r1,c1);
    uint32_t dW0 = soff(0,1,r0,c0), dW1 = soff(0,1,r1,c1);
    uint32_t dV0 = soff(0,2,r0,c0), dV1 = soff(0,2,r1,c1);
    const uint32_t STG = 3*128*SROW;

    wmma::fragment<wmma::accumulator,16,16,16,float> acc[4][2];
#pragma unroll
    for (int i = 0; i < 4; i++)
#pragma unroll
        for (int j = 0; j < 2; j++) wmma::fill_fragment(acc[i][j], 0.f);

    int ktiles = Kpad >> 5;

    auto issue = [&](int kt) {
        int st = kt % 3;
        int go = kt * 32;
        uint32_t so = st * STG;
        cp16(sbase + 2*(dA0+so), pA0 + go, 16); cp16(sbase + 2*(dA1+so), pA1 + go, 16);
        cp16(sbase + 2*(dW0+so), pW0 + go, wsz0); cp16(sbase + 2*(dW1+so), pW1 + go, wsz1);
        cp16(sbase + 2*(dV0+so), pV0 + go, wsz0); cp16(sbase + 2*(dV1+so), pV1 + go, wsz1);
        cp_commit();
    };

    issue(0);
    issue(1);

    for (int kt = 0; kt < ktiles; kt++) {
        // keep one group (tile kt+1's data) pending; empty groups issued on the
        // tail BEFORE the wait so the wait always covers the data group for kt.
        if (kt + 2 >= ktiles) cp_commit();   // empty placeholder for missing tile
        cp_wait<1>();
        __syncthreads();
        if (kt + 2 < ktiles) issue(kt + 2);

        if (wnvalid) {
            const h16* bA   = sm + (size_t)(kt%3)*STG + 0*128*SROW;
            const h16* bWhi = sm + (size_t)(kt%3)*STG + 1*128*SROW;
            const h16* bWlo = sm + (size_t)(kt%3)*STG + 2*128*SROW;
#pragma unroll
            for (int ks = 0; ks < 32; ks += 16) {
                wmma::fragment<wmma::matrix_b,16,16,16,h16,wmma::col_major> bhi[2], blo[2];
#pragma unroll
                for (int j = 0; j < 2; j++) {
                    wmma::load_matrix_sync(bhi[j], bWhi + (wn*32 + j*16)*SROW + ks, SROW);
                    wmma::load_matrix_sync(blo[j], bWlo + (wn*32 + j*16)*SROW + ks, SROW);
                }
#pragma unroll
                for (int i = 0; i < 4; i++) {
                    wmma::fragment<wmma::matrix_a,16,16,16,h16,wmma::row_major> af;
                    wmma::load_matrix_sync(af, bA + (wm*64 + i*16)*SROW + ks, SROW);
#pragma unroll
                    for (int j = 0; j < 2; j++) {
                        wmma::mma_sync(acc[i][j], af, bhi[j], acc[i][j]);
                        wmma::mma_sync(acc[i][j], af, blo[j], acc[i][j]);
                    }
                }
            }
        }
    }
    if (wnvalid) {
#pragma unroll
        for (int i = 0; i < 4; i++)
#pragma unroll
            for (int j = 0; j < 2; j++) {
                int n0 = nb + wn*32 + j*16;
                if (n0 < N)
                    wmma::store_matrix_sync(C + (size_t)(mb + wm*64 + i*16)*N + n0,
                                            acc[i][j], N, wmma::mem_row_major);
            }
    }
}
#define GEMM_SMEM (3*3*128*SROW*2)   // 92160 bytes -> 2 CTAs/SM

// ---------------- mega1: conv + x_proj (3-term fp16 tensor) + scan1 ----------------
#define MG_AHI  0
#define MG_ALO  (64*XKS*2)
#define MG_WH   (2*64*XKS*2)
#define MG_WL   (MG_WH + 64*72*2)
#define MG_DBL  (MG_WL + 64*72*2)
#define MG_SMEM (MG_DBL + 64*68*4)
__global__ void __launch_bounds__(DINNER) mega1(
    const float* __restrict__ conv_w, const float* __restrict__ conv_b,
    const float* __restrict__ dt_w, const float* __restrict__ dt_b,
    int layer)
{
    extern __shared__ __align__(16) char smx[];
    h16*  Ahi  = (h16*)(smx + MG_AHI);
    h16*  Alo  = (h16*)(smx + MG_ALO);
    h16*  Wh   = (h16*)(smx + MG_WH);
    h16*  Wl   = (h16*)(smx + MG_WL);
    float* sdbl = (float*)(smx + MG_DBL);

    int c = blockIdx.x, b = blockIdx.y;
    int tid = threadIdx.x;
    int d = tid;
    int warp = tid >> 5;
    int t0 = c*CHUNK;
    int m0 = b*TSEQ + t0;

    // ---- conv phase (MLP-batched loads) ----
    {
        const float* wp = conv_w + (size_t)(layer*DINNER + d)*DCONV;
        float w0 = wp[0], w1 = wp[1], w2 = wp[2], w3 = wp[3];
        float bias = conv_b[layer*DINNER + d];
        size_t base = (size_t)(b*TSEQ)*(2*DINNER) + d;
        float x0 = (t0-3 >= 0) ? g_xz[base + (size_t)(t0-3)*(2*DINNER)] : 0.f;
        float x1 = (t0-2 >= 0) ? g_xz[base + (size_t)(t0-2)*(2*DINNER)] : 0.f;
        float x2 = (t0-1 >= 0) ? g_xz[base + (size_t)(t0-1)*(2*DINNER)] : 0.f;
        for (int i0 = 0; i0 < CHUNK; i0 += 8) {
            float xv[8];
#pragma unroll
            for (int j = 0; j < 8; j++)
                xv[j] = g_xz[base + (size_t)(t0+i0+j)*(2*DINNER)];
#pragma unroll
            for (int j = 0; j < 8; j++) {
                float x3 = xv[j];
                float s = bias;
                s = fmaf(w0, x0, s); s = fmaf(w1, x1, s);
                s = fmaf(w2, x2, s); s = fmaf(w3, x3, s);
                float sl = s / (1.f + __expf(-s));
                h16 hi, lo; split_h16(sl, hi, lo);
                Ahi[(i0+j)*XKS + d] = hi;
                Alo[(i0+j)*XKS + d] = lo;
                x0 = x1; x1 = x2; x2 = x3;
            }
        }
        if (d < XK - DINNER) {
            h16 z0 = __float2half(0.f);
            for (int i = 0; i < CHUNK; i++) {
                Ahi[i*XKS + DINNER + d] = z0;
                Alo[i*XKS + DINNER + d] = z0;
            }
        }
    }
    __syncthreads();

    // ---- x_proj GEMM: sdbl[64][64] = A[64][576] @ Wx[64][576]^T (3-term) ----
    {
        wmma::fragment<wmma::accumulator,16,16,16,float> accf;
        if (warp < 16) wmma::fill_fragment(accf, 0.f);
        int ti = warp >> 2, tj = warp & 3;
        const h16* gwh = g_wx_hi + (size_t)layer*64*XK;
        const h16* gwl = g_wx_lo + (size_t)layer*64*XK;
        for (int kc = 0; kc < XK/64; kc++) {
            __syncthreads();
            for (int idx = tid; idx < 512; idx += DINNER) {
                int r = idx >> 3, q = (idx & 7)*8;
                *(uint4*)&Wh[r*72 + q] = *(const uint4*)&gwh[(size_t)r*XK + kc*64 + q];
                *(uint4*)&Wl[r*72 + q] = *(const uint4*)&gwl[(size_t)r*XK + kc*64 + q];
            }
            __syncthreads();
            if (warp < 16) {
#pragma unroll
                for (int ks = 0; ks < 64; ks += 16) {
                    wmma::fragment<wmma::matrix_a,16,16,16,h16,wmma::row_major> ah, al;
                    wmma::fragment<wmma::matrix_b,16,16,16,h16,wmma::col_major> bh, bl;
                    wmma::load_matrix_sync(ah, Ahi + ti*16*XKS + kc*64 + ks, XKS);
                    wmma::load_matrix_sync(al, Alo + ti*16*XKS + kc*64 + ks, XKS);
                    wmma::load_matrix_sync(bh, Wh + tj*16*72 + ks, 72);
                    wmma::load_matrix_sync(bl, Wl + tj*16*72 + ks, 72);
                    wmma::mma_sync(accf, ah, bh, accf);
                    wmma::mma_sync(accf, ah, bl, accf);
                    wmma::mma_sync(accf, al, bh, accf);
                }
            }
        }
        __syncthreads();
        if (warp < 16)
            wmma::store_matrix_sync(sdbl + ti*16*68 + tj*16, accf, 68, wmma::mem_row_major);
    }
    __syncthreads();

    // dbl -> global for scan3
    for (int idx = tid; idx < 64*64; idx += DINNER) {
        int i = idx >> 6, j = idx & 63;
        g_dbl2[(size_t)(m0+i)*NX + j] = sdbl[i*68 + j];
    }

    // ---- scan1 phase ----
    {
        float wreg[DTRANK];
#pragma unroll
        for (int r = 0; r < DTRANK; r++)
            wreg[r] = dt_w[(size_t)(layer*DINNER + d)*DTRANK + r];
        float dbias = dt_b[layer*DINNER + d];
        float A2[DSTATE];
#pragma unroll
        for (int n = 0; n < DSTATE; n++)
            A2[n] = g_A2[(size_t)(layer*DINNER + d)*DSTATE + n];
        float ab = A2[0];
        bool fast = true;
#pragma unroll
        for (int n = 1; n < DSTATE; n++)
            fast = fast && (fabsf(A2[n] - (float)(n+1)*ab)
                            <= 1e-4f*fabsf((float)(n+1)*ab) + 1e-6f);

        float h[DSTATE];
#pragma unroll
        for (int n = 0; n < DSTATE; n++) h[n] = 0.f;
        float sumd = 0.f;

        for (int i = 0; i < CHUNK; i++) {
            float sdt = dbias;
#pragma unroll
            for (int r = 0; r < DTRANK; r++) sdt = fmaf(sdbl[i*68 + r], wreg[r], sdt);
            float delta = fmaxf(sdt, 0.f) + log1pf(__expf(-fabsf(sdt)));
            float u = __half2float(Ahi[i*XKS + d]) + __half2float(Alo[i*XKS + d]);
            float du = delta * u;
            if (fast) {
                float e1 = ex2(delta * ab);
                float p = e1;
#pragma unroll
                for (int n = 0; n < DSTATE; n++) {
                    h[n] = fmaf(p, h[n], du * sdbl[i*68 + DTRANK + n]);
                    p *= e1;
                }
            } else {
#pragma unroll
                for (int n = 0; n < DSTATE; n++) {
                    float a = ex2(delta * A2[n]);
                    h[n] = fmaf(a, h[n], du * sdbl[i*68 + DTRANK + n]);
                }
            }
            sumd += delta;
        }
        size_t o = ((size_t)(b*NCHUNK + c)*DINNER + d)*DSTATE;
#pragma unroll
        for (int n = 0; n < DSTATE; n++) {
            g_hend[o + n] = h[n];
            g_P[o + n] = ex2(A2[n] * sumd);
        }
    }
}

__global__ void __launch_bounds__(256) scan2_kernel()
{
    int gw = (blockIdx.x*256 + threadIdx.x) >> 5;
    int lane = threadIdx.x & 31;
    if (gw >= BATCH*(DINNER/2)) return;
    int b = gw / (DINNER/2);
    int dp = gw - b*(DINNER/2);
    float H = 0.f;
    for (int c = 0; c < NCHUNK; c++) {
        size_t o = ((size_t)(b*NCHUNK + c)*DINNER + dp*2)*DSTATE + lane;
        float P = g_P[o];
        float E = g_hend[o];
        g_Hin[o] = H;
        H = fmaf(P, H, E);
    }
}

// ---------------- scan3: inline conv + scan + gate -> yg fp16 (MLP-batched) ----------------
__global__ void __launch_bounds__(DINNER) scan3_kernel(
    const float* __restrict__ conv_w, const float* __restrict__ conv_b,
    const float* __restrict__ dt_w, const float* __restrict__ dt_b,
    const float* __restrict__ D_param, int layer)
{
    int c = blockIdx.x, b = blockIdx.y;
    int d = threadIdx.x;
    __shared__ float sD[CHUNK][NDBL+1];
    int t0 = c*CHUNK;
    int m0 = b*TSEQ + t0;
    for (int idx = d; idx < CHUNK*NDBL; idx += DINNER) {
        int i = idx / NDBL, j = idx - i*NDBL;
        sD[i][j] = g_dbl2[(size_t)(m0+i)*NX + j];
    }
    float wreg[DTRANK];
#pragma unroll
    for (int r = 0; r < DTRANK; r++)
        wreg[r] = dt_w[(size_t)(layer*DINNER + d)*DTRANK + r];
    float dbias = dt_b[layer*DINNER + d];
    float A2[DSTATE];
#pragma unroll
    for (int n = 0; n < DSTATE; n++)
        A2[n] = g_A2[(size_t)(layer*DINNER + d)*DSTATE + n];
    float ab = A2[0];
    bool fast = true;
#pragma unroll
    for (int n = 1; n < DSTATE; n++)
        fast = fast && (fabsf(A2[n] - (float)(n+1)*ab)
                        <= 1e-4f*fabsf((float)(n+1)*ab) + 1e-6f);

    const float* wp = conv_w + (size_t)(layer*DINNER + d)*DCONV;
    float w0 = wp[0], w1 = wp[1], w2 = wp[2], w3 = wp[3];
    float cbias = conv_b[layer*DINNER + d];
    size_t base = (size_t)(b*TSEQ)*(2*DINNER) + d;
    float x0 = (t0-3 >= 0) ? g_xz[base + (size_t)(t0-3)*(2*DINNER)] : 0.f;
    float x1 = (t0-2 >= 0) ? g_xz[base + (size_t)(t0-2)*(2*DINNER)] : 0.f;
    float x2 = (t0-1 >= 0) ? g_xz[base + (size_t)(t0-1)*(2*DINNER)] : 0.f;

    float h[DSTATE];
    size_t oin = ((size_t)(b*NCHUNK + c)*DINNER + d)*DSTATE;
#pragma unroll
    for (int n = 0; n < DSTATE; n++) h[n] = g_Hin[oin + n];
    float Dp = D_param[layer*DINNER + d];
    __syncthreads();

    for (int i0 = 0; i0 < CHUNK; i0 += 8) {
        float xv[8], zv[8];
#pragma unroll
        for (int j = 0; j < 8; j++) {
            size_t rowoff = base + (size_t)(t0+i0+j)*(2*DINNER);
            xv[j] = g_xz[rowoff];
            zv[j] = g_xz[rowoff + DINNER];
        }
#pragma unroll
        for (int j = 0; j < 8; j++) {
            int i = i0 + j;
            int m = m0 + i;
            float x3 = xv[j];
            float cs = cbias;
            cs = fmaf(w0, x0, cs); cs = fmaf(w1, x1, cs);
            cs = fmaf(w2, x2, cs); cs = fmaf(w3, x3, cs);
            float u = cs / (1.f + __expf(-cs));
            x0 = x1; x1 = x2; x2 = x3;

            float sdt = dbias;
#pragma unroll
            for (int r = 0; r < DTRANK; r++) sdt = fmaf(sD[i][r], wreg[r], sdt);
            float delta = fmaxf(sdt, 0.f) + log1pf(__expf(-fabsf(sdt)));
            float du = delta * u;
            float y = 0.f;
            if (fast) {
                float e1 = ex2(delta * ab);
                float p = e1;
#pragma unroll
                for (int n = 0; n < DSTATE; n++) {
                    h[n] = fmaf(p, h[n], du * sD[i][DTRANK + n]);
                    y = fmaf(h[n], sD[i][DTRANK + DSTATE + n], y);
                    p *= e1;
                }
            } else {
#pragma unroll
                for (int n = 0; n < DSTATE; n++) {
                    float a = ex2(delta * A2[n]);
                    h[n] = fmaf(a, h[n], du * sD[i][DTRANK + n]);
                    y = fmaf(h[n], sD[i][DTRANK + DSTATE + n], y);
                }
            }
            float silz = zv[j] / (1.f + __expf(-zv[j]));
            float yg = fmaf(u, Dp, y) * silz;
            g_yg[(size_t)m*DINNER + d] = __float2half_rn(yg);
        }
    }
}

// ---------------- host launcher ----------------
extern "C" void kernel_launch(void* const* d_in, const int* in_sizes, int n_in,
                              void* d_out, int out_size)
{
    (void)in_sizes; (void)n_in; (void)out_size;
    const int*   type_seq = (const int*)  d_in[0];
    const float* time_seq = (const float*)d_in[1];
    const float* temp_seq = (const float*)d_in[2];
    const float* emb      = (const float*)d_in[3];
    const float* norm_w   = (const float*)d_in[4];
    const float* norm_b   = (const float*)d_in[5];
    const float* in_w     = (const float*)d_in[6];
    const float* conv_w   = (const float*)d_in[7];
    const float* conv_b   = (const float*)d_in[8];
    const float* xproj_w  = (const float*)d_in[9];
    const float* dt_w     = (const float*)d_in[10];
    const float* dt_b     = (const float*)d_in[11];
    const float* A_log    = (const float*)d_in[12];
    const float* D_param  = (const float*)d_in[13];
    const float* out_w    = (const float*)d_in[14];
    const float* normf_w  = (const float*)d_in[15];
    const float* normf_b  = (const float*)d_in[16];
    float* out = (float*)d_out;

    float *p_xz, *p_h;
    cudaGetSymbolAddress((void**)&p_xz, g_xz);
    cudaGetSymbolAddress((void**)&p_h,  g_h);
    h16 *p_hn, *p_yg, *p_w1h, *p_w1l, *p_w2h, *p_w2l;
    cudaGetSymbolAddress((void**)&p_hn,  g_hn);
    cudaGetSymbolAddress((void**)&p_yg,  g_yg);
    cudaGetSymbolAddress((void**)&p_w1h, g_w1_hi);
    cudaGetSymbolAddress((void**)&p_w1l, g_w1_lo);
    cudaGetSymbolAddress((void**)&p_w2h, g_w2_hi);
    cudaGetSymbolAddress((void**)&p_w2l, g_w2_lo);

    cudaFuncSetAttribute(gemm_h16,
                         cudaFuncAttributeMaxDynamicSharedMemorySize, GEMM_SMEM);
    cudaFuncSetAttribute(mega1,
                         cudaFuncAttributeMaxDynamicSharedMemorySize, MG_SMEM);

    embed_kernel<<<MROWS, DDIM>>>(type_seq, time_seq, temp_seq, emb);
    prep_all<<<(W1TOT + W2TOT + WXTOT + A2TOT + 255)/256, 256>>>(
        in_w, out_w, xproj_w, A_log);

    for (int l = 0; l < NLAYER; l++) {
        addnorm_kernel<<<MROWS, 128>>>(norm_w + l*DDIM, norm_b + l*DDIM, l > 0);

        gemm_h16<<<dim3((2*DINNER + 127)/128, MROWS/128), 256, GEMM_SMEM>>>(
            p_hn,
            p_w1h + (size_t)l*2*DINNER*KPAD1, p_w1l + (size_t)l*2*DINNER*KPAD1,
            p_xz, MROWS, 2*DINNER, KPAD1);

        mega1<<<dim3(NCHUNK, BATCH), DINNER, MG_SMEM>>>(
            conv_w, conv_b, dt_w, dt_b, l);

        scan2_kernel<<<(BATCH*(DINNER/2)*32 + 255)/256, 256>>>();

        scan3_kernel<<<dim3(NCHUNK, BATCH), DINNER>>>(
            conv_w, conv_b, dt_w, dt_b, D_param, l);

        gemm_h16<<<dim3((DDIM + 127)/128, MROWS/128), 256, GEMM_SMEM>>>(
            p_yg,
            p_w2h + (size_t)l*DDIM*DINNER, p_w2l + (size_t)l*DDIM*DINNER,
            p_h, MROWS, DDIM, DINNER);
    }

    final_kernel<<<BATCH*LQ, 128>>>(normf_w, normf_b, out);
}

// round 12
// speedup vs baseline: 3.1110x; 1.0158x over previous
#include <cuda_runtime.h>
#include <cuda_fp16.h>
#include <math.h>
#include <stdint.h>
#include <mma.h>

using namespace nvcuda;

#define BATCH   4
#define LQ      1024
#define TSEQ    2048
#define DMODEL  256
#define DTIME   16
#define DDIM    272
#define KPAD1   288
#define NLAYER  4
#define DINNER  544
#define DSTATE  16
#define DCONV   4
#define DTRANK  17
#define NDBL    (DTRANK + 2*DSTATE)   // 49
#define MROWS   (BATCH*TSEQ)          // 8192
#define NCHUNK  32
#define CHUNK   (TSEQ/NCHUNK)         // 64
#define XK      576
#define XKS     (XK+8)
#define NX      64

typedef __half h16;

__device__ float g_h   [MROWS*DDIM];
__device__ float g_res [MROWS*DDIM];
__device__ float g_xz  [MROWS*2*DINNER];
__device__ float g_dbl2[MROWS*NX];
__device__ float g_hend[BATCH*NCHUNK*DINNER*DSTATE];
__device__ float g_P   [BATCH*NCHUNK*DINNER*DSTATE];
__device__ float g_Hin [BATCH*NCHUNK*DINNER*DSTATE];
__device__ float g_A2  [NLAYER*DINNER*DSTATE];
__device__ h16 g_hn [MROWS*KPAD1];
__device__ h16 g_yg [MROWS*DINNER];
__device__ h16 g_w1_hi[NLAYER*2*DINNER*KPAD1];
__device__ h16 g_w1_lo[NLAYER*2*DINNER*KPAD1];
__device__ h16 g_w2_hi[NLAYER*DDIM*DINNER];
__device__ h16 g_w2_lo[NLAYER*DDIM*DINNER];
__device__ h16 g_wx_hi[NLAYER*64*XK];
__device__ h16 g_wx_lo[NLAYER*64*XK];

__device__ __forceinline__ float ex2(float x) {
    float y; asm("ex2.approx.ftz.f32 %0, %1;" : "=f"(y) : "f"(x)); return y;
}
__device__ __forceinline__ void split_h16(float v, h16& hi, h16& lo) {
    hi = __float2half_rn(v);
    lo = __float2half_rn(v - __half2float(hi));
}
__device__ __forceinline__ void cp16(uint32_t saddr, const void* g, int srcsz) {
    asm volatile("cp.async.ca.shared.global [%0], [%1], 16, %2;\n"
                 :: "r"(saddr), "l"(g), "r"(srcsz));
}
__device__ __forceinline__ void cp_commit() { asm volatile("cp.async.commit_group;\n"); }
template<int NN> __device__ __forceinline__ void cp_wait() {
    asm volatile("cp.async.wait_group %0;\n" :: "n"(NN));
}

// ---------------- embedding ----------------
__global__ void __launch_bounds__(DDIM) embed_kernel(
    const int* __restrict__ type_seq, const float* __restrict__ time_seq,
    const float* __restrict__ temp_seq, const float* __restrict__ emb)
{
    int row = blockIdx.x;
    int d = threadIdx.x;
    int b = row / TSEQ, t = row % TSEQ;
    float v;
    if (t < LQ) {
        if (d < DMODEL) {
            v = tanhf(emb[(size_t)type_seq[b*LQ + t]*DMODEL + d]);
        } else {
            int j = d - DMODEL;
            int i = j >> 1;
            float div = expf(-0.57564627324851142f * (float)(2*i));
            float arg = time_seq[b*LQ + t] * div;
            v = (j & 1) ? cosf(arg) : sinf(arg);
        }
    } else {
        v = (d < DMODEL) ? 0.f
                         : temp_seq[(size_t)(b*LQ + (t - LQ))*DTIME + (d - DMODEL)];
    }
    g_h[(size_t)row*DDIM + d] = v;
}

// ---------------- one-time prep ----------------
#define W1TOT (NLAYER*2*DINNER*KPAD1)
#define W2TOT (NLAYER*DDIM*DINNER)
#define WXTOT (NLAYER*64*XK)
#define A2TOT (NLAYER*DINNER*DSTATE)
__global__ void __launch_bounds__(256) prep_all(
    const float* __restrict__ in_w, const float* __restrict__ out_w,
    const float* __restrict__ xproj_w, const float* __restrict__ A_log)
{
    int idx = blockIdx.x*256 + threadIdx.x;
    if (idx < W1TOT) {
        const int per = 2*DINNER*KPAD1;
        int l = idx / per, rem = idx - l*per;
        int r = rem / KPAD1, c = rem - r*KPAD1;
        float v = (c < DDIM) ? in_w[((size_t)l*2*DINNER + r)*DDIM + c] : 0.f;
        split_h16(v, g_w1_hi[idx], g_w1_lo[idx]);
    } else if (idx < W1TOT + W2TOT) {
        int j = idx - W1TOT;
        split_h16(out_w[j], g_w2_hi[j], g_w2_lo[j]);
    } else if (idx < W1TOT + W2TOT + WXTOT) {
        int j = idx - W1TOT - W2TOT;
        const int per = 64*XK;
        int l = j / per, rem = j - l*per;
        int r = rem / XK, cc = rem - r*XK;
        float v = (r < NDBL && cc < DINNER)
                ? xproj_w[((size_t)l*NDBL + r)*DINNER + cc] : 0.f;
        split_h16(v, g_wx_hi[j], g_wx_lo[j]);
    } else if (idx < W1TOT + W2TOT + WXTOT + A2TOT) {
        int j = idx - W1TOT - W2TOT - WXTOT;
        g_A2[j] = -__expf(A_log[j]) * 1.4426950408889634f;
    }
}

// ---------------- residual add + layernorm -> fp16 hn ----------------
__global__ void __launch_bounds__(128) addnorm_kernel(
    const float* __restrict__ gamma, const float* __restrict__ beta, int addflag)
{
    int row = blockIdx.x;
    int tid = threadIdx.x;
    float v[3];
    float s = 0.f, s2 = 0.f;
#pragma unroll
    for (int j = 0; j < 3; j++) {
        int d = tid + j*128;
        float x = 0.f;
        if (d < DDIM) {
            x = g_h[(size_t)row*DDIM + d];
            if (addflag) x += g_res[(size_t)row*DDIM + d];
        }
        v[j] = x; s += x; s2 += x*x;
    }
#pragma unroll
    for (int o = 16; o > 0; o >>= 1) {
        s  += __shfl_down_sync(0xffffffffu, s,  o);
        s2 += __shfl_down_sync(0xffffffffu, s2, o);
    }
    __shared__ float ss[4], ss2[4];
    if ((tid & 31) == 0) { ss[tid >> 5] = s; ss2[tid >> 5] = s2; }
    __syncthreads();
    if (tid == 0) {
        float a  = ss[0]+ss[1]+ss[2]+ss[3];
        float a2 = ss2[0]+ss2[1]+ss2[2]+ss2[3];
        float mean = a * (1.f/DDIM);
        float var  = a2 * (1.f/DDIM) - mean*mean;
        ss[0] = mean;
        ss2[0] = rsqrtf(var + 1e-5f);
    }
    __syncthreads();
    float mean = ss[0], rstd = ss2[0];
#pragma unroll
    for (int j = 0; j < 3; j++) {
        int d = tid + j*128;
        if (d < DDIM) {
            g_res[(size_t)row*DDIM + d] = v[j];
            float hn = (v[j]-mean)*rstd*gamma[d] + beta[d];
            g_hn[(size_t)row*KPAD1 + d] = __float2half_rn(hn);
        } else if (d < KPAD1) {
            g_hn[(size_t)row*KPAD1 + d] = __float2half(0.f);
        }
    }
}

// ---------------- final add + layernorm ----------------
__global__ void __launch_bounds__(128) final_kernel(
    const float* __restrict__ gamma, const float* __restrict__ beta,
    float* __restrict__ out)
{
    int rowo = blockIdx.x;
    int tid = threadIdx.x;
    int b = rowo / LQ, t = rowo % LQ;
    int m = b*TSEQ + t;
    float v[3];
    float s = 0.f, s2 = 0.f;
#pragma unroll
    for (int j = 0; j < 3; j++) {
        int d = tid + j*128;
        float x = 0.f;
        if (d < DDIM) x = g_h[(size_t)m*DDIM + d] + g_res[(size_t)m*DDIM + d];
        v[j] = x; s += x; s2 += x*x;
    }
#pragma unroll
    for (int o = 16; o > 0; o >>= 1) {
        s  += __shfl_down_sync(0xffffffffu, s,  o);
        s2 += __shfl_down_sync(0xffffffffu, s2, o);
    }
    __shared__ float ss[4], ss2[4];
    if ((tid & 31) == 0) { ss[tid >> 5] = s; ss2[tid >> 5] = s2; }
    __syncthreads();
    if (tid == 0) {
        float a  = ss[0]+ss[1]+ss[2]+ss[3];
        float a2 = ss2[0]+ss2[1]+ss2[2]+ss2[3];
        float mean = a * (1.f/DDIM);
        float var  = a2 * (1.f/DDIM) - mean*mean;
        ss[0] = mean;
        ss2[0] = rsqrtf(var + 1e-5f);
    }
    __syncthreads();
    float mean = ss[0], rstd = ss2[0];
#pragma unroll
    for (int j = 0; j < 3; j++) {
        int d = tid + j*128;
        if (d < DDIM)
            out[(size_t)rowo*DDIM + d] = (v[j]-mean)*rstd*gamma[d] + beta[d];
    }
}

// ---------------- fp16 2-term GEMM, cp.async 2-stage (R8 pipeline) + slab skip ----------------
#define SPAD 8
#define SROW (32+SPAD)
__global__ void __launch_bounds__(256, 2) gemm_h16(
    const h16* __restrict__ A,
    const h16* __restrict__ Whi, const h16* __restrict__ Wlo,
    float* __restrict__ C, int M, int N, int Kpad)
{
    extern __shared__ h16 sm[];
    int tid = threadIdx.x;
    int warp = tid >> 5;
    int wm = warp >> 2;
    int wn = warp & 3;
    int mb = blockIdx.y * 128;
    int nb = blockIdx.x * 128;
    bool wnvalid = (nb + wn*32) < N;     // whole 32-col slab OOB -> skip compute

    int aIdx0 = tid*2, aIdx1 = tid*2 + 1;
    int r0 = aIdx0 >> 2, c0 = (aIdx0 & 3) * 8;
    int r1 = aIdx1 >> 2, c1 = (aIdx1 & 3) * 8;
    int wsz0 = ((nb + r0) < N) ? 16 : 0;
    int wsz1 = ((nb + r1) < N) ? 16 : 0;

    const h16* pA0 = A   + (size_t)(mb + r0)*Kpad + c0;
    const h16* pA1 = A   + (size_t)(mb + r1)*Kpad + c1;
    const h16* pW0 = Whi + (size_t)(nb + r0)*Kpad + c0;
    const h16* pW1 = Whi + (size_t)(nb + r1)*Kpad + c1;
    const h16* pV0 = Wlo + (size_t)(nb + r0)*Kpad + c0;
    const h16* pV1 = Wlo + (size_t)(nb + r1)*Kpad + c1;

    uint32_t sbase = (uint32_t)__cvta_generic_to_shared(sm);
    auto soff = [&](int stage, int arr, int row, int col) -> uint32_t {
        return (uint32_t)((((stage*3 + arr)*128) + row)*SROW + col);
    };
    uint32_t dA0 = soff(0,0,r0,c0), dA1 = soff(0,0,r1,c1);
    uint32_t dW0 = soff(0,1,r0,c0), dW1 = soff(0,1,r1,c1);
    uint32_t dV0 = soff(0,2,r0,c0), dV1 = soff(0,2,r1,c1);
    const uint32_t STG = 3*128*SROW;

    wmma::fragment<wmma::accumulator,16,16,16,float> acc[4][2];
#pragma unroll
    for (int i = 0; i < 4; i++)
#pragma unroll
        for (int j = 0; j < 2; j++) wmma::fill_fragment(acc[i][j], 0.f);

    int ktiles = Kpad >> 5;

    // stage 0
    cp16(sbase + 2*dA0, pA0, 16); cp16(sbase + 2*dA1, pA1, 16);
    cp16(sbase + 2*dW0, pW0, wsz0); cp16(sbase + 2*dW1, pW1, wsz1);
    cp16(sbase + 2*dV0, pV0, wsz0); cp16(sbase + 2*dV1, pV1, wsz1);
    cp_commit();

    for (int kt = 0; kt < ktiles; kt++) {
        if (kt + 1 < ktiles) {
            int st = (kt+1) & 1;
            int go = (kt+1) * 32;
            uint32_t so = st * STG;
            cp16(sbase + 2*(dA0+so), pA0 + go, 16); cp16(sbase + 2*(dA1+so), pA1 + go, 16);
            cp16(sbase + 2*(dW0+so), pW0 + go, wsz0); cp16(sbase + 2*(dW1+so), pW1 + go, wsz1);
            cp16(sbase + 2*(dV0+so), pV0 + go, wsz0); cp16(sbase + 2*(dV1+so), pV1 + go, wsz1);
            cp_commit();
            cp_wait<1>();
        } else {
            cp_wait<0>();
        }
        __syncthreads();

        if (wnvalid) {
            const h16* bA   = sm + (size_t)(kt&1)*STG + 0*128*SROW;
            const h16* bWhi = sm + (size_t)(kt&1)*STG + 1*128*SROW;
            const h16* bWlo = sm + (size_t)(kt&1)*STG + 2*128*SROW;
#pragma unroll
            for (int ks = 0; ks < 32; ks += 16) {
                wmma::fragment<wmma::matrix_b,16,16,16,h16,wmma::col_major> bhi[2], blo[2];
#pragma unroll
                for (int j = 0; j < 2; j++) {
                    wmma::load_matrix_sync(bhi[j], bWhi + (wn*32 + j*16)*SROW + ks, SROW);
                    wmma::load_matrix_sync(blo[j], bWlo + (wn*32 + j*16)*SROW + ks, SROW);
                }
#pragma unroll
                for (int i = 0; i < 4; i++) {
                    wmma::fragment<wmma::matrix_a,16,16,16,h16,wmma::row_major> af;
                    wmma::load_matrix_sync(af, bA + (wm*64 + i*16)*SROW + ks, SROW);
#pragma unroll
                    for (int j = 0; j < 2; j++) {
                        wmma::mma_sync(acc[i][j], af, bhi[j], acc[i][j]);
                        wmma::mma_sync(acc[i][j], af, blo[j], acc[i][j]);
                    }
                }
            }
        }
        __syncthreads();
    }
    if (wnvalid) {
#pragma unroll
        for (int i = 0; i < 4; i++)
#pragma unroll
            for (int j = 0; j < 2; j++) {
                int n0 = nb + wn*32 + j*16;
                if (n0 < N)
                    wmma::store_matrix_sync(C + (size_t)(mb + wm*64 + i*16)*N + n0,
                                            acc[i][j], N, wmma::mem_row_major);
            }
    }
}
#define GEMM_SMEM (2*3*128*SROW*2)   // 61440 bytes -> 2 CTAs/SM

// ---------------- mega1: conv + x_proj (3-term fp16 tensor) + scan1 ----------------
#define MG_AHI  0
#define MG_ALO  (64*XKS*2)
#define MG_WH   (2*64*XKS*2)
#define MG_WL   (MG_WH + 64*72*2)
#define MG_DBL  (MG_WL + 64*72*2)
#define MG_SMEM (MG_DBL + 64*68*4)
__global__ void __launch_bounds__(DINNER) mega1(
    const float* __restrict__ conv_w, const float* __restrict__ conv_b,
    const float* __restrict__ dt_w, const float* __restrict__ dt_b,
    int layer)
{
    extern __shared__ __align__(16) char smx[];
    h16*  Ahi  = (h16*)(smx + MG_AHI);
    h16*  Alo  = (h16*)(smx + MG_ALO);
    h16*  Wh   = (h16*)(smx + MG_WH);
    h16*  Wl   = (h16*)(smx + MG_WL);
    float* sdbl = (float*)(smx + MG_DBL);

    int c = blockIdx.x, b = blockIdx.y;
    int tid = threadIdx.x;
    int d = tid;
    int warp = tid >> 5;
    int t0 = c*CHUNK;
    int m0 = b*TSEQ + t0;

    // ---- conv phase (MLP-batched loads) ----
    {
        const float* wp = conv_w + (size_t)(layer*DINNER + d)*DCONV;
        float w0 = wp[0], w1 = wp[1], w2 = wp[2], w3 = wp[3];
        float bias = conv_b[layer*DINNER + d];
        size_t base = (size_t)(b*TSEQ)*(2*DINNER) + d;
        float x0 = (t0-3 >= 0) ? g_xz[base + (size_t)(t0-3)*(2*DINNER)] : 0.f;
        float x1 = (t0-2 >= 0) ? g_xz[base + (size_t)(t0-2)*(2*DINNER)] : 0.f;
        float x2 = (t0-1 >= 0) ? g_xz[base + (size_t)(t0-1)*(2*DINNER)] : 0.f;
        for (int i0 = 0; i0 < CHUNK; i0 += 8) {
            float xv[8];
#pragma unroll
            for (int j = 0; j < 8; j++)
                xv[j] = g_xz[base + (size_t)(t0+i0+j)*(2*DINNER)];
#pragma unroll
            for (int j = 0; j < 8; j++) {
                float x3 = xv[j];
                float s = bias;
                s = fmaf(w0, x0, s); s = fmaf(w1, x1, s);
                s = fmaf(w2, x2, s); s = fmaf(w3, x3, s);
                float sl = s / (1.f + __expf(-s));
                h16 hi, lo; split_h16(sl, hi, lo);
                Ahi[(i0+j)*XKS + d] = hi;
                Alo[(i0+j)*XKS + d] = lo;
                x0 = x1; x1 = x2; x2 = x3;
            }
        }
        if (d < XK - DINNER) {
            h16 z0 = __float2half(0.f);
            for (int i = 0; i < CHUNK; i++) {
                Ahi[i*XKS + DINNER + d] = z0;
                Alo[i*XKS + DINNER + d] = z0;
            }
        }
    }
    __syncthreads();

    // ---- x_proj GEMM: sdbl[64][64] = A[64][576] @ Wx[64][576]^T (3-term) ----
    {
        wmma::fragment<wmma::accumulator,16,16,16,float> accf;
        if (warp < 16) wmma::fill_fragment(accf, 0.f);
        int ti = warp >> 2, tj = warp & 3;
        const h16* gwh = g_wx_hi + (size_t)layer*64*XK;
        const h16* gwl = g_wx_lo + (size_t)layer*64*XK;
        for (int kc = 0; kc < XK/64; kc++) {
            __syncthreads();
            for (int idx = tid; idx < 512; idx += DINNER) {
                int r = idx >> 3, q = (idx & 7)*8;
                *(uint4*)&Wh[r*72 + q] = *(const uint4*)&gwh[(size_t)r*XK + kc*64 + q];
                *(uint4*)&Wl[r*72 + q] = *(const uint4*)&gwl[(size_t)r*XK + kc*64 + q];
            }
            __syncthreads();
            if (warp < 16) {
#pragma unroll
                for (int ks = 0; ks < 64; ks += 16) {
                    wmma::fragment<wmma::matrix_a,16,16,16,h16,wmma::row_major> ah, al;
                    wmma::fragment<wmma::matrix_b,16,16,16,h16,wmma::col_major> bh, bl;
                    wmma::load_matrix_sync(ah, Ahi + ti*16*XKS + kc*64 + ks, XKS);
                    wmma::load_matrix_sync(al, Alo + ti*16*XKS + kc*64 + ks, XKS);
                    wmma::load_matrix_sync(bh, Wh + tj*16*72 + ks, 72);
                    wmma::load_matrix_sync(bl, Wl + tj*16*72 + ks, 72);
                    wmma::mma_sync(accf, ah, bh, accf);
                    wmma::mma_sync(accf, ah, bl, accf);
                    wmma::mma_sync(accf, al, bh, accf);
                }
            }
        }
        __syncthreads();
        if (warp < 16)
            wmma::store_matrix_sync(sdbl + ti*16*68 + tj*16, accf, 68, wmma::mem_row_major);
    }
    __syncthreads();

    // dbl -> global for scan3
    for (int idx = tid; idx < 64*64; idx += DINNER) {
        int i = idx >> 6, j = idx & 63;
        g_dbl2[(size_t)(m0+i)*NX + j] = sdbl[i*68 + j];
    }

    // ---- scan1 phase ----
    {
        float wreg[DTRANK];
#pragma unroll
        for (int r = 0; r < DTRANK; r++)
            wreg[r] = dt_w[(size_t)(layer*DINNER + d)*DTRANK + r];
        float dbias = dt_b[layer*DINNER + d];
        float A2[DSTATE];
#pragma unroll
        for (int n = 0; n < DSTATE; n++)
            A2[n] = g_A2[(size_t)(layer*DINNER + d)*DSTATE + n];
        float ab = A2[0];
        bool fast = true;
#pragma unroll
        for (int n = 1; n < DSTATE; n++)
            fast = fast && (fabsf(A2[n] - (float)(n+1)*ab)
                            <= 1e-4f*fabsf((float)(n+1)*ab) + 1e-6f);

        float h[DSTATE];
#pragma unroll
        for (int n = 0; n < DSTATE; n++) h[n] = 0.f;
        float sumd = 0.f;

        for (int i = 0; i < CHUNK; i++) {
            float sdt = dbias;
#pragma unroll
            for (int r = 0; r < DTRANK; r++) sdt = fmaf(sdbl[i*68 + r], wreg[r], sdt);
            float delta = fmaxf(sdt, 0.f) + log1pf(__expf(-fabsf(sdt)));
            float u = __half2float(Ahi[i*XKS + d]) + __half2float(Alo[i*XKS + d]);
            float du = delta * u;
            if (fast) {
                float e1 = ex2(delta * ab);
                float p = e1;
#pragma unroll
                for (int n = 0; n < DSTATE; n++) {
                    h[n] = fmaf(p, h[n], du * sdbl[i*68 + DTRANK + n]);
                    p *= e1;
                }
            } else {
#pragma unroll
                for (int n = 0; n < DSTATE; n++) {
                    float a = ex2(delta * A2[n]);
                    h[n] = fmaf(a, h[n], du * sdbl[i*68 + DTRANK + n]);
                }
            }
            sumd += delta;
        }
        size_t o = ((size_t)(b*NCHUNK + c)*DINNER + d)*DSTATE;
#pragma unroll
        for (int n = 0; n < DSTATE; n++) {
            g_hend[o + n] = h[n];
            g_P[o + n] = ex2(A2[n] * sumd);
        }
    }
}

__global__ void __launch_bounds__(256) scan2_kernel()
{
    int gw = (blockIdx.x*256 + threadIdx.x) >> 5;
    int lane = threadIdx.x & 31;
    if (gw >= BATCH*(DINNER/2)) return;
    int b = gw / (DINNER/2);
    int dp = gw - b*(DINNER/2);
    float H = 0.f;
    for (int c = 0; c < NCHUNK; c++) {
        size_t o = ((size_t)(b*NCHUNK + c)*DINNER + dp*2)*DSTATE + lane;
        float P = g_P[o];
        float E = g_hend[o];
        g_Hin[o] = H;
        H = fmaf(P, H, E);
    }
}

// ---------------- scan3: inline conv + scan + gate -> yg fp16 (MLP-batched) ----------------
__global__ void __launch_bounds__(DINNER) scan3_kernel(
    const float* __restrict__ conv_w, const float* __restrict__ conv_b,
    const float* __restrict__ dt_w, const float* __restrict__ dt_b,
    const float* __restrict__ D_param, int layer)
{
    int c = blockIdx.x, b = blockIdx.y;
    int d = threadIdx.x;
    __shared__ float sD[CHUNK][NDBL+1];
    int t0 = c*CHUNK;
    int m0 = b*TSEQ + t0;
    for (int idx = d; idx < CHUNK*NDBL; idx += DINNER) {
        int i = idx / NDBL, j = idx - i*NDBL;
        sD[i][j] = g_dbl2[(size_t)(m0+i)*NX + j];
    }
    float wreg[DTRANK];
#pragma unroll
    for (int r = 0; r < DTRANK; r++)
        wreg[r] = dt_w[(size_t)(layer*DINNER + d)*DTRANK + r];
    float dbias = dt_b[layer*DINNER + d];
    float A2[DSTATE];
#pragma unroll
    for (int n = 0; n < DSTATE; n++)
        A2[n] = g_A2[(size_t)(layer*DINNER + d)*DSTATE + n];
    float ab = A2[0];
    bool fast = true;
#pragma unroll
    for (int n = 1; n < DSTATE; n++)
        fast = fast && (fabsf(A2[n] - (float)(n+1)*ab)
                        <= 1e-4f*fabsf((float)(n+1)*ab) + 1e-6f);

    const float* wp = conv_w + (size_t)(layer*DINNER + d)*DCONV;
    float w0 = wp[0], w1 = wp[1], w2 = wp[2], w3 = wp[3];
    float cbias = conv_b[layer*DINNER + d];
    size_t base = (size_t)(b*TSEQ)*(2*DINNER) + d;
    float x0 = (t0-3 >= 0) ? g_xz[base + (size_t)(t0-3)*(2*DINNER)] : 0.f;
    float x1 = (t0-2 >= 0) ? g_xz[base + (size_t)(t0-2)*(2*DINNER)] : 0.f;
    float x2 = (t0-1 >= 0) ? g_xz[base + (size_t)(t0-1)*(2*DINNER)] : 0.f;

    float h[DSTATE];
    size_t oin = ((size_t)(b*NCHUNK + c)*DINNER + d)*DSTATE;
#pragma unroll
    for (int n = 0; n < DSTATE; n++) h[n] = g_Hin[oin + n];
    float Dp = D_param[layer*DINNER + d];
    __syncthreads();

    for (int i0 = 0; i0 < CHUNK; i0 += 8) {
        float xv[8], zv[8];
#pragma unroll
        for (int j = 0; j < 8; j++) {
            size_t rowoff = base + (size_t)(t0+i0+j)*(2*DINNER);
            xv[j] = g_xz[rowoff];
            zv[j] = g_xz[rowoff + DINNER];
        }
#pragma unroll
        for (int j = 0; j < 8; j++) {
            int i = i0 + j;
            int m = m0 + i;
            float x3 = xv[j];
            float cs = cbias;
            cs = fmaf(w0, x0, cs); cs = fmaf(w1, x1, cs);
            cs = fmaf(w2, x2, cs); cs = fmaf(w3, x3, cs);
            float u = cs / (1.f + __expf(-cs));
            x0 = x1; x1 = x2; x2 = x3;

            float sdt = dbias;
#pragma unroll
            for (int r = 0; r < DTRANK; r++) sdt = fmaf(sD[i][r], wreg[r], sdt);
            float delta = fmaxf(sdt, 0.f) + log1pf(__expf(-fabsf(sdt)));
            float du = delta * u;
            float y = 0.f;
            if (fast) {
                float e1 = ex2(delta * ab);
                float p = e1;
#pragma unroll
                for (int n = 0; n < DSTATE; n++) {
                    h[n] = fmaf(p, h[n], du * sD[i][DTRANK + n]);
                    y = fmaf(h[n], sD[i][DTRANK + DSTATE + n], y);
                    p *= e1;
                }
            } else {
#pragma unroll
                for (int n = 0; n < DSTATE; n++) {
                    float a = ex2(delta * A2[n]);
                    h[n] = fmaf(a, h[n], du * sD[i][DTRANK + n]);
                    y = fmaf(h[n], sD[i][DTRANK + DSTATE + n], y);
                }
            }
            float silz = zv[j] / (1.f + __expf(-zv[j]));
            float yg = fmaf(u, Dp, y) * silz;
            g_yg[(size_t)m*DINNER + d] = __float2half_rn(yg);
        }
    }
}

// ---------------- host launcher ----------------
extern "C" void kernel_launch(void* const* d_in, const int* in_sizes, int n_in,
                              void* d_out, int out_size)
{
    (void)in_sizes; (void)n_in; (void)out_size;
    const int*   type_seq = (const int*)  d_in[0];
    const float* time_seq = (const float*)d_in[1];
    const float* temp_seq = (const float*)d_in[2];
    const float* emb      = (const float*)d_in[3];
    const float* norm_w   = (const float*)d_in[4];
    const float* norm_b   = (const float*)d_in[5];
    const float* in_w     = (const float*)d_in[6];
    const float* conv_w   = (const float*)d_in[7];
    const float* conv_b   = (const float*)d_in[8];
    const float* xproj_w  = (const float*)d_in[9];
    const float* dt_w     = (const float*)d_in[10];
    const float* dt_b     = (const float*)d_in[11];
    const float* A_log    = (const float*)d_in[12];
    const float* D_param  = (const float*)d_in[13];
    const float* out_w    = (const float*)d_in[14];
    const float* normf_w  = (const float*)d_in[15];
    const float* normf_b  = (const float*)d_in[16];
    float* out = (float*)d_out;

    float *p_xz, *p_h;
    cudaGetSymbolAddress((void**)&p_xz, g_xz);
    cudaGetSymbolAddress((void**)&p_h,  g_h);
    h16 *p_hn, *p_yg, *p_w1h, *p_w1l, *p_w2h, *p_w2l;
    cudaGetSymbolAddress((void**)&p_hn,  g_hn);
    cudaGetSymbolAddress((void**)&p_yg,  g_yg);
    cudaGetSymbolAddress((void**)&p_w1h, g_w1_hi);
    cudaGetSymbolAddress((void**)&p_w1l, g_w1_lo);
    cudaGetSymbolAddress((void**)&p_w2h, g_w2_hi);
    cudaGetSymbolAddress((void**)&p_w2l, g_w2_lo);

    cudaFuncSetAttribute(gemm_h16,
                         cudaFuncAttributeMaxDynamicSharedMemorySize, GEMM_SMEM);
    cudaFuncSetAttribute(mega1,
                         cudaFuncAttributeMaxDynamicSharedMemorySize, MG_SMEM);

    embed_kernel<<<MROWS, DDIM>>>(type_seq, time_seq, temp_seq, emb);
    prep_all<<<(W1TOT + W2TOT + WXTOT + A2TOT + 255)/256, 256>>>(
        in_w, out_w, xproj_w, A_log);

    for (int l = 0; l < NLAYER; l++) {
        addnorm_kernel<<<MROWS, 128>>>(norm_w + l*DDIM, norm_b + l*DDIM, l > 0);

        gemm_h16<<<dim3((2*DINNER + 127)/128, MROWS/128), 256, GEMM_SMEM>>>(
            p_hn,
            p_w1h + (size_t)l*2*DINNER*KPAD1, p_w1l + (size_t)l*2*DINNER*KPAD1,
            p_xz, MROWS, 2*DINNER, KPAD1);

        mega1<<<dim3(NCHUNK, BATCH), DINNER, MG_SMEM>>>(
            conv_w, conv_b, dt_w, dt_b, l);

        scan2_kernel<<<(BATCH*(DINNER/2)*32 + 255)/256, 256>>>();

        scan3_kernel<<<dim3(NCHUNK, BATCH), DINNER>>>(
            conv_w, conv_b, dt_w, dt_b, D_param, l);

        gemm_h16<<<dim3((DDIM + 127)/128, MROWS/128), 256, GEMM_SMEM>>>(
            p_yg,
            p_w2h + (size_t)l*DDIM*DINNER, p_w2l + (size_t)l*DDIM*DINNER,
            p_h, MROWS, DDIM, DINNER);
    }

    final_kernel<<<BATCH*LQ, 128>>>(normf_w, normf_b, out);
}